// round 11
// baseline (speedup 1.0000x reference)
#include <cuda_runtime.h>
#include <cuda_fp16.h>
#include <math.h>
#include <stdint.h>

#define Dm   512
#define Tn   1024
#define NT   2048
#define Ln   4
#define En   8
#define FFn  2048
#define NEn  4096
#define DHn  64

typedef __half h16;

// ---------------- scratch ----------------
__device__ __align__(128) float g_y[NT * Dm];
__device__ __align__(128) float g_proj[NT * Dm];
__device__ __align__(128) float g_probs[NT * En];
__device__ __align__(128) float g_gates[NEn];
__device__ __align__(128) float g_eout[(size_t)NEn * Dm];
__device__ int g_topi[NEn];
__device__ int g_perm[NEn];
__device__ int g_offs[En + 1];
__device__ __align__(128) h16 g_qkvh[3 * NT * Dm], g_qkvl[3 * NT * Dm];
__device__ __align__(128) h16 g_yh[NT * Dm],  g_yl[NT * Dm];
__device__ __align__(128) h16 g_ench[NT * Dm], g_encl[NT * Dm];
__device__ __align__(128) h16 g_ath[NT * Dm], g_atl[NT * Dm];
__device__ __align__(128) h16 g_Hh[(size_t)NEn * FFn], g_Hl[(size_t)NEn * FFn];
__device__ __align__(128) h16 g_sawh[(size_t)Ln * 4 * Dm * Dm], g_sawl[(size_t)Ln * 4 * Dm * Dm];
__device__ __align__(128) h16 g_cawh[(size_t)Ln * 4 * Dm * Dm], g_cawl[(size_t)Ln * 4 * Dm * Dm];
__device__ __align__(128) h16 g_w1h[(size_t)Ln * En * FFn * Dm], g_w1l[(size_t)Ln * En * FFn * Dm];
__device__ __align__(128) h16 g_w2h[(size_t)Ln * En * Dm * FFn], g_w2l[(size_t)Ln * En * Dm * FFn];

__device__ __forceinline__ uint32_t smem_u32(const void* p) {
    uint32_t a;
    asm("{ .reg .u64 t; cvta.to.shared.u64 t, %1; cvt.u32.u64 %0, t; }" : "=r"(a) : "l"(p));
    return a;
}
__device__ __forceinline__ void hsplit(float v, h16& h, h16& l) {
    h = __float2half_rn(v);
    l = __float2half_rn(v - __half2float(h));
}
#define CPA(d, s, sz) asm volatile("cp.async.ca.shared.global [%0], [%1], 16, %2;" :: "r"(d), "l"(s), "r"(sz) : "memory")
#define CP_COMMIT()   asm volatile("cp.async.commit_group;" ::: "memory")
#define CP_WAIT1()    asm volatile("cp.async.wait_group 1;" ::: "memory")
#define CP_WAIT0()    asm volatile("cp.async.wait_group 0;" ::: "memory")

__device__ __forceinline__ void mma_f16(float c[4], const uint32_t a[4], const uint32_t b[2])
{
    asm volatile(
        "mma.sync.aligned.m16n8k16.row.col.f32.f16.f16.f32 "
        "{%0,%1,%2,%3},{%4,%5,%6,%7},{%8,%9},{%0,%1,%2,%3};"
        : "+f"(c[0]), "+f"(c[1]), "+f"(c[2]), "+f"(c[3])
        : "r"(a[0]), "r"(a[1]), "r"(a[2]), "r"(a[3]), "r"(b[0]), "r"(b[1]));
}

// ---------------- A providers ----------------
struct RowAh {
    const h16 *Ah, *Al; int lda; long zs; int M;
    __device__ int setz(int z) { Ah += (long)z * zs; Al += (long)z * zs; return M; }
    __device__ const h16* rowh(int m) const { return Ah + (long)m * lda; }
    __device__ const h16* rowl(int m) const { return Al + (long)m * lda; }
};
struct GatherAh {
    const h16 *Yh, *Yl; const int* perm; const int* offs; int base;
    __device__ int setz(int e) { base = offs[e]; return offs[e + 1] - base; }
    __device__ const h16* rowh(int m) const { return Yh + (long)(perm[base + m] >> 1) * Dm; }
    __device__ const h16* rowl(int m) const { return Yl + (long)(perm[base + m] >> 1) * Dm; }
};
struct HRowAh {
    const h16 *Hh, *Hl; const int* offs; const h16 *Ah, *Al;
    __device__ int setz(int e) {
        int b0 = offs[e];
        Ah = Hh + (long)b0 * FFn; Al = Hl + (long)b0 * FFn;
        return offs[e + 1] - b0;
    }
    __device__ const h16* rowh(int m) const { return Ah + (long)m * FFn; }
    __device__ const h16* rowl(int m) const { return Al + (long)m * FFn; }
};
// ---------------- epilogues ----------------
struct EpiBias {
    const float* bias; long biasZ; float* C; long cZ; int ldc;
    __device__ void setz(int z) { bias += (long)z * biasZ; C += (long)z * cZ; }
    __device__ void op(int m, int n, float v) { C[(long)m * ldc + n] = v + bias[n]; }
};
struct EpiBiasH {
    const float* bias; long biasZ; h16* Ch; h16* Cl; long cZ; int ldc;
    __device__ void setz(int z) { bias += (long)z * biasZ; Ch += (long)z * cZ; Cl += (long)z * cZ; }
    __device__ void op(int m, int n, float v) {
        v += bias[n];
        h16 h, l; hsplit(v, h, l);
        Ch[(long)m * ldc + n] = h; Cl[(long)m * ldc + n] = l;
    }
};
struct EpiMoE1 {
    const float* b1l; const int* offs; h16* Hh; h16* Hl;
    const float* bias; h16 *Ch, *Cl;
    __device__ void setz(int e) {
        bias = b1l + (long)e * FFn;
        Ch = Hh + (long)offs[e] * FFn; Cl = Hl + (long)offs[e] * FFn;
    }
    __device__ void op(int m, int n, float v) {
        v = fmaxf(v + bias[n], 0.f);
        h16 h, l; hsplit(v, h, l);
        Ch[(long)m * FFn + n] = h; Cl[(long)m * FFn + n] = l;
    }
};
struct EpiMoE2 {
    const float* b2l; const int* offs; const int* perm; const float* gates; float* eout;
    const float* bias; int base;
    __device__ void setz(int e) { bias = b2l + (long)e * Dm; base = offs[e]; }
    __device__ void op(int m, int n, float v) {
        int entry = perm[base + m];
        eout[(long)entry * Dm + n] = gates[entry] * (v + bias[n]);
    }
};

// ------- fp16x3 GEMM: 128x64 tile, BK=32, 3-stage cp.async, 1 sync/iter -----
constexpr int STGH = 15360;               // halves per stage
constexpr int GSMEM = 3 * STGH * 2;       // bytes = 92160

template <class AP, class EP>
__global__ void __launch_bounds__(256, 2) gemm_k(AP ap, const h16* __restrict__ BTh,
                                                 const h16* __restrict__ BTl, long bz,
                                                 EP ep, int K)
{
    extern __shared__ h16 smh[];
    int z = blockIdx.z;
    int M = ap.setz(z);
    int m0 = blockIdx.x * 128;
    if (m0 >= M) return;
    ep.setz(z);
    int n0 = blockIdx.y * 64;

    int tid = threadIdx.x, lane = tid & 31, wid = tid >> 5;
    int wm = wid & 3, wn = wid >> 2;
    int g = lane >> 2, tg = lane & 3;
    uint32_t smb = smem_u32(smh);

    int r4 = tid >> 2;
    int c4 = (tid & 3) * 8;
    bool v0 = (m0 + r4) < M, v1 = (m0 + 64 + r4) < M;
    uint32_t szA0 = v0 ? 16u : 0u, szA1 = v1 ? 16u : 0u;
    const h16* sAh0 = ap.rowh(v0 ? m0 + r4 : m0) + c4;
    const h16* sAl0 = ap.rowl(v0 ? m0 + r4 : m0) + c4;
    const h16* sAh1 = ap.rowh(v1 ? m0 + 64 + r4 : m0) + c4;
    const h16* sAl1 = ap.rowl(v1 ? m0 + 64 + r4 : m0) + c4;
    const h16* sBh = BTh + (long)z * bz + (long)(n0 + r4) * K + c4;
    const h16* sBl = BTl + (long)z * bz + (long)(n0 + r4) * K + c4;

    uint32_t dA0 = (uint32_t)r4 * 80 + (uint32_t)(tid & 3) * 16;
    uint32_t dA1 = dA0 + 5120;

    auto issue = [&](int s, int buf) {
        uint32_t b = smb + (uint32_t)buf * (STGH * 2);
        int ko = s * 32;
        CPA(b + dA0, sAh0 + ko, szA0);
        CPA(b + dA1, sAh1 + ko, szA1);
        CPA(b + 10240 + dA0, sAl0 + ko, szA0);
        CPA(b + 10240 + dA1, sAl1 + ko, szA1);
        CPA(b + 20480 + dA0, sBh + ko, 16u);
        CPA(b + 25600 + dA0, sBl + ko, 16u);
        CP_COMMIT();
    };

    float acc[2][4][4];
    #pragma unroll
    for (int mt = 0; mt < 2; mt++)
        #pragma unroll
        for (int nt = 0; nt < 4; nt++)
            #pragma unroll
            for (int j = 0; j < 4; j++) acc[mt][nt][j] = 0.f;

    int ns = K / 32;
    issue(0, 0);
    if (ns > 1) issue(1, 1);
    int cbuf = 0, ibuf = 2;
    for (int s = 0; s < ns; s++) {
        if (s + 1 < ns) CP_WAIT1(); else CP_WAIT0();
        __syncthreads();
        if (s + 2 < ns) issue(s + 2, ibuf);

        const uint32_t* W = (const uint32_t*)(smh + (size_t)cbuf * STGH);
        #pragma unroll
        for (int kc = 0; kc < 2; kc++) {
            int ko = kc * 8;
            uint32_t ah[2][4], al[2][4];
            #pragma unroll
            for (int mt = 0; mt < 2; mt++) {
                int p = (wm * 32 + g + mt * 16) * 20 + tg + ko;
                ah[mt][0] = W[p];           ah[mt][1] = W[p + 8 * 20];
                ah[mt][2] = W[p + 4];       ah[mt][3] = W[p + 8 * 20 + 4];
                al[mt][0] = W[2560 + p];        al[mt][1] = W[2560 + p + 8 * 20];
                al[mt][2] = W[2560 + p + 4];    al[mt][3] = W[2560 + p + 8 * 20 + 4];
            }
            uint32_t bh[4][2], bl[4][2];
            #pragma unroll
            for (int nt = 0; nt < 4; nt++) {
                int p = (wn * 32 + nt * 8 + g) * 20 + tg + ko;
                bh[nt][0] = W[5120 + p];  bh[nt][1] = W[5120 + p + 4];
                bl[nt][0] = W[6400 + p];  bl[nt][1] = W[6400 + p + 4];
            }
            #pragma unroll
            for (int mt = 0; mt < 2; mt++)
                #pragma unroll
                for (int nt = 0; nt < 4; nt++) {
                    mma_f16(acc[mt][nt], al[mt], bh[nt]);
                    mma_f16(acc[mt][nt], ah[mt], bl[nt]);
                    mma_f16(acc[mt][nt], ah[mt], bh[nt]);
                }
        }
        cbuf = (cbuf == 2) ? 0 : cbuf + 1;
        ibuf = (ibuf == 2) ? 0 : ibuf + 1;
    }

    int r0 = wm * 32 + g;
    int c0 = wn * 32 + tg * 2;
    #pragma unroll
    for (int mt = 0; mt < 2; mt++) {
        int gm0 = m0 + r0 + mt * 16;
        int gm1 = gm0 + 8;
        #pragma unroll
        for (int nt = 0; nt < 4; nt++) {
            int gn = n0 + c0 + nt * 8;
            if (gm0 < M) { ep.op(gm0, gn, acc[mt][nt][0]); ep.op(gm0, gn + 1, acc[mt][nt][1]); }
            if (gm1 < M) { ep.op(gm1, gn, acc[mt][nt][2]); ep.op(gm1, gn + 1, acc[mt][nt][3]); }
        }
    }
}

// -------- weight transpose+split --------
__global__ void __launch_bounds__(256) wsplit_t_k(const float* __restrict__ W,
                                                  h16* __restrict__ Oh, h16* __restrict__ Ol,
                                                  int K, int N)
{
    __shared__ float t[32][33];
    size_t zo = (size_t)blockIdx.z * K * N;
    int k0 = blockIdx.x * 32, n0 = blockIdx.y * 32;
    int tx = threadIdx.x & 31, ty = threadIdx.x >> 5;
    #pragma unroll
    for (int j = 0; j < 32; j += 8)
        t[ty + j][tx] = W[zo + (size_t)(k0 + ty + j) * N + n0 + tx];
    __syncthreads();
    #pragma unroll
    for (int j = 0; j < 32; j += 8) {
        float v = t[tx][ty + j];
        h16 h, l; hsplit(v, h, l);
        size_t o = zo + (size_t)(n0 + ty + j) * K + k0 + tx;
        Oh[o] = h; Ol[o] = l;
    }
}

__global__ void __launch_bounds__(256) split_k(const float* __restrict__ x,
                                               h16* __restrict__ oh, h16* __restrict__ ol, int n)
{
    int i = blockIdx.x * 256 + threadIdx.x;
    if (i < n) { h16 h, l; hsplit(x[i], h, l); oh[i] = h; ol[i] = l; }
}

__global__ void embed_k(const int* __restrict__ ids, const float* __restrict__ emb,
                        const float* __restrict__ pos, float* __restrict__ y,
                        h16* __restrict__ yh, h16* __restrict__ yl)
{
    int t = blockIdx.x;
    int id = ids[t];
    int tq = t & (Tn - 1);
    const float* er = emb + (long)id * Dm;
    const float* pr = pos + (long)tq * Dm;
    long o = (long)t * Dm;
    for (int d = threadIdx.x; d < Dm; d += blockDim.x) {
        float v = er[d] + pr[d];
        y[o + d] = v;
        h16 h, l; hsplit(v, h, l);
        yh[o + d] = h; yl[o + d] = l;
    }
}

// ---------------- tensor-core flash attention (unchanged from R10) -----------
constexpr int FSMEM = 57344;

__global__ void __launch_bounds__(256) flash_k(const h16* __restrict__ Qh, const h16* __restrict__ Ql,
                                               const h16* __restrict__ Kh, const h16* __restrict__ Kl,
                                               const h16* __restrict__ Vh, const h16* __restrict__ Vl,
                                               h16* __restrict__ Oh, h16* __restrict__ Ol,
                                               const int* __restrict__ am, int Tk, int causal)
{
    extern __shared__ h16 fs[];
    h16 *Qhs = fs, *Qls = fs + 4608, *Khs = fs + 9216, *Kls = fs + 11520;
    h16 *Vths = fs + 13824, *Vtls = fs + 16384, *Phs = fs + 18944, *Pls = fs + 21504;
    float* Ps = (float*)(fs + 24064);
    float* rowm = Ps + 64 * 33;
    float* rowl = rowm + 64;
    float* alph = rowl + 64;

    int q0 = blockIdx.x * 64;
    int bh = blockIdx.y;
    int b = bh >> 3, h = bh & 7;
    const h16* Qbh = Qh + ((long)b * Tn + q0) * Dm + h * DHn;
    const h16* Qbl = Ql + ((long)b * Tn + q0) * Dm + h * DHn;
    const h16* Kbh = Kh + (long)b * Tk * Dm + h * DHn;
    const h16* Kbl = Kl + (long)b * Tk * Dm + h * DHn;
    const h16* Vbh = Vh + (long)b * Tk * Dm + h * DHn;
    const h16* Vbl = Vl + (long)b * Tk * Dm + h * DHn;

    int tid = threadIdx.x, lane = tid & 31, wid = tid >> 5;
    int wm = wid & 3, wn = wid >> 2;
    int g = lane >> 2, tg = lane & 3;

    #pragma unroll
    for (int it = 0; it < 2; it++) {
        int idx = tid + it * 256;
        int r = idx >> 3, c8 = (idx & 7) * 8;
        *(uint4*)(Qhs + r * 72 + c8) = *(const uint4*)(Qbh + (long)r * Dm + c8);
        *(uint4*)(Qls + r * 72 + c8) = *(const uint4*)(Qbl + (long)r * Dm + c8);
    }
    if (tid < 64) { rowm[tid] = -1e30f; rowl[tid] = 0.f; }

    float o[4][4];
    #pragma unroll
    for (int i = 0; i < 4; i++)
        #pragma unroll
        for (int j = 0; j < 4; j++) o[i][j] = 0.f;

    const uint32_t* QWh = (const uint32_t*)Qhs;
    const uint32_t* QWl = (const uint32_t*)Qls;
    const uint32_t* KWh = (const uint32_t*)Khs;
    const uint32_t* KWl = (const uint32_t*)Kls;
    const uint32_t* VWh = (const uint32_t*)Vths;
    const uint32_t* VWl = (const uint32_t*)Vtls;
    const uint32_t* PWh = (const uint32_t*)Phs;
    const uint32_t* PWl = (const uint32_t*)Pls;

    int kvmax = causal ? (q0 + 64) : Tk;
    for (int kv0 = 0; kv0 < kvmax; kv0 += 32) {
        __syncthreads();
        {
            int r = tid >> 3, c8 = (tid & 7) * 8;
            *(uint4*)(Khs + r * 72 + c8) = *(const uint4*)(Kbh + (long)(kv0 + r) * Dm + c8);
            *(uint4*)(Kls + r * 72 + c8) = *(const uint4*)(Kbl + (long)(kv0 + r) * Dm + c8);
            h16 vh8[8], vl8[8];
            *(uint4*)vh8 = *(const uint4*)(Vbh + (long)(kv0 + r) * Dm + c8);
            *(uint4*)vl8 = *(const uint4*)(Vbl + (long)(kv0 + r) * Dm + c8);
            #pragma unroll
            for (int j = 0; j < 8; j++) {
                Vths[(c8 + j) * 40 + r] = vh8[j];
                Vtls[(c8 + j) * 40 + r] = vl8[j];
            }
        }
        __syncthreads();

        float s[2][4] = {{0.f, 0.f, 0.f, 0.f}, {0.f, 0.f, 0.f, 0.f}};
        #pragma unroll
        for (int kc = 0; kc < 4; kc++) {
            int ko = kc * 8;
            int pa = (wm * 16 + g) * 36 + tg + ko;
            uint32_t ah[4], al[4];
            ah[0] = QWh[pa]; ah[1] = QWh[pa + 8 * 36]; ah[2] = QWh[pa + 4]; ah[3] = QWh[pa + 8 * 36 + 4];
            al[0] = QWl[pa]; al[1] = QWl[pa + 8 * 36]; al[2] = QWl[pa + 4]; al[3] = QWl[pa + 8 * 36 + 4];
            #pragma unroll
            for (int nt = 0; nt < 2; nt++) {
                int pb = (wn * 16 + nt * 8 + g) * 36 + tg + ko;
                uint32_t bh2[2] = { KWh[pb], KWh[pb + 4] };
                uint32_t bl2[2] = { KWl[pb], KWl[pb + 4] };
                mma_f16(s[nt], al, bh2);
                mma_f16(s[nt], ah, bl2);
                mma_f16(s[nt], ah, bh2);
            }
        }
        #pragma unroll
        for (int nt = 0; nt < 2; nt++) {
            #pragma unroll
            for (int j = 0; j < 4; j++) {
                int row = wm * 16 + g + (j >> 1) * 8;
                int col = wn * 16 + nt * 8 + tg * 2 + (j & 1);
                float sv = s[nt][j] * 0.125f;
                if (causal) {
                    int kg = kv0 + col, qg = q0 + row;
                    if (kg > qg || am[b * Tn + kg] == 0) sv = -1e9f;
                }
                Ps[row * 33 + col] = sv;
            }
        }
        __syncthreads();
        {
            int row = tid >> 2, sub = tid & 3;
            float mo = rowm[row], mx = mo;
            #pragma unroll
            for (int j = 0; j < 8; j++) mx = fmaxf(mx, Ps[row * 33 + sub * 8 + j]);
            mx = fmaxf(mx, __shfl_xor_sync(0xffffffffu, mx, 1));
            mx = fmaxf(mx, __shfl_xor_sync(0xffffffffu, mx, 2));
            float sum = 0.f;
            #pragma unroll
            for (int j = 0; j < 8; j++) {
                float p = __expf(Ps[row * 33 + sub * 8 + j] - mx);
                h16 ph, pl; hsplit(p, ph, pl);
                Phs[row * 40 + sub * 8 + j] = ph;
                Pls[row * 40 + sub * 8 + j] = pl;
                sum += p;
            }
            sum += __shfl_xor_sync(0xffffffffu, sum, 1);
            sum += __shfl_xor_sync(0xffffffffu, sum, 2);
            if (sub == 0) {
                float al2 = __expf(mo - mx);
                rowm[row] = mx;
                rowl[row] = rowl[row] * al2 + sum;
                alph[row] = al2;
            }
        }
        __syncthreads();
        {
            float a0 = alph[wm * 16 + g], a1 = alph[wm * 16 + g + 8];
            #pragma unroll
            for (int nt = 0; nt < 4; nt++) {
                o[nt][0] *= a0; o[nt][1] *= a0;
                o[nt][2] *= a1; o[nt][3] *= a1;
            }
        }
        #pragma unroll
        for (int kc = 0; kc < 2; kc++) {
            int ko = kc * 8;
            int pa = (wm * 16 + g) * 20 + tg + ko;
            uint32_t ah[4], al[4];
            ah[0] = PWh[pa]; ah[1] = PWh[pa + 8 * 20]; ah[2] = PWh[pa + 4]; ah[3] = PWh[pa + 8 * 20 + 4];
            al[0] = PWl[pa]; al[1] = PWl[pa + 8 * 20]; al[2] = PWl[pa + 4]; al[3] = PWl[pa + 8 * 20 + 4];
            #pragma unroll
            for (int nt = 0; nt < 4; nt++) {
                int pb = (wn * 32 + nt * 8 + g) * 20 + tg + ko;
                uint32_t bh2[2] = { VWh[pb], VWh[pb + 4] };
                uint32_t bl2[2] = { VWl[pb], VWl[pb + 4] };
                mma_f16(o[nt], al, bh2);
                mma_f16(o[nt], ah, bl2);
                mma_f16(o[nt], ah, bh2);
            }
        }
    }
    __syncthreads();
    {
        float inv0 = 1.f / rowl[wm * 16 + g];
        float inv1 = 1.f / rowl[wm * 16 + g + 8];
        int row0 = q0 + wm * 16 + g;
        #pragma unroll
        for (int nt = 0; nt < 4; nt++) {
            int col = h * DHn + wn * 32 + nt * 8 + tg * 2;
            long o0 = ((long)b * Tn + row0) * Dm + col;
            long o1 = ((long)b * Tn + row0 + 8) * Dm + col;
            h16 hh, ll;
            hsplit(o[nt][0] * inv0, hh, ll); Oh[o0] = hh;     Ol[o0] = ll;
            hsplit(o[nt][1] * inv0, hh, ll); Oh[o0 + 1] = hh; Ol[o0 + 1] = ll;
            hsplit(o[nt][2] * inv1, hh, ll); Oh[o1] = hh;     Ol[o1] = ll;
            hsplit(o[nt][3] * inv1, hh, ll); Oh[o1 + 1] = hh; Ol[o1 + 1] = ll;
        }
    }
}

// ---------------- add + layernorm ----------------
__global__ void __launch_bounds__(256) add_ln_k(const float* __restrict__ base,
                                                const float* __restrict__ delta, int nslots,
                                                const float* __restrict__ g,
                                                const float* __restrict__ bet,
                                                float* __restrict__ out,
                                                h16* __restrict__ oh, h16* __restrict__ ol)
{
    int t = blockIdx.x, tid = threadIdx.x;
    __shared__ float red[256];
    float x0 = base[(long)t * Dm + tid];
    float x1 = base[(long)t * Dm + 256 + tid];
    if (nslots == 1) {
        x0 += delta[(long)t * Dm + tid];
        x1 += delta[(long)t * Dm + 256 + tid];
    } else {
        x0 += delta[(long)(t * 2) * Dm + tid] + delta[(long)(t * 2 + 1) * Dm + tid];
        x1 += delta[(long)(t * 2) * Dm + 256 + tid] + delta[(long)(t * 2 + 1) * Dm + 256 + tid];
    }
    red[tid] = x0 + x1;
    __syncthreads();
    #pragma unroll
    for (int s = 128; s > 0; s >>= 1) {
        if (tid < s) red[tid] += red[tid + s];
        __syncthreads();
    }
    float mu = red[0] * (1.f / Dm);
    __syncthreads();
    float d0 = x0 - mu, d1 = x1 - mu;
    red[tid] = d0 * d0 + d1 * d1;
    __syncthreads();
    #pragma unroll
    for (int s = 128; s > 0; s >>= 1) {
        if (tid < s) red[tid] += red[tid + s];
        __syncthreads();
    }
    float rs = rsqrtf(red[0] * (1.f / Dm) + 1e-5f);
    float v0 = d0 * rs * g[tid] + bet[tid];
    float v1 = d1 * rs * g[tid + 256] + bet[tid + 256];
    out[(long)t * Dm + tid] = v0;
    out[(long)t * Dm + 256 + tid] = v1;
    h16 h, l;
    hsplit(v0, h, l); oh[(long)t * Dm + tid] = h; ol[(long)t * Dm + tid] = l;
    hsplit(v1, h, l); oh[(long)t * Dm + 256 + tid] = h; ol[(long)t * Dm + 256 + tid] = l;
}

// ---------------- router / aux loss / grouping ----------------
__global__ void __launch_bounds__(256) router_k(const float* __restrict__ y,
                                                const float* __restrict__ rw,
                                                const float* __restrict__ rb,
                                                float* __restrict__ probs,
                                                int* __restrict__ topi,
                                                float* __restrict__ gates)
{
    int warp = (blockIdx.x * blockDim.x + threadIdx.x) >> 5;
    int lane = threadIdx.x & 31;
    if (warp >= NT) return;
    const float* x = y + (long)warp * Dm;
    float acc[En];
    #pragma unroll
    for (int e = 0; e < En; e++) acc[e] = 0.f;
    for (int d = lane; d < Dm; d += 32) {
        float xv = x[d];
        const float* w = rw + (long)d * En;
        #pragma unroll
        for (int e = 0; e < En; e++) acc[e] += xv * w[e];
    }
    #pragma unroll
    for (int e = 0; e < En; e++) {
        #pragma unroll
        for (int off = 16; off > 0; off >>= 1)
            acc[e] += __shfl_xor_sync(0xffffffffu, acc[e], off);
    }
    float lg[En], p[En];
    float m = -1e30f;
    #pragma unroll
    for (int e = 0; e < En; e++) { lg[e] = acc[e] + rb[e]; m = fmaxf(m, lg[e]); }
    float sum = 0.f;
    #pragma unroll
    for (int e = 0; e < En; e++) { p[e] = __expf(lg[e] - m); sum += p[e]; }
    float inv = 1.f / sum;
    #pragma unroll
    for (int e = 0; e < En; e++) p[e] *= inv;
    int e0 = 0; float v0 = p[0];
    #pragma unroll
    for (int e = 1; e < En; e++) if (p[e] > v0) { v0 = p[e]; e0 = e; }
    int e1 = -1; float v1 = -1.f;
    #pragma unroll
    for (int e = 0; e < En; e++) if (e != e0 && p[e] > v1) { v1 = p[e]; e1 = e; }
    if (lane == 0) {
        #pragma unroll
        for (int e = 0; e < En; e++) probs[(long)warp * En + e] = p[e];
        float den = 1.f / (v0 + v1);
        topi[warp * 2 + 0] = e0;
        topi[warp * 2 + 1] = e1;
        gates[warp * 2 + 0] = v0 * den;
        gates[warp * 2 + 1] = v1 * den;
    }
}

__global__ void __launch_bounds__(1024) lb_k(const float* __restrict__ probs,
                                             const int* __restrict__ topi,
                                             float* __restrict__ lbout, int first)
{
    __shared__ float sm[1024];
    int tid = threadIdx.x;
    float ps[En], cs[En];
    #pragma unroll
    for (int e = 0; e < En; e++) { ps[e] = 0.f; cs[e] = 0.f; }
    for (int t = tid; t < NT; t += 1024) {
        #pragma unroll
        for (int e = 0; e < En; e++) ps[e] += probs[(long)t * En + e];
        int a = topi[2 * t], b = topi[2 * t + 1];
        #pragma unroll
        for (int e = 0; e < En; e++) cs[e] += (float)((e == a) + (e == b));
    }
    float lb = 0.f;
    for (int e = 0; e < En; e++) {
        sm[tid] = ps[e]; __syncthreads();
        for (int s = 512; s > 0; s >>= 1) { if (tid < s) sm[tid] += sm[tid + s]; __syncthreads(); }
        float P = sm[0]; __syncthreads();
        sm[tid] = cs[e]; __syncthreads();
        for (int s = 512; s > 0; s >>= 1) { if (tid < s) sm[tid] += sm[tid + s]; __syncthreads(); }
        float C = sm[0]; __syncthreads();
        lb += (C * (1.f / NT)) * (P * (1.f / NT));
    }
    if (tid == 0) {
        lb *= (float)En;
        if (first) *lbout = lb; else *lbout += lb;
    }
}

__global__ void __launch_bounds__(256) group_k(const int* __restrict__ topi,
                                               int* __restrict__ perm,
                                               int* __restrict__ offsets)
{
    __shared__ int cnts[En];
    __shared__ int offs_s[En + 1];
    int w = threadIdx.x >> 5, lane = threadIdx.x & 31;
    int c = 0;
    for (int i = lane; i < NEn; i += 32) c += (topi[i] == w);
    #pragma unroll
    for (int off = 16; off > 0; off >>= 1) c += __shfl_xor_sync(0xffffffffu, c, off);
    if (lane == 0) cnts[w] = c;
    __syncthreads();
    if (threadIdx.x == 0) {
        offs_s[0] = 0;
        for (int e = 0; e < En; e++) offs_s[e + 1] = offs_s[e] + cnts[e];
        for (int e = 0; e <= En; e++) offsets[e] = offs_s[e];
    }
    __syncthreads();
    int pos = offs_s[w];
    for (int i0 = 0; i0 < NEn; i0 += 32) {
        int i = i0 + lane;
        int e = topi[i];
        unsigned mk = __ballot_sync(0xffffffffu, e == w);
        if (e == w) {
            int r = __popc(mk & ((1u << lane) - 1u));
            perm[pos + r] = i;
        }
        pos += __popc(mk);
    }
}

// ---------------- host ----------------
extern "C" void kernel_launch(void* const* d_in, const int* in_sizes, int n_in,
                              void* d_out, int out_size)
{
    (void)in_sizes; (void)n_in;
    const int*   ids  = (const int*)d_in[0];
    const float* enc  = (const float*)d_in[1];
    const int*   am   = (const int*)d_in[2];
    const float* emb  = (const float*)d_in[3];
    const float* pos  = (const float*)d_in[4];
    const float* sa_w = (const float*)d_in[5];
    const float* sa_b = (const float*)d_in[6];
    const float* ca_w = (const float*)d_in[7];
    const float* ca_b = (const float*)d_in[8];
    const float* ln_g = (const float*)d_in[9];
    const float* ln_b = (const float*)d_in[10];
    const float* rw   = (const float*)d_in[11];
    const float* rb   = (const float*)d_in[12];
    const float* w1   = (const float*)d_in[13];
    const float* b1   = (const float*)d_in[14];
    const float* w2   = (const float*)d_in[15];
    const float* b2   = (const float*)d_in[16];
    float* out = (float*)d_out;

    float *y, *proj, *probs, *gates, *eout;
    int *topi, *perm, *offs;
    h16 *qkvh, *qkvl, *yh, *yl, *ench, *encl, *ath, *atl, *Hh, *Hl;
    h16 *sawh, *sawl, *cawh, *cawl, *w1h, *w1l, *w2h, *w2l;
    cudaGetSymbolAddress((void**)&y, g_y);
    cudaGetSymbolAddress((void**)&proj, g_proj);
    cudaGetSymbolAddress((void**)&probs, g_probs);
    cudaGetSymbolAddress((void**)&gates, g_gates);
    cudaGetSymbolAddress((void**)&eout, g_eout);
    cudaGetSymbolAddress((void**)&topi, g_topi);
    cudaGetSymbolAddress((void**)&perm, g_perm);
    cudaGetSymbolAddress((void**)&offs, g_offs);
    cudaGetSymbolAddress((void**)&qkvh, g_qkvh);
    cudaGetSymbolAddress((void**)&qkvl, g_qkvl);
    cudaGetSymbolAddress((void**)&yh, g_yh);
    cudaGetSymbolAddress((void**)&yl, g_yl);
    cudaGetSymbolAddress((void**)&ench, g_ench);
    cudaGetSymbolAddress((void**)&encl, g_encl);
    cudaGetSymbolAddress((void**)&ath, g_ath);
    cudaGetSymbolAddress((void**)&atl, g_atl);
    cudaGetSymbolAddress((void**)&Hh, g_Hh);
    cudaGetSymbolAddress((void**)&Hl, g_Hl);
    cudaGetSymbolAddress((void**)&sawh, g_sawh);
    cudaGetSymbolAddress((void**)&sawl, g_sawl);
    cudaGetSymbolAddress((void**)&cawh, g_cawh);
    cudaGetSymbolAddress((void**)&cawl, g_cawl);
    cudaGetSymbolAddress((void**)&w1h, g_w1h);
    cudaGetSymbolAddress((void**)&w1l, g_w1l);
    cudaGetSymbolAddress((void**)&w2h, g_w2h);
    cudaGetSymbolAddress((void**)&w2l, g_w2l);

    cudaFuncSetAttribute(gemm_k<RowAh, EpiBiasH>,   cudaFuncAttributeMaxDynamicSharedMemorySize, GSMEM);
    cudaFuncSetAttribute(gemm_k<RowAh, EpiBias>,    cudaFuncAttributeMaxDynamicSharedMemorySize, GSMEM);
    cudaFuncSetAttribute(gemm_k<GatherAh, EpiMoE1>, cudaFuncAttributeMaxDynamicSharedMemorySize, GSMEM);
    cudaFuncSetAttribute(gemm_k<HRowAh, EpiMoE2>,   cudaFuncAttributeMaxDynamicSharedMemorySize, GSMEM);
    cudaFuncSetAttribute(flash_k, cudaFuncAttributeMaxDynamicSharedMemorySize, FSMEM);

    const long DD = (long)Dm * Dm;
    const long SLOT = (long)NT * Dm;

    wsplit_t_k<<<dim3(16, 16, Ln * 4), 256>>>(sa_w, sawh, sawl, Dm, Dm);
    wsplit_t_k<<<dim3(16, 16, Ln * 4), 256>>>(ca_w, cawh, cawl, Dm, Dm);
    wsplit_t_k<<<dim3(16, 64, Ln * En), 256>>>(w1, w1h, w1l, Dm, FFn);
    wsplit_t_k<<<dim3(64, 16, Ln * En), 256>>>(w2, w2h, w2l, FFn, Dm);
    split_k<<<(NT * Dm + 255) / 256, 256>>>(enc, ench, encl, NT * Dm);

    embed_k<<<NT, 256>>>(ids, emb, pos, y, yh, yl);

    for (int l = 0; l < Ln; l++) {
        gemm_k<<<dim3(16, 8, 3), 256, GSMEM>>>(
            RowAh{yh, yl, Dm, 0, NT}, sawh + l * 4 * DD, sawl + l * 4 * DD, DD,
            EpiBiasH{sa_b + (long)l * 4 * Dm, Dm, qkvh, qkvl, SLOT, Dm}, Dm);
        flash_k<<<dim3(Tn / 64, 16), 256, FSMEM>>>(qkvh, qkvl, qkvh + SLOT, qkvl + SLOT,
                                                   qkvh + 2 * SLOT, qkvl + 2 * SLOT, ath, atl, am, Tn, 1);
        gemm_k<<<dim3(16, 8, 1), 256, GSMEM>>>(
            RowAh{ath, atl, Dm, 0, NT}, sawh + (l * 4 + 3) * DD, sawl + (l * 4 + 3) * DD, 0,
            EpiBias{sa_b + (long)(l * 4 + 3) * Dm, 0, proj, 0, Dm}, Dm);
        add_ln_k<<<NT, 256>>>(y, proj, 1, ln_g + (l * 3 + 0) * Dm, ln_b + (l * 3 + 0) * Dm, y, yh, yl);

        gemm_k<<<dim3(16, 8, 1), 256, GSMEM>>>(
            RowAh{yh, yl, Dm, 0, NT}, cawh + l * 4 * DD, cawl + l * 4 * DD, 0,
            EpiBiasH{ca_b + (long)l * 4 * Dm, 0, qkvh, qkvl, 0, Dm}, Dm);
        gemm_k<<<dim3(16, 8, 2), 256, GSMEM>>>(
            RowAh{ench, encl, Dm, 0, NT}, cawh + (l * 4 + 1) * DD, cawl + (l * 4 + 1) * DD, DD,
            EpiBiasH{ca_b + (long)(l * 4 + 1) * Dm, Dm, qkvh + SLOT, qkvl + SLOT, SLOT, Dm}, Dm);
        flash_k<<<dim3(Tn / 64, 16), 256, FSMEM>>>(qkvh, qkvl, qkvh + SLOT, qkvl + SLOT,
                                                   qkvh + 2 * SLOT, qkvl + 2 * SLOT, ath, atl, nullptr, Tn, 0);
        gemm_k<<<dim3(16, 8, 1), 256, GSMEM>>>(
            RowAh{ath, atl, Dm, 0, NT}, cawh + (l * 4 + 3) * DD, cawl + (l * 4 + 3) * DD, 0,
            EpiBias{ca_b + (long)(l * 4 + 3) * Dm, 0, proj, 0, Dm}, Dm);
        add_ln_k<<<NT, 256>>>(y, proj, 1, ln_g + (l * 3 + 1) * Dm, ln_b + (l * 3 + 1) * Dm, y, yh, yl);

        router_k<<<NT / 8, 256>>>(y, rw + (long)l * Dm * En, rb + l * En, probs, topi, gates);
        lb_k<<<1, 1024>>>(probs, topi, out + (out_size - 1), l == 0 ? 1 : 0);
        group_k<<<1, 256>>>(topi, perm, offs);
        gemm_k<<<dim3(32, 32, En), 256, GSMEM>>>(
            GatherAh{yh, yl, perm, offs, 0},
            w1h + (long)l * En * FFn * Dm, w1l + (long)l * En * FFn * Dm, (long)FFn * Dm,
            EpiMoE1{b1 + (long)l * En * FFn, offs, Hh, Hl, nullptr, nullptr, nullptr}, Dm);
        gemm_k<<<dim3(32, 8, En), 256, GSMEM>>>(
            HRowAh{Hh, Hl, offs, nullptr, nullptr},
            w2h + (long)l * En * Dm * FFn, w2l + (long)l * En * Dm * FFn, (long)Dm * FFn,
            EpiMoE2{b2 + (long)l * En * Dm, offs, perm, gates, eout, nullptr, 0}, FFn);
        float* lnout = (l == Ln - 1) ? out : y;
        add_ln_k<<<NT, 256>>>(y, eout, 2, ln_g + (l * 3 + 2) * Dm, ln_b + (l * 3 + 2) * Dm, lnout, yh, yl);
    }
}

// round 12
// speedup vs baseline: 1.0205x; 1.0205x over previous
#include <cuda_runtime.h>
#include <cuda_fp16.h>
#include <math.h>
#include <stdint.h>

#define Dm   512
#define Tn   1024
#define NT   2048
#define Ln   4
#define En   8
#define FFn  2048
#define NEn  4096
#define DHn  64

typedef __half h16;

// ---------------- scratch ----------------
__device__ __align__(128) float g_y[NT * Dm];
__device__ __align__(128) float g_proj[NT * Dm];
__device__ __align__(128) float g_probs[NT * En];
__device__ __align__(128) float g_gates[NEn];
__device__ __align__(128) float g_eout[(size_t)NEn * Dm];
__device__ int g_topi[NEn];
__device__ int g_perm[NEn];
__device__ int g_offs[En + 1];
__device__ __align__(128) h16 g_qkvh[3 * NT * Dm], g_qkvl[3 * NT * Dm];
__device__ __align__(128) h16 g_yh[NT * Dm],  g_yl[NT * Dm];
__device__ __align__(128) h16 g_ench[NT * Dm], g_encl[NT * Dm];
__device__ __align__(128) h16 g_ath[NT * Dm], g_atl[NT * Dm];
__device__ __align__(128) h16 g_Hh[(size_t)NEn * FFn], g_Hl[(size_t)NEn * FFn];
__device__ __align__(128) h16 g_sawh[(size_t)Ln * 4 * Dm * Dm], g_sawl[(size_t)Ln * 4 * Dm * Dm];
__device__ __align__(128) h16 g_cawh[(size_t)Ln * 4 * Dm * Dm], g_cawl[(size_t)Ln * 4 * Dm * Dm];
__device__ __align__(128) h16 g_w1h[(size_t)Ln * En * FFn * Dm], g_w1l[(size_t)Ln * En * FFn * Dm];
__device__ __align__(128) h16 g_w2h[(size_t)Ln * En * Dm * FFn], g_w2l[(size_t)Ln * En * Dm * FFn];

__device__ __forceinline__ uint32_t smem_u32(const void* p) {
    uint32_t a;
    asm("{ .reg .u64 t; cvta.to.shared.u64 t, %1; cvt.u32.u64 %0, t; }" : "=r"(a) : "l"(p));
    return a;
}
__device__ __forceinline__ void hsplit(float v, h16& h, h16& l) {
    h = __float2half_rn(v);
    l = __float2half_rn(v - __half2float(h));
}
#define CPA(d, s, sz) asm volatile("cp.async.ca.shared.global [%0], [%1], 16, %2;" :: "r"(d), "l"(s), "r"(sz) : "memory")
#define CP_COMMIT()   asm volatile("cp.async.commit_group;" ::: "memory")
#define CP_WAIT1()    asm volatile("cp.async.wait_group 1;" ::: "memory")
#define CP_WAIT0()    asm volatile("cp.async.wait_group 0;" ::: "memory")

__device__ __forceinline__ void mma_f16(float c[4], const uint32_t a[4], const uint32_t b[2])
{
    asm volatile(
        "mma.sync.aligned.m16n8k16.row.col.f32.f16.f16.f32 "
        "{%0,%1,%2,%3},{%4,%5,%6,%7},{%8,%9},{%0,%1,%2,%3};"
        : "+f"(c[0]), "+f"(c[1]), "+f"(c[2]), "+f"(c[3])
        : "r"(a[0]), "r"(a[1]), "r"(a[2]), "r"(a[3]), "r"(b[0]), "r"(b[1]));
}

// ---------------- A providers ----------------
struct RowAh {
    const h16 *Ah, *Al; int lda; long zs; int M;
    __device__ int setz(int z) { Ah += (long)z * zs; Al += (long)z * zs; return M; }
    __device__ const h16* rowh(int m) const { return Ah + (long)m * lda; }
    __device__ const h16* rowl(int m) const { return Al + (long)m * lda; }
};
struct GatherAh {
    const h16 *Yh, *Yl; const int* perm; const int* offs; int base;
    __device__ int setz(int e) { base = offs[e]; return offs[e + 1] - base; }
    __device__ const h16* rowh(int m) const { return Yh + (long)(perm[base + m] >> 1) * Dm; }
    __device__ const h16* rowl(int m) const { return Yl + (long)(perm[base + m] >> 1) * Dm; }
};
struct HRowAh {
    const h16 *Hh, *Hl; const int* offs; const h16 *Ah, *Al;
    __device__ int setz(int e) {
        int b0 = offs[e];
        Ah = Hh + (long)b0 * FFn; Al = Hl + (long)b0 * FFn;
        return offs[e + 1] - b0;
    }
    __device__ const h16* rowh(int m) const { return Ah + (long)m * FFn; }
    __device__ const h16* rowl(int m) const { return Al + (long)m * FFn; }
};
// ---------------- epilogues ----------------
struct EpiBias {
    const float* bias; long biasZ; float* C; long cZ; int ldc;
    __device__ void setz(int z) { bias += (long)z * biasZ; C += (long)z * cZ; }
    __device__ void op(int m, int n, float v) { C[(long)m * ldc + n] = v + bias[n]; }
};
struct EpiBiasH {
    const float* bias; long biasZ; h16* Ch; h16* Cl; long cZ; int ldc;
    __device__ void setz(int z) { bias += (long)z * biasZ; Ch += (long)z * cZ; Cl += (long)z * cZ; }
    __device__ void op(int m, int n, float v) {
        v += bias[n];
        h16 h, l; hsplit(v, h, l);
        Ch[(long)m * ldc + n] = h; Cl[(long)m * ldc + n] = l;
    }
};
struct EpiMoE1 {
    const float* b1l; const int* offs; h16* Hh; h16* Hl;
    const float* bias; h16 *Ch, *Cl;
    __device__ void setz(int e) {
        bias = b1l + (long)e * FFn;
        Ch = Hh + (long)offs[e] * FFn; Cl = Hl + (long)offs[e] * FFn;
    }
    __device__ void op(int m, int n, float v) {
        v = fmaxf(v + bias[n], 0.f);
        h16 h, l; hsplit(v, h, l);
        Ch[(long)m * FFn + n] = h; Cl[(long)m * FFn + n] = l;
    }
};
struct EpiMoE2 {
    const float* b2l; const int* offs; const int* perm; const float* gates; float* eout;
    const float* bias; int base;
    __device__ void setz(int e) { bias = b2l + (long)e * Dm; base = offs[e]; }
    __device__ void op(int m, int n, float v) {
        int entry = perm[base + m];
        eout[(long)entry * Dm + n] = gates[entry] * (v + bias[n]);
    }
};

// ------- fp16x3 GEMM: 128x64 tile, BK=32, 2-stage cp.async (R10 proven) -----
constexpr int STGH = 15360;               // halves per stage
constexpr int GSMEM = 2 * STGH * 2;       // bytes = 61440

template <class AP, class EP>
__global__ void __launch_bounds__(256, 2) gemm_k(AP ap, const h16* __restrict__ BTh,
                                                 const h16* __restrict__ BTl, long bz,
                                                 EP ep, int K)
{
    extern __shared__ h16 smh[];
    int z = blockIdx.z;
    int M = ap.setz(z);
    int m0 = blockIdx.x * 128;
    if (m0 >= M) return;
    ep.setz(z);
    int n0 = blockIdx.y * 64;

    int tid = threadIdx.x, lane = tid & 31, wid = tid >> 5;
    int wm = wid & 3, wn = wid >> 2;
    int g = lane >> 2, tg = lane & 3;
    uint32_t smb = smem_u32(smh);

    int r4 = tid >> 2;
    int c4 = (tid & 3) * 8;
    bool v0 = (m0 + r4) < M, v1 = (m0 + 64 + r4) < M;
    uint32_t szA0 = v0 ? 16u : 0u, szA1 = v1 ? 16u : 0u;
    const h16* sAh0 = ap.rowh(v0 ? m0 + r4 : m0) + c4;
    const h16* sAl0 = ap.rowl(v0 ? m0 + r4 : m0) + c4;
    const h16* sAh1 = ap.rowh(v1 ? m0 + 64 + r4 : m0) + c4;
    const h16* sAl1 = ap.rowl(v1 ? m0 + 64 + r4 : m0) + c4;
    const h16* sBh = BTh + (long)z * bz + (long)(n0 + r4) * K + c4;
    const h16* sBl = BTl + (long)z * bz + (long)(n0 + r4) * K + c4;

    uint32_t dA0 = (uint32_t)r4 * 80 + (uint32_t)(tid & 3) * 16;
    uint32_t dA1 = dA0 + 5120;

    auto issue = [&](int s) {
        uint32_t b = smb + (uint32_t)(s & 1) * (STGH * 2);
        int ko = s * 32;
        CPA(b + dA0, sAh0 + ko, szA0);
        CPA(b + dA1, sAh1 + ko, szA1);
        CPA(b + 10240 + dA0, sAl0 + ko, szA0);
        CPA(b + 10240 + dA1, sAl1 + ko, szA1);
        CPA(b + 20480 + dA0, sBh + ko, 16u);
        CPA(b + 25600 + dA0, sBl + ko, 16u);
        CP_COMMIT();
    };

    float acc[2][4][4];
    #pragma unroll
    for (int mt = 0; mt < 2; mt++)
        #pragma unroll
        for (int nt = 0; nt < 4; nt++)
            #pragma unroll
            for (int j = 0; j < 4; j++) acc[mt][nt][j] = 0.f;

    int ns = K / 32;
    issue(0);
    for (int s = 0; s < ns; s++) {
        bool more = (s + 1 < ns);
        if (more) issue(s + 1);
        if (more) CP_WAIT1(); else CP_WAIT0();
        __syncthreads();

        const uint32_t* W = (const uint32_t*)(smh + (size_t)(s & 1) * STGH);
        #pragma unroll
        for (int kc = 0; kc < 2; kc++) {
            int ko = kc * 8;
            uint32_t ah[2][4], al[2][4];
            #pragma unroll
            for (int mt = 0; mt < 2; mt++) {
                int p = (wm * 32 + g + mt * 16) * 20 + tg + ko;
                ah[mt][0] = W[p];           ah[mt][1] = W[p + 8 * 20];
                ah[mt][2] = W[p + 4];       ah[mt][3] = W[p + 8 * 20 + 4];
                al[mt][0] = W[2560 + p];        al[mt][1] = W[2560 + p + 8 * 20];
                al[mt][2] = W[2560 + p + 4];    al[mt][3] = W[2560 + p + 8 * 20 + 4];
            }
            uint32_t bh[4][2], bl[4][2];
            #pragma unroll
            for (int nt = 0; nt < 4; nt++) {
                int p = (wn * 32 + nt * 8 + g) * 20 + tg + ko;
                bh[nt][0] = W[5120 + p];  bh[nt][1] = W[5120 + p + 4];
                bl[nt][0] = W[6400 + p];  bl[nt][1] = W[6400 + p + 4];
            }
            #pragma unroll
            for (int mt = 0; mt < 2; mt++)
                #pragma unroll
                for (int nt = 0; nt < 4; nt++) {
                    mma_f16(acc[mt][nt], al[mt], bh[nt]);
                    mma_f16(acc[mt][nt], ah[mt], bl[nt]);
                    mma_f16(acc[mt][nt], ah[mt], bh[nt]);
                }
        }
        __syncthreads();
    }

    int r0 = wm * 32 + g;
    int c0 = wn * 32 + tg * 2;
    #pragma unroll
    for (int mt = 0; mt < 2; mt++) {
        int gm0 = m0 + r0 + mt * 16;
        int gm1 = gm0 + 8;
        #pragma unroll
        for (int nt = 0; nt < 4; nt++) {
            int gn = n0 + c0 + nt * 8;
            if (gm0 < M) { ep.op(gm0, gn, acc[mt][nt][0]); ep.op(gm0, gn + 1, acc[mt][nt][1]); }
            if (gm1 < M) { ep.op(gm1, gn, acc[mt][nt][2]); ep.op(gm1, gn + 1, acc[mt][nt][3]); }
        }
    }
}

// -------- weight transpose+split --------
__global__ void __launch_bounds__(256) wsplit_t_k(const float* __restrict__ W,
                                                  h16* __restrict__ Oh, h16* __restrict__ Ol,
                                                  int K, int N)
{
    __shared__ float t[32][33];
    size_t zo = (size_t)blockIdx.z * K * N;
    int k0 = blockIdx.x * 32, n0 = blockIdx.y * 32;
    int tx = threadIdx.x & 31, ty = threadIdx.x >> 5;
    #pragma unroll
    for (int j = 0; j < 32; j += 8)
        t[ty + j][tx] = W[zo + (size_t)(k0 + ty + j) * N + n0 + tx];
    __syncthreads();
    #pragma unroll
    for (int j = 0; j < 32; j += 8) {
        float v = t[tx][ty + j];
        h16 h, l; hsplit(v, h, l);
        size_t o = zo + (size_t)(n0 + ty + j) * K + k0 + tx;
        Oh[o] = h; Ol[o] = l;
    }
}

__global__ void __launch_bounds__(256) split_k(const float* __restrict__ x,
                                               h16* __restrict__ oh, h16* __restrict__ ol, int n)
{
    int i = blockIdx.x * 256 + threadIdx.x;
    if (i < n) { h16 h, l; hsplit(x[i], h, l); oh[i] = h; ol[i] = l; }
}

__global__ void embed_k(const int* __restrict__ ids, const float* __restrict__ emb,
                        const float* __restrict__ pos, float* __restrict__ y,
                        h16* __restrict__ yh, h16* __restrict__ yl)
{
    int t = blockIdx.x;
    int id = ids[t];
    int tq = t & (Tn - 1);
    const float* er = emb + (long)id * Dm;
    const float* pr = pos + (long)tq * Dm;
    long o = (long)t * Dm;
    for (int d = threadIdx.x; d < Dm; d += blockDim.x) {
        float v = er[d] + pr[d];
        y[o + d] = v;
        h16 h, l; hsplit(v, h, l);
        yh[o + d] = h; yl[o + d] = l;
    }
}

// ---------------- tensor-core flash attention -------------------------------
constexpr int FSMEM = 57344;

__global__ void __launch_bounds__(256, 2) flash_k(const h16* __restrict__ Qh, const h16* __restrict__ Ql,
                                                  const h16* __restrict__ Kh, const h16* __restrict__ Kl,
                                                  const h16* __restrict__ Vh, const h16* __restrict__ Vl,
                                                  h16* __restrict__ Oh, h16* __restrict__ Ol,
                                                  const int* __restrict__ am, int Tk, int causal)
{
    extern __shared__ h16 fs[];
    h16 *Qhs = fs, *Qls = fs + 4608, *Khs = fs + 9216, *Kls = fs + 11520;
    h16 *Vths = fs + 13824, *Vtls = fs + 16384, *Phs = fs + 18944, *Pls = fs + 21504;
    float* Ps = (float*)(fs + 24064);
    float* rowm = Ps + 64 * 33;
    float* rowl = rowm + 64;
    float* alph = rowl + 64;

    int q0 = blockIdx.x * 64;
    int bh = blockIdx.y;
    int b = bh >> 3, h = bh & 7;
    const h16* Qbh = Qh + ((long)b * Tn + q0) * Dm + h * DHn;
    const h16* Qbl = Ql + ((long)b * Tn + q0) * Dm + h * DHn;
    const h16* Kbh = Kh + (long)b * Tk * Dm + h * DHn;
    const h16* Kbl = Kl + (long)b * Tk * Dm + h * DHn;
    const h16* Vbh = Vh + (long)b * Tk * Dm + h * DHn;
    const h16* Vbl = Vl + (long)b * Tk * Dm + h * DHn;

    int tid = threadIdx.x, lane = tid & 31, wid = tid >> 5;
    int wm = wid & 3, wn = wid >> 2;
    int g = lane >> 2, tg = lane & 3;

    #pragma unroll
    for (int it = 0; it < 2; it++) {
        int idx = tid + it * 256;
        int r = idx >> 3, c8 = (idx & 7) * 8;
        *(uint4*)(Qhs + r * 72 + c8) = *(const uint4*)(Qbh + (long)r * Dm + c8);
        *(uint4*)(Qls + r * 72 + c8) = *(const uint4*)(Qbl + (long)r * Dm + c8);
    }
    if (tid < 64) { rowm[tid] = -1e30f; rowl[tid] = 0.f; }

    float o[4][4];
    #pragma unroll
    for (int i = 0; i < 4; i++)
        #pragma unroll
        for (int j = 0; j < 4; j++) o[i][j] = 0.f;

    const uint32_t* QWh = (const uint32_t*)Qhs;
    const uint32_t* QWl = (const uint32_t*)Qls;
    const uint32_t* KWh = (const uint32_t*)Khs;
    const uint32_t* KWl = (const uint32_t*)Kls;
    const uint32_t* VWh = (const uint32_t*)Vths;
    const uint32_t* VWl = (const uint32_t*)Vtls;
    const uint32_t* PWh = (const uint32_t*)Phs;
    const uint32_t* PWl = (const uint32_t*)Pls;

    int kvmax = causal ? (q0 + 64) : Tk;
    for (int kv0 = 0; kv0 < kvmax; kv0 += 32) {
        __syncthreads();
        {
            int r = tid >> 3, c8 = (tid & 7) * 8;
            *(uint4*)(Khs + r * 72 + c8) = *(const uint4*)(Kbh + (long)(kv0 + r) * Dm + c8);
            *(uint4*)(Kls + r * 72 + c8) = *(const uint4*)(Kbl + (long)(kv0 + r) * Dm + c8);
            h16 vh8[8], vl8[8];
            *(uint4*)vh8 = *(const uint4*)(Vbh + (long)(kv0 + r) * Dm + c8);
            *(uint4*)vl8 = *(const uint4*)(Vbl + (long)(kv0 + r) * Dm + c8);
            #pragma unroll
            for (int j = 0; j < 8; j++) {
                Vths[(c8 + j) * 40 + r] = vh8[j];
                Vtls[(c8 + j) * 40 + r] = vl8[j];
            }
        }
        __syncthreads();

        float s[2][4] = {{0.f, 0.f, 0.f, 0.f}, {0.f, 0.f, 0.f, 0.f}};
        #pragma unroll
        for (int kc = 0; kc < 4; kc++) {
            int ko = kc * 8;
            int pa = (wm * 16 + g) * 36 + tg + ko;
            uint32_t ah[4], al[4];
            ah[0] = QWh[pa]; ah[1] = QWh[pa + 8 * 36]; ah[2] = QWh[pa + 4]; ah[3] = QWh[pa + 8 * 36 + 4];
            al[0] = QWl[pa]; al[1] = QWl[pa + 8 * 36]; al[2] = QWl[pa + 4]; al[3] = QWl[pa + 8 * 36 + 4];
            #pragma unroll
            for (int nt = 0; nt < 2; nt++) {
                int pb = (wn * 16 + nt * 8 + g) * 36 + tg + ko;
                uint32_t bh2[2] = { KWh[pb], KWh[pb + 4] };
                uint32_t bl2[2] = { KWl[pb], KWl[pb + 4] };
                mma_f16(s[nt], al, bh2);
                mma_f16(s[nt], ah, bl2);
                mma_f16(s[nt], ah, bh2);
            }
        }
        #pragma unroll
        for (int nt = 0; nt < 2; nt++) {
            #pragma unroll
            for (int j = 0; j < 4; j++) {
                int row = wm * 16 + g + (j >> 1) * 8;
                int col = wn * 16 + nt * 8 + tg * 2 + (j & 1);
                float sv = s[nt][j] * 0.125f;
                if (causal) {
                    int kg = kv0 + col, qg = q0 + row;
                    if (kg > qg || am[b * Tn + kg] == 0) sv = -1e9f;
                }
                Ps[row * 33 + col] = sv;
            }
        }
        __syncthreads();
        {
            int row = tid >> 2, sub = tid & 3;
            float mo = rowm[row], mx = mo;
            #pragma unroll
            for (int j = 0; j < 8; j++) mx = fmaxf(mx, Ps[row * 33 + sub * 8 + j]);
            mx = fmaxf(mx, __shfl_xor_sync(0xffffffffu, mx, 1));
            mx = fmaxf(mx, __shfl_xor_sync(0xffffffffu, mx, 2));
            float sum = 0.f;
            #pragma unroll
            for (int j = 0; j < 8; j++) {
                float p = __expf(Ps[row * 33 + sub * 8 + j] - mx);
                h16 ph, pl; hsplit(p, ph, pl);
                Phs[row * 40 + sub * 8 + j] = ph;
                Pls[row * 40 + sub * 8 + j] = pl;
                sum += p;
            }
            sum += __shfl_xor_sync(0xffffffffu, sum, 1);
            sum += __shfl_xor_sync(0xffffffffu, sum, 2);
            if (sub == 0) {
                float al2 = __expf(mo - mx);
                rowm[row] = mx;
                rowl[row] = rowl[row] * al2 + sum;
                alph[row] = al2;
            }
        }
        __syncthreads();
        {
            float a0 = alph[wm * 16 + g], a1 = alph[wm * 16 + g + 8];
            #pragma unroll
            for (int nt = 0; nt < 4; nt++) {
                o[nt][0] *= a0; o[nt][1] *= a0;
                o[nt][2] *= a1; o[nt][3] *= a1;
            }
        }
        #pragma unroll
        for (int kc = 0; kc < 2; kc++) {
            int ko = kc * 8;
            int pa = (wm * 16 + g) * 20 + tg + ko;
            uint32_t ah[4], al[4];
            ah[0] = PWh[pa]; ah[1] = PWh[pa + 8 * 20]; ah[2] = PWh[pa + 4]; ah[3] = PWh[pa + 8 * 20 + 4];
            al[0] = PWl[pa]; al[1] = PWl[pa + 8 * 20]; al[2] = PWl[pa + 4]; al[3] = PWl[pa + 8 * 20 + 4];
            #pragma unroll
            for (int nt = 0; nt < 4; nt++) {
                int pb = (wn * 32 + nt * 8 + g) * 20 + tg + ko;
                uint32_t bh2[2] = { VWh[pb], VWh[pb + 4] };
                uint32_t bl2[2] = { VWl[pb], VWl[pb + 4] };
                mma_f16(o[nt], al, bh2);
                mma_f16(o[nt], ah, bl2);
                mma_f16(o[nt], ah, bh2);
            }
        }
    }
    __syncthreads();
    {
        float inv0 = 1.f / rowl[wm * 16 + g];
        float inv1 = 1.f / rowl[wm * 16 + g + 8];
        int row0 = q0 + wm * 16 + g;
        #pragma unroll
        for (int nt = 0; nt < 4; nt++) {
            int col = h * DHn + wn * 32 + nt * 8 + tg * 2;
            long o0 = ((long)b * Tn + row0) * Dm + col;
            long o1 = ((long)b * Tn + row0 + 8) * Dm + col;
            h16 hh, ll;
            hsplit(o[nt][0] * inv0, hh, ll); Oh[o0] = hh;     Ol[o0] = ll;
            hsplit(o[nt][1] * inv0, hh, ll); Oh[o0 + 1] = hh; Ol[o0 + 1] = ll;
            hsplit(o[nt][2] * inv1, hh, ll); Oh[o1] = hh;     Ol[o1] = ll;
            hsplit(o[nt][3] * inv1, hh, ll); Oh[o1 + 1] = hh; Ol[o1 + 1] = ll;
        }
    }
}

// ---------------- add + layernorm ----------------
__global__ void __launch_bounds__(256) add_ln_k(const float* __restrict__ base,
                                                const float* __restrict__ delta, int nslots,
                                                const float* __restrict__ g,
                                                const float* __restrict__ bet,
                                                float* __restrict__ out,
                                                h16* __restrict__ oh, h16* __restrict__ ol)
{
    int t = blockIdx.x, tid = threadIdx.x;
    __shared__ float red[256];
    float x0 = base[(long)t * Dm + tid];
    float x1 = base[(long)t * Dm + 256 + tid];
    if (nslots == 1) {
        x0 += delta[(long)t * Dm + tid];
        x1 += delta[(long)t * Dm + 256 + tid];
    } else {
        x0 += delta[(long)(t * 2) * Dm + tid] + delta[(long)(t * 2 + 1) * Dm + tid];
        x1 += delta[(long)(t * 2) * Dm + 256 + tid] + delta[(long)(t * 2 + 1) * Dm + 256 + tid];
    }
    red[tid] = x0 + x1;
    __syncthreads();
    #pragma unroll
    for (int s = 128; s > 0; s >>= 1) {
        if (tid < s) red[tid] += red[tid + s];
        __syncthreads();
    }
    float mu = red[0] * (1.f / Dm);
    __syncthreads();
    float d0 = x0 - mu, d1 = x1 - mu;
    red[tid] = d0 * d0 + d1 * d1;
    __syncthreads();
    #pragma unroll
    for (int s = 128; s > 0; s >>= 1) {
        if (tid < s) red[tid] += red[tid + s];
        __syncthreads();
    }
    float rs = rsqrtf(red[0] * (1.f / Dm) + 1e-5f);
    float v0 = d0 * rs * g[tid] + bet[tid];
    float v1 = d1 * rs * g[tid + 256] + bet[tid + 256];
    out[(long)t * Dm + tid] = v0;
    out[(long)t * Dm + 256 + tid] = v1;
    h16 h, l;
    hsplit(v0, h, l); oh[(long)t * Dm + tid] = h; ol[(long)t * Dm + tid] = l;
    hsplit(v1, h, l); oh[(long)t * Dm + 256 + tid] = h; ol[(long)t * Dm + 256 + tid] = l;
}

// ---------------- router / aux loss / grouping ----------------
__global__ void __launch_bounds__(256) router_k(const float* __restrict__ y,
                                                const float* __restrict__ rw,
                                                const float* __restrict__ rb,
                                                float* __restrict__ probs,
                                                int* __restrict__ topi,
                                                float* __restrict__ gates)
{
    int warp = (blockIdx.x * blockDim.x + threadIdx.x) >> 5;
    int lane = threadIdx.x & 31;
    if (warp >= NT) return;
    const float* x = y + (long)warp * Dm;
    float acc[En];
    #pragma unroll
    for (int e = 0; e < En; e++) acc[e] = 0.f;
    for (int d = lane; d < Dm; d += 32) {
        float xv = x[d];
        const float* w = rw + (long)d * En;
        #pragma unroll
        for (int e = 0; e < En; e++) acc[e] += xv * w[e];
    }
    #pragma unroll
    for (int e = 0; e < En; e++) {
        #pragma unroll
        for (int off = 16; off > 0; off >>= 1)
            acc[e] += __shfl_xor_sync(0xffffffffu, acc[e], off);
    }
    float lg[En], p[En];
    float m = -1e30f;
    #pragma unroll
    for (int e = 0; e < En; e++) { lg[e] = acc[e] + rb[e]; m = fmaxf(m, lg[e]); }
    float sum = 0.f;
    #pragma unroll
    for (int e = 0; e < En; e++) { p[e] = __expf(lg[e] - m); sum += p[e]; }
    float inv = 1.f / sum;
    #pragma unroll
    for (int e = 0; e < En; e++) p[e] *= inv;
    int e0 = 0; float v0 = p[0];
    #pragma unroll
    for (int e = 1; e < En; e++) if (p[e] > v0) { v0 = p[e]; e0 = e; }
    int e1 = -1; float v1 = -1.f;
    #pragma unroll
    for (int e = 0; e < En; e++) if (e != e0 && p[e] > v1) { v1 = p[e]; e1 = e; }
    if (lane == 0) {
        #pragma unroll
        for (int e = 0; e < En; e++) probs[(long)warp * En + e] = p[e];
        float den = 1.f / (v0 + v1);
        topi[warp * 2 + 0] = e0;
        topi[warp * 2 + 1] = e1;
        gates[warp * 2 + 0] = v0 * den;
        gates[warp * 2 + 1] = v1 * den;
    }
}

__global__ void __launch_bounds__(1024) lb_k(const float* __restrict__ probs,
                                             const int* __restrict__ topi,
                                             float* __restrict__ lbout, int first)
{
    __shared__ float sm[1024];
    int tid = threadIdx.x;
    float ps[En], cs[En];
    #pragma unroll
    for (int e = 0; e < En; e++) { ps[e] = 0.f; cs[e] = 0.f; }
    for (int t = tid; t < NT; t += 1024) {
        #pragma unroll
        for (int e = 0; e < En; e++) ps[e] += probs[(long)t * En + e];
        int a = topi[2 * t], b = topi[2 * t + 1];
        #pragma unroll
        for (int e = 0; e < En; e++) cs[e] += (float)((e == a) + (e == b));
    }
    float lb = 0.f;
    for (int e = 0; e < En; e++) {
        sm[tid] = ps[e]; __syncthreads();
        for (int s = 512; s > 0; s >>= 1) { if (tid < s) sm[tid] += sm[tid + s]; __syncthreads(); }
        float P = sm[0]; __syncthreads();
        sm[tid] = cs[e]; __syncthreads();
        for (int s = 512; s > 0; s >>= 1) { if (tid < s) sm[tid] += sm[tid + s]; __syncthreads(); }
        float C = sm[0]; __syncthreads();
        lb += (C * (1.f / NT)) * (P * (1.f / NT));
    }
    if (tid == 0) {
        lb *= (float)En;
        if (first) *lbout = lb; else *lbout += lb;
    }
}

__global__ void __launch_bounds__(256) group_k(const int* __restrict__ topi,
                                               int* __restrict__ perm,
                                               int* __restrict__ offsets)
{
    __shared__ int cnts[En];
    __shared__ int offs_s[En + 1];
    int w = threadIdx.x >> 5, lane = threadIdx.x & 31;
    int c = 0;
    for (int i = lane; i < NEn; i += 32) c += (topi[i] == w);
    #pragma unroll
    for (int off = 16; off > 0; off >>= 1) c += __shfl_xor_sync(0xffffffffu, c, off);
    if (lane == 0) cnts[w] = c;
    __syncthreads();
    if (threadIdx.x == 0) {
        offs_s[0] = 0;
        for (int e = 0; e < En; e++) offs_s[e + 1] = offs_s[e] + cnts[e];
        for (int e = 0; e <= En; e++) offsets[e] = offs_s[e];
    }
    __syncthreads();
    int pos = offs_s[w];
    for (int i0 = 0; i0 < NEn; i0 += 32) {
        int i = i0 + lane;
        int e = topi[i];
        unsigned mk = __ballot_sync(0xffffffffu, e == w);
        if (e == w) {
            int r = __popc(mk & ((1u << lane) - 1u));
            perm[pos + r] = i;
        }
        pos += __popc(mk);
    }
}

// ---------------- host ----------------
extern "C" void kernel_launch(void* const* d_in, const int* in_sizes, int n_in,
                              void* d_out, int out_size)
{
    (void)in_sizes; (void)n_in;
    const int*   ids  = (const int*)d_in[0];
    const float* enc  = (const float*)d_in[1];
    const int*   am   = (const int*)d_in[2];
    const float* emb  = (const float*)d_in[3];
    const float* pos  = (const float*)d_in[4];
    const float* sa_w = (const float*)d_in[5];
    const float* sa_b = (const float*)d_in[6];
    const float* ca_w = (const float*)d_in[7];
    const float* ca_b = (const float*)d_in[8];
    const float* ln_g = (const float*)d_in[9];
    const float* ln_b = (const float*)d_in[10];
    const float* rw   = (const float*)d_in[11];
    const float* rb   = (const float*)d_in[12];
    const float* w1   = (const float*)d_in[13];
    const float* b1   = (const float*)d_in[14];
    const float* w2   = (const float*)d_in[15];
    const float* b2   = (const float*)d_in[16];
    float* out = (float*)d_out;

    float *y, *proj, *probs, *gates, *eout;
    int *topi, *perm, *offs;
    h16 *qkvh, *qkvl, *yh, *yl, *ench, *encl, *ath, *atl, *Hh, *Hl;
    h16 *sawh, *sawl, *cawh, *cawl, *w1h, *w1l, *w2h, *w2l;
    cudaGetSymbolAddress((void**)&y, g_y);
    cudaGetSymbolAddress((void**)&proj, g_proj);
    cudaGetSymbolAddress((void**)&probs, g_probs);
    cudaGetSymbolAddress((void**)&gates, g_gates);
    cudaGetSymbolAddress((void**)&eout, g_eout);
    cudaGetSymbolAddress((void**)&topi, g_topi);
    cudaGetSymbolAddress((void**)&perm, g_perm);
    cudaGetSymbolAddress((void**)&offs, g_offs);
    cudaGetSymbolAddress((void**)&qkvh, g_qkvh);
    cudaGetSymbolAddress((void**)&qkvl, g_qkvl);
    cudaGetSymbolAddress((void**)&yh, g_yh);
    cudaGetSymbolAddress((void**)&yl, g_yl);
    cudaGetSymbolAddress((void**)&ench, g_ench);
    cudaGetSymbolAddress((void**)&encl, g_encl);
    cudaGetSymbolAddress((void**)&ath, g_ath);
    cudaGetSymbolAddress((void**)&atl, g_atl);
    cudaGetSymbolAddress((void**)&Hh, g_Hh);
    cudaGetSymbolAddress((void**)&Hl, g_Hl);
    cudaGetSymbolAddress((void**)&sawh, g_sawh);
    cudaGetSymbolAddress((void**)&sawl, g_sawl);
    cudaGetSymbolAddress((void**)&cawh, g_cawh);
    cudaGetSymbolAddress((void**)&cawl, g_cawl);
    cudaGetSymbolAddress((void**)&w1h, g_w1h);
    cudaGetSymbolAddress((void**)&w1l, g_w1l);
    cudaGetSymbolAddress((void**)&w2h, g_w2h);
    cudaGetSymbolAddress((void**)&w2l, g_w2l);

    cudaFuncSetAttribute(gemm_k<RowAh, EpiBiasH>,   cudaFuncAttributeMaxDynamicSharedMemorySize, GSMEM);
    cudaFuncSetAttribute(gemm_k<RowAh, EpiBias>,    cudaFuncAttributeMaxDynamicSharedMemorySize, GSMEM);
    cudaFuncSetAttribute(gemm_k<GatherAh, EpiMoE1>, cudaFuncAttributeMaxDynamicSharedMemorySize, GSMEM);
    cudaFuncSetAttribute(gemm_k<HRowAh, EpiMoE2>,   cudaFuncAttributeMaxDynamicSharedMemorySize, GSMEM);
    cudaFuncSetAttribute(flash_k, cudaFuncAttributeMaxDynamicSharedMemorySize, FSMEM);

    const long DD = (long)Dm * Dm;
    const long SLOT = (long)NT * Dm;

    wsplit_t_k<<<dim3(16, 16, Ln * 4), 256>>>(sa_w, sawh, sawl, Dm, Dm);
    wsplit_t_k<<<dim3(16, 16, Ln * 4), 256>>>(ca_w, cawh, cawl, Dm, Dm);
    wsplit_t_k<<<dim3(16, 64, Ln * En), 256>>>(w1, w1h, w1l, Dm, FFn);
    wsplit_t_k<<<dim3(64, 16, Ln * En), 256>>>(w2, w2h, w2l, FFn, Dm);
    split_k<<<(NT * Dm + 255) / 256, 256>>>(enc, ench, encl, NT * Dm);

    embed_k<<<NT, 256>>>(ids, emb, pos, y, yh, yl);

    for (int l = 0; l < Ln; l++) {
        gemm_k<<<dim3(16, 8, 3), 256, GSMEM>>>(
            RowAh{yh, yl, Dm, 0, NT}, sawh + l * 4 * DD, sawl + l * 4 * DD, DD,
            EpiBiasH{sa_b + (long)l * 4 * Dm, Dm, qkvh, qkvl, SLOT, Dm}, Dm);
        flash_k<<<dim3(Tn / 64, 16), 256, FSMEM>>>(qkvh, qkvl, qkvh + SLOT, qkvl + SLOT,
                                                   qkvh + 2 * SLOT, qkvl + 2 * SLOT, ath, atl, am, Tn, 1);
        gemm_k<<<dim3(16, 8, 1), 256, GSMEM>>>(
            RowAh{ath, atl, Dm, 0, NT}, sawh + (l * 4 + 3) * DD, sawl + (l * 4 + 3) * DD, 0,
            EpiBias{sa_b + (long)(l * 4 + 3) * Dm, 0, proj, 0, Dm}, Dm);
        add_ln_k<<<NT, 256>>>(y, proj, 1, ln_g + (l * 3 + 0) * Dm, ln_b + (l * 3 + 0) * Dm, y, yh, yl);

        gemm_k<<<dim3(16, 8, 1), 256, GSMEM>>>(
            RowAh{yh, yl, Dm, 0, NT}, cawh + l * 4 * DD, cawl + l * 4 * DD, 0,
            EpiBiasH{ca_b + (long)l * 4 * Dm, 0, qkvh, qkvl, 0, Dm}, Dm);
        gemm_k<<<dim3(16, 8, 2), 256, GSMEM>>>(
            RowAh{ench, encl, Dm, 0, NT}, cawh + (l * 4 + 1) * DD, cawl + (l * 4 + 1) * DD, DD,
            EpiBiasH{ca_b + (long)(l * 4 + 1) * Dm, Dm, qkvh + SLOT, qkvl + SLOT, SLOT, Dm}, Dm);
        flash_k<<<dim3(Tn / 64, 16), 256, FSMEM>>>(qkvh, qkvl, qkvh + SLOT, qkvl + SLOT,
                                                   qkvh + 2 * SLOT, qkvl + 2 * SLOT, ath, atl, nullptr, Tn, 0);
        gemm_k<<<dim3(16, 8, 1), 256, GSMEM>>>(
            RowAh{ath, atl, Dm, 0, NT}, cawh + (l * 4 + 3) * DD, cawl + (l * 4 + 3) * DD, 0,
            EpiBias{ca_b + (long)(l * 4 + 3) * Dm, 0, proj, 0, Dm}, Dm);
        add_ln_k<<<NT, 256>>>(y, proj, 1, ln_g + (l * 3 + 1) * Dm, ln_b + (l * 3 + 1) * Dm, y, yh, yl);

        router_k<<<NT / 8, 256>>>(y, rw + (long)l * Dm * En, rb + l * En, probs, topi, gates);
        lb_k<<<1, 1024>>>(probs, topi, out + (out_size - 1), l == 0 ? 1 : 0);
        group_k<<<1, 256>>>(topi, perm, offs);
        gemm_k<<<dim3(32, 32, En), 256, GSMEM>>>(
            GatherAh{yh, yl, perm, offs, 0},
            w1h + (long)l * En * FFn * Dm, w1l + (long)l * En * FFn * Dm, (long)FFn * Dm,
            EpiMoE1{b1 + (long)l * En * FFn, offs, Hh, Hl, nullptr, nullptr, nullptr}, Dm);
        gemm_k<<<dim3(32, 8, En), 256, GSMEM>>>(
            HRowAh{Hh, Hl, offs, nullptr, nullptr},
            w2h + (long)l * En * Dm * FFn, w2l + (long)l * En * Dm * FFn, (long)Dm * FFn,
            EpiMoE2{b2 + (long)l * En * Dm, offs, perm, gates, eout, nullptr, 0}, FFn);
        float* lnout = (l == Ln - 1) ? out : y;
        add_ln_k<<<NT, 256>>>(y, eout, 2, ln_g + (l * 3 + 2) * Dm, ln_b + (l * 3 + 2) * Dm, lnout, yh, yl);
    }
}

// round 13
// speedup vs baseline: 1.0320x; 1.0113x over previous
#include <cuda_runtime.h>
#include <cuda_fp16.h>
#include <math.h>
#include <stdint.h>

#define Dm   512
#define Tn   1024
#define NT   2048
#define Ln   4
#define En   8
#define FFn  2048
#define NEn  4096
#define DHn  64

typedef __half h16;

// ---------------- scratch ----------------
__device__ __align__(128) float g_y[NT * Dm];
__device__ __align__(128) float g_proj[NT * Dm];
__device__ __align__(128) float g_probs[NT * En];
__device__ __align__(128) float g_gates[NEn];
__device__ __align__(128) float g_eout[(size_t)NEn * Dm];
__device__ int g_topi[NEn];
__device__ int g_perm[NEn];
__device__ int g_offs[En + 1];
__device__ __align__(128) h16 g_qkvh[3 * NT * Dm], g_qkvl[3 * NT * Dm];
__device__ __align__(128) h16 g_yh[NT * Dm],  g_yl[NT * Dm];
__device__ __align__(128) h16 g_ench[NT * Dm], g_encl[NT * Dm];
__device__ __align__(128) h16 g_ath[NT * Dm], g_atl[NT * Dm];
__device__ __align__(128) h16 g_Hh[(size_t)NEn * FFn], g_Hl[(size_t)NEn * FFn];
__device__ __align__(128) h16 g_sawh[(size_t)Ln * 4 * Dm * Dm], g_sawl[(size_t)Ln * 4 * Dm * Dm];
__device__ __align__(128) h16 g_cawh[(size_t)Ln * 4 * Dm * Dm], g_cawl[(size_t)Ln * 4 * Dm * Dm];
__device__ __align__(128) h16 g_w1h[(size_t)Ln * En * FFn * Dm], g_w1l[(size_t)Ln * En * FFn * Dm];
__device__ __align__(128) h16 g_w2h[(size_t)Ln * En * Dm * FFn], g_w2l[(size_t)Ln * En * Dm * FFn];

__device__ __forceinline__ uint32_t smem_u32(const void* p) {
    uint32_t a;
    asm("{ .reg .u64 t; cvta.to.shared.u64 t, %1; cvt.u32.u64 %0, t; }" : "=r"(a) : "l"(p));
    return a;
}
__device__ __forceinline__ void hsplit(float v, h16& h, h16& l) {
    h = __float2half_rn(v);
    l = __float2half_rn(v - __half2float(h));
}
#define CPA(d, s, sz) asm volatile("cp.async.ca.shared.global [%0], [%1], 16, %2;" :: "r"(d), "l"(s), "r"(sz) : "memory")
#define CP_COMMIT()   asm volatile("cp.async.commit_group;" ::: "memory")
#define CP_WAIT1()    asm volatile("cp.async.wait_group 1;" ::: "memory")
#define CP_WAIT0()    asm volatile("cp.async.wait_group 0;" ::: "memory")

__device__ __forceinline__ void mma_f16(float c[4], const uint32_t a[4], const uint32_t b[2])
{
    asm volatile(
        "mma.sync.aligned.m16n8k16.row.col.f32.f16.f16.f32 "
        "{%0,%1,%2,%3},{%4,%5,%6,%7},{%8,%9},{%0,%1,%2,%3};"
        : "+f"(c[0]), "+f"(c[1]), "+f"(c[2]), "+f"(c[3])
        : "r"(a[0]), "r"(a[1]), "r"(a[2]), "r"(a[3]), "r"(b[0]), "r"(b[1]));
}

// ---------------- A providers ----------------
struct RowAh {
    const h16 *Ah, *Al; int lda; long zs; int M;
    __device__ int setz(int z) { Ah += (long)z * zs; Al += (long)z * zs; return M; }
    __device__ const h16* rowh(int m) const { return Ah + (long)m * lda; }
    __device__ const h16* rowl(int m) const { return Al + (long)m * lda; }
};
struct CrossAh {   // z==0 -> y (q-proj), z>=1 -> enc (k/v-proj)
    const h16 *Yh, *Yl, *Eh, *El;
    const h16 *Ah, *Al;
    __device__ int setz(int z) {
        Ah = (z == 0) ? Yh : Eh;
        Al = (z == 0) ? Yl : El;
        return NT;
    }
    __device__ const h16* rowh(int m) const { return Ah + (long)m * Dm; }
    __device__ const h16* rowl(int m) const { return Al + (long)m * Dm; }
};
struct GatherAh {
    const h16 *Yh, *Yl; const int* perm; const int* offs; int base;
    __device__ int setz(int e) { base = offs[e]; return offs[e + 1] - base; }
    __device__ const h16* rowh(int m) const { return Yh + (long)(perm[base + m] >> 1) * Dm; }
    __device__ const h16* rowl(int m) const { return Yl + (long)(perm[base + m] >> 1) * Dm; }
};
struct HRowAh {
    const h16 *Hh, *Hl; const int* offs; const h16 *Ah, *Al;
    __device__ int setz(int e) {
        int b0 = offs[e];
        Ah = Hh + (long)b0 * FFn; Al = Hl + (long)b0 * FFn;
        return offs[e + 1] - b0;
    }
    __device__ const h16* rowh(int m) const { return Ah + (long)m * FFn; }
    __device__ const h16* rowl(int m) const { return Al + (long)m * FFn; }
};
// ---------------- epilogues ----------------
struct EpiBias {
    const float* bias; long biasZ; float* C; long cZ; int ldc;
    __device__ void setz(int z) { bias += (long)z * biasZ; C += (long)z * cZ; }
    __device__ void op(int m, int n, float v) { C[(long)m * ldc + n] = v + bias[n]; }
};
struct EpiBiasH {
    const float* bias; long biasZ; h16* Ch; h16* Cl; long cZ; int ldc;
    __device__ void setz(int z) { bias += (long)z * biasZ; Ch += (long)z * cZ; Cl += (long)z * cZ; }
    __device__ void op(int m, int n, float v) {
        v += bias[n];
        h16 h, l; hsplit(v, h, l);
        Ch[(long)m * ldc + n] = h; Cl[(long)m * ldc + n] = l;
    }
};
struct EpiMoE1 {
    const float* b1l; const int* offs; h16* Hh; h16* Hl;
    const float* bias; h16 *Ch, *Cl;
    __device__ void setz(int e) {
        bias = b1l + (long)e * FFn;
        Ch = Hh + (long)offs[e] * FFn; Cl = Hl + (long)offs[e] * FFn;
    }
    __device__ void op(int m, int n, float v) {
        v = fmaxf(v + bias[n], 0.f);
        h16 h, l; hsplit(v, h, l);
        Ch[(long)m * FFn + n] = h; Cl[(long)m * FFn + n] = l;
    }
};
struct EpiMoE2 {
    const float* b2l; const int* offs; const int* perm; const float* gates; float* eout;
    const float* bias; int base;
    __device__ void setz(int e) { bias = b2l + (long)e * Dm; base = offs[e]; }
    __device__ void op(int m, int n, float v) {
        int entry = perm[base + m];
        eout[(long)entry * Dm + n] = gates[entry] * (v + bias[n]);
    }
};

// ------- fp16x3 GEMM: 128x64 tile, BK=32, 2-stage cp.async (R10 proven) -----
constexpr int STGH = 15360;               // halves per stage
constexpr int GSMEM = 2 * STGH * 2;       // bytes = 61440

template <class AP, class EP>
__global__ void __launch_bounds__(256, 2) gemm_k(AP ap, const h16* __restrict__ BTh,
                                                 const h16* __restrict__ BTl, long bz,
                                                 EP ep, int K)
{
    extern __shared__ h16 smh[];
    int z = blockIdx.z;
    int M = ap.setz(z);
    int m0 = blockIdx.x * 128;
    if (m0 >= M) return;
    ep.setz(z);
    int n0 = blockIdx.y * 64;

    int tid = threadIdx.x, lane = tid & 31, wid = tid >> 5;
    int wm = wid & 3, wn = wid >> 2;
    int g = lane >> 2, tg = lane & 3;
    uint32_t smb = smem_u32(smh);

    int r4 = tid >> 2;
    int c4 = (tid & 3) * 8;
    bool v0 = (m0 + r4) < M, v1 = (m0 + 64 + r4) < M;
    uint32_t szA0 = v0 ? 16u : 0u, szA1 = v1 ? 16u : 0u;
    const h16* sAh0 = ap.rowh(v0 ? m0 + r4 : m0) + c4;
    const h16* sAl0 = ap.rowl(v0 ? m0 + r4 : m0) + c4;
    const h16* sAh1 = ap.rowh(v1 ? m0 + 64 + r4 : m0) + c4;
    const h16* sAl1 = ap.rowl(v1 ? m0 + 64 + r4 : m0) + c4;
    const h16* sBh = BTh + (long)z * bz + (long)(n0 + r4) * K + c4;
    const h16* sBl = BTl + (long)z * bz + (long)(n0 + r4) * K + c4;

    uint32_t dA0 = (uint32_t)r4 * 80 + (uint32_t)(tid & 3) * 16;
    uint32_t dA1 = dA0 + 5120;

    auto issue = [&](int s) {
        uint32_t b = smb + (uint32_t)(s & 1) * (STGH * 2);
        int ko = s * 32;
        CPA(b + dA0, sAh0 + ko, szA0);
        CPA(b + dA1, sAh1 + ko, szA1);
        CPA(b + 10240 + dA0, sAl0 + ko, szA0);
        CPA(b + 10240 + dA1, sAl1 + ko, szA1);
        CPA(b + 20480 + dA0, sBh + ko, 16u);
        CPA(b + 25600 + dA0, sBl + ko, 16u);
        CP_COMMIT();
    };

    float acc[2][4][4];
    #pragma unroll
    for (int mt = 0; mt < 2; mt++)
        #pragma unroll
        for (int nt = 0; nt < 4; nt++)
            #pragma unroll
            for (int j = 0; j < 4; j++) acc[mt][nt][j] = 0.f;

    int ns = K / 32;
    issue(0);
    for (int s = 0; s < ns; s++) {
        bool more = (s + 1 < ns);
        if (more) issue(s + 1);
        if (more) CP_WAIT1(); else CP_WAIT0();
        __syncthreads();

        const uint32_t* W = (const uint32_t*)(smh + (size_t)(s & 1) * STGH);
        #pragma unroll
        for (int kc = 0; kc < 2; kc++) {
            int ko = kc * 8;
            uint32_t ah[2][4], al[2][4];
            #pragma unroll
            for (int mt = 0; mt < 2; mt++) {
                int p = (wm * 32 + g + mt * 16) * 20 + tg + ko;
                ah[mt][0] = W[p];           ah[mt][1] = W[p + 8 * 20];
                ah[mt][2] = W[p + 4];       ah[mt][3] = W[p + 8 * 20 + 4];
                al[mt][0] = W[2560 + p];        al[mt][1] = W[2560 + p + 8 * 20];
                al[mt][2] = W[2560 + p + 4];    al[mt][3] = W[2560 + p + 8 * 20 + 4];
            }
            uint32_t bh[4][2], bl[4][2];
            #pragma unroll
            for (int nt = 0; nt < 4; nt++) {
                int p = (wn * 32 + nt * 8 + g) * 20 + tg + ko;
                bh[nt][0] = W[5120 + p];  bh[nt][1] = W[5120 + p + 4];
                bl[nt][0] = W[6400 + p];  bl[nt][1] = W[6400 + p + 4];
            }
            #pragma unroll
            for (int mt = 0; mt < 2; mt++)
                #pragma unroll
                for (int nt = 0; nt < 4; nt++) {
                    mma_f16(acc[mt][nt], al[mt], bh[nt]);
                    mma_f16(acc[mt][nt], ah[mt], bl[nt]);
                    mma_f16(acc[mt][nt], ah[mt], bh[nt]);
                }
        }
        __syncthreads();
    }

    int r0 = wm * 32 + g;
    int c0 = wn * 32 + tg * 2;
    #pragma unroll
    for (int mt = 0; mt < 2; mt++) {
        int gm0 = m0 + r0 + mt * 16;
        int gm1 = gm0 + 8;
        #pragma unroll
        for (int nt = 0; nt < 4; nt++) {
            int gn = n0 + c0 + nt * 8;
            if (gm0 < M) { ep.op(gm0, gn, acc[mt][nt][0]); ep.op(gm0, gn + 1, acc[mt][nt][1]); }
            if (gm1 < M) { ep.op(gm1, gn, acc[mt][nt][2]); ep.op(gm1, gn + 1, acc[mt][nt][3]); }
        }
    }
}

// -------- weight transpose+split --------
__global__ void __launch_bounds__(256) wsplit_t_k(const float* __restrict__ W,
                                                  h16* __restrict__ Oh, h16* __restrict__ Ol,
                                                  int K, int N)
{
    __shared__ float t[32][33];
    size_t zo = (size_t)blockIdx.z * K * N;
    int k0 = blockIdx.x * 32, n0 = blockIdx.y * 32;
    int tx = threadIdx.x & 31, ty = threadIdx.x >> 5;
    #pragma unroll
    for (int j = 0; j < 32; j += 8)
        t[ty + j][tx] = W[zo + (size_t)(k0 + ty + j) * N + n0 + tx];
    __syncthreads();
    #pragma unroll
    for (int j = 0; j < 32; j += 8) {
        float v = t[tx][ty + j];
        h16 h, l; hsplit(v, h, l);
        size_t o = zo + (size_t)(n0 + ty + j) * K + k0 + tx;
        Oh[o] = h; Ol[o] = l;
    }
}

__global__ void __launch_bounds__(256) split_k(const float* __restrict__ x,
                                               h16* __restrict__ oh, h16* __restrict__ ol, int n)
{
    int i = blockIdx.x * 256 + threadIdx.x;
    if (i < n) { h16 h, l; hsplit(x[i], h, l); oh[i] = h; ol[i] = l; }
}

__global__ void embed_k(const int* __restrict__ ids, const float* __restrict__ emb,
                        const float* __restrict__ pos, float* __restrict__ y,
                        h16* __restrict__ yh, h16* __restrict__ yl)
{
    int t = blockIdx.x;
    int id = ids[t];
    int tq = t & (Tn - 1);
    const float* er = emb + (long)id * Dm;
    const float* pr = pos + (long)tq * Dm;
    long o = (long)t * Dm;
    for (int d = threadIdx.x; d < Dm; d += blockDim.x) {
        float v = er[d] + pr[d];
        y[o + d] = v;
        h16 h, l; hsplit(v, h, l);
        yh[o + d] = h; yl[o + d] = l;
    }
}

// ---------------- tensor-core flash attention (R10 proven) -------------------
constexpr int FSMEM = 57344;

__global__ void __launch_bounds__(256) flash_k(const h16* __restrict__ Qh, const h16* __restrict__ Ql,
                                               const h16* __restrict__ Kh, const h16* __restrict__ Kl,
                                               const h16* __restrict__ Vh, const h16* __restrict__ Vl,
                                               h16* __restrict__ Oh, h16* __restrict__ Ol,
                                               const int* __restrict__ am, int Tk, int causal)
{
    extern __shared__ h16 fs[];
    h16 *Qhs = fs, *Qls = fs + 4608, *Khs = fs + 9216, *Kls = fs + 11520;
    h16 *Vths = fs + 13824, *Vtls = fs + 16384, *Phs = fs + 18944, *Pls = fs + 21504;
    float* Ps = (float*)(fs + 24064);
    float* rowm = Ps + 64 * 33;
    float* rowl = rowm + 64;
    float* alph = rowl + 64;

    int q0 = blockIdx.x * 64;
    int bh = blockIdx.y;
    int b = bh >> 3, h = bh & 7;
    const h16* Qbh = Qh + ((long)b * Tn + q0) * Dm + h * DHn;
    const h16* Qbl = Ql + ((long)b * Tn + q0) * Dm + h * DHn;
    const h16* Kbh = Kh + (long)b * Tk * Dm + h * DHn;
    const h16* Kbl = Kl + (long)b * Tk * Dm + h * DHn;
    const h16* Vbh = Vh + (long)b * Tk * Dm + h * DHn;
    const h16* Vbl = Vl + (long)b * Tk * Dm + h * DHn;

    int tid = threadIdx.x, lane = tid & 31, wid = tid >> 5;
    int wm = wid & 3, wn = wid >> 2;
    int g = lane >> 2, tg = lane & 3;

    #pragma unroll
    for (int it = 0; it < 2; it++) {
        int idx = tid + it * 256;
        int r = idx >> 3, c8 = (idx & 7) * 8;
        *(uint4*)(Qhs + r * 72 + c8) = *(const uint4*)(Qbh + (long)r * Dm + c8);
        *(uint4*)(Qls + r * 72 + c8) = *(const uint4*)(Qbl + (long)r * Dm + c8);
    }
    if (tid < 64) { rowm[tid] = -1e30f; rowl[tid] = 0.f; }

    float o[4][4];
    #pragma unroll
    for (int i = 0; i < 4; i++)
        #pragma unroll
        for (int j = 0; j < 4; j++) o[i][j] = 0.f;

    const uint32_t* QWh = (const uint32_t*)Qhs;
    const uint32_t* QWl = (const uint32_t*)Qls;
    const uint32_t* KWh = (const uint32_t*)Khs;
    const uint32_t* KWl = (const uint32_t*)Kls;
    const uint32_t* VWh = (const uint32_t*)Vths;
    const uint32_t* VWl = (const uint32_t*)Vtls;
    const uint32_t* PWh = (const uint32_t*)Phs;
    const uint32_t* PWl = (const uint32_t*)Pls;

    int kvmax = causal ? (q0 + 64) : Tk;
    for (int kv0 = 0; kv0 < kvmax; kv0 += 32) {
        __syncthreads();
        {
            int r = tid >> 3, c8 = (tid & 7) * 8;
            *(uint4*)(Khs + r * 72 + c8) = *(const uint4*)(Kbh + (long)(kv0 + r) * Dm + c8);
            *(uint4*)(Kls + r * 72 + c8) = *(const uint4*)(Kbl + (long)(kv0 + r) * Dm + c8);
            h16 vh8[8], vl8[8];
            *(uint4*)vh8 = *(const uint4*)(Vbh + (long)(kv0 + r) * Dm + c8);
            *(uint4*)vl8 = *(const uint4*)(Vbl + (long)(kv0 + r) * Dm + c8);
            #pragma unroll
            for (int j = 0; j < 8; j++) {
                Vths[(c8 + j) * 40 + r] = vh8[j];
                Vtls[(c8 + j) * 40 + r] = vl8[j];
            }
        }
        __syncthreads();

        float s[2][4] = {{0.f, 0.f, 0.f, 0.f}, {0.f, 0.f, 0.f, 0.f}};
        #pragma unroll
        for (int kc = 0; kc < 4; kc++) {
            int ko = kc * 8;
            int pa = (wm * 16 + g) * 36 + tg + ko;
            uint32_t ah[4], al[4];
            ah[0] = QWh[pa]; ah[1] = QWh[pa + 8 * 36]; ah[2] = QWh[pa + 4]; ah[3] = QWh[pa + 8 * 36 + 4];
            al[0] = QWl[pa]; al[1] = QWl[pa + 8 * 36]; al[2] = QWl[pa + 4]; al[3] = QWl[pa + 8 * 36 + 4];
            #pragma unroll
            for (int nt = 0; nt < 2; nt++) {
                int pb = (wn * 16 + nt * 8 + g) * 36 + tg + ko;
                uint32_t bh2[2] = { KWh[pb], KWh[pb + 4] };
                uint32_t bl2[2] = { KWl[pb], KWl[pb + 4] };
                mma_f16(s[nt], al, bh2);
                mma_f16(s[nt], ah, bl2);
                mma_f16(s[nt], ah, bh2);
            }
        }
        #pragma unroll
        for (int nt = 0; nt < 2; nt++) {
            #pragma unroll
            for (int j = 0; j < 4; j++) {
                int row = wm * 16 + g + (j >> 1) * 8;
                int col = wn * 16 + nt * 8 + tg * 2 + (j & 1);
                float sv = s[nt][j] * 0.125f;
                if (causal) {
                    int kg = kv0 + col, qg = q0 + row;
                    if (kg > qg || am[b * Tn + kg] == 0) sv = -1e9f;
                }
                Ps[row * 33 + col] = sv;
            }
        }
        __syncthreads();
        {
            int row = tid >> 2, sub = tid & 3;
            float mo = rowm[row], mx = mo;
            #pragma unroll
            for (int j = 0; j < 8; j++) mx = fmaxf(mx, Ps[row * 33 + sub * 8 + j]);
            mx = fmaxf(mx, __shfl_xor_sync(0xffffffffu, mx, 1));
            mx = fmaxf(mx, __shfl_xor_sync(0xffffffffu, mx, 2));
            float sum = 0.f;
            #pragma unroll
            for (int j = 0; j < 8; j++) {
                float p = __expf(Ps[row * 33 + sub * 8 + j] - mx);
                h16 ph, pl; hsplit(p, ph, pl);
                Phs[row * 40 + sub * 8 + j] = ph;
                Pls[row * 40 + sub * 8 + j] = pl;
                sum += p;
            }
            sum += __shfl_xor_sync(0xffffffffu, sum, 1);
            sum += __shfl_xor_sync(0xffffffffu, sum, 2);
            if (sub == 0) {
                float al2 = __expf(mo - mx);
                rowm[row] = mx;
                rowl[row] = rowl[row] * al2 + sum;
                alph[row] = al2;
            }
        }
        __syncthreads();
        {
            float a0 = alph[wm * 16 + g], a1 = alph[wm * 16 + g + 8];
            #pragma unroll
            for (int nt = 0; nt < 4; nt++) {
                o[nt][0] *= a0; o[nt][1] *= a0;
                o[nt][2] *= a1; o[nt][3] *= a1;
            }
        }
        #pragma unroll
        for (int kc = 0; kc < 2; kc++) {
            int ko = kc * 8;
            int pa = (wm * 16 + g) * 20 + tg + ko;
            uint32_t ah[4], al[4];
            ah[0] = PWh[pa]; ah[1] = PWh[pa + 8 * 20]; ah[2] = PWh[pa + 4]; ah[3] = PWh[pa + 8 * 20 + 4];
            al[0] = PWl[pa]; al[1] = PWl[pa + 8 * 20]; al[2] = PWl[pa + 4]; al[3] = PWl[pa + 8 * 20 + 4];
            #pragma unroll
            for (int nt = 0; nt < 4; nt++) {
                int pb = (wn * 32 + nt * 8 + g) * 20 + tg + ko;
                uint32_t bh2[2] = { VWh[pb], VWh[pb + 4] };
                uint32_t bl2[2] = { VWl[pb], VWl[pb + 4] };
                mma_f16(o[nt], al, bh2);
                mma_f16(o[nt], ah, bl2);
                mma_f16(o[nt], ah, bh2);
            }
        }
    }
    __syncthreads();
    {
        float inv0 = 1.f / rowl[wm * 16 + g];
        float inv1 = 1.f / rowl[wm * 16 + g + 8];
        int row0 = q0 + wm * 16 + g;
        #pragma unroll
        for (int nt = 0; nt < 4; nt++) {
            int col = h * DHn + wn * 32 + nt * 8 + tg * 2;
            long o0 = ((long)b * Tn + row0) * Dm + col;
            long o1 = ((long)b * Tn + row0 + 8) * Dm + col;
            h16 hh, ll;
            hsplit(o[nt][0] * inv0, hh, ll); Oh[o0] = hh;     Ol[o0] = ll;
            hsplit(o[nt][1] * inv0, hh, ll); Oh[o0 + 1] = hh; Ol[o0 + 1] = ll;
            hsplit(o[nt][2] * inv1, hh, ll); Oh[o1] = hh;     Ol[o1] = ll;
            hsplit(o[nt][3] * inv1, hh, ll); Oh[o1 + 1] = hh; Ol[o1 + 1] = ll;
        }
    }
}

// ---------------- add + layernorm ----------------
__global__ void __launch_bounds__(256) add_ln_k(const float* __restrict__ base,
                                                const float* __restrict__ delta, int nslots,
                                                const float* __restrict__ g,
                                                const float* __restrict__ bet,
                                                float* __restrict__ out,
                                                h16* __restrict__ oh, h16* __restrict__ ol)
{
    int t = blockIdx.x, tid = threadIdx.x;
    __shared__ float red[256];
    float x0 = base[(long)t * Dm + tid];
    float x1 = base[(long)t * Dm + 256 + tid];
    if (nslots == 1) {
        x0 += delta[(long)t * Dm + tid];
        x1 += delta[(long)t * Dm + 256 + tid];
    } else {
        x0 += delta[(long)(t * 2) * Dm + tid] + delta[(long)(t * 2 + 1) * Dm + tid];
        x1 += delta[(long)(t * 2) * Dm + 256 + tid] + delta[(long)(t * 2 + 1) * Dm + 256 + tid];
    }
    red[tid] = x0 + x1;
    __syncthreads();
    #pragma unroll
    for (int s = 128; s > 0; s >>= 1) {
        if (tid < s) red[tid] += red[tid + s];
        __syncthreads();
    }
    float mu = red[0] * (1.f / Dm);
    __syncthreads();
    float d0 = x0 - mu, d1 = x1 - mu;
    red[tid] = d0 * d0 + d1 * d1;
    __syncthreads();
    #pragma unroll
    for (int s = 128; s > 0; s >>= 1) {
        if (tid < s) red[tid] += red[tid + s];
        __syncthreads();
    }
    float rs = rsqrtf(red[0] * (1.f / Dm) + 1e-5f);
    float v0 = d0 * rs * g[tid] + bet[tid];
    float v1 = d1 * rs * g[tid + 256] + bet[tid + 256];
    out[(long)t * Dm + tid] = v0;
    out[(long)t * Dm + 256 + tid] = v1;
    h16 h, l;
    hsplit(v0, h, l); oh[(long)t * Dm + tid] = h; ol[(long)t * Dm + tid] = l;
    hsplit(v1, h, l); oh[(long)t * Dm + 256 + tid] = h; ol[(long)t * Dm + 256 + tid] = l;
}

// ---------------- router / aux loss / grouping ----------------
__global__ void __launch_bounds__(256) router_k(const float* __restrict__ y,
                                                const float* __restrict__ rw,
                                                const float* __restrict__ rb,
                                                float* __restrict__ probs,
                                                int* __restrict__ topi,
                                                float* __restrict__ gates)
{
    int warp = (blockIdx.x * blockDim.x + threadIdx.x) >> 5;
    int lane = threadIdx.x & 31;
    if (warp >= NT) return;
    const float* x = y + (long)warp * Dm;
    float acc[En];
    #pragma unroll
    for (int e = 0; e < En; e++) acc[e] = 0.f;
    for (int d = lane; d < Dm; d += 32) {
        float xv = x[d];
        const float* w = rw + (long)d * En;
        #pragma unroll
        for (int e = 0; e < En; e++) acc[e] += xv * w[e];
    }
    #pragma unroll
    for (int e = 0; e < En; e++) {
        #pragma unroll
        for (int off = 16; off > 0; off >>= 1)
            acc[e] += __shfl_xor_sync(0xffffffffu, acc[e], off);
    }
    float lg[En], p[En];
    float m = -1e30f;
    #pragma unroll
    for (int e = 0; e < En; e++) { lg[e] = acc[e] + rb[e]; m = fmaxf(m, lg[e]); }
    float sum = 0.f;
    #pragma unroll
    for (int e = 0; e < En; e++) { p[e] = __expf(lg[e] - m); sum += p[e]; }
    float inv = 1.f / sum;
    #pragma unroll
    for (int e = 0; e < En; e++) p[e] *= inv;
    int e0 = 0; float v0 = p[0];
    #pragma unroll
    for (int e = 1; e < En; e++) if (p[e] > v0) { v0 = p[e]; e0 = e; }
    int e1 = -1; float v1 = -1.f;
    #pragma unroll
    for (int e = 0; e < En; e++) if (e != e0 && p[e] > v1) { v1 = p[e]; e1 = e; }
    if (lane == 0) {
        #pragma unroll
        for (int e = 0; e < En; e++) probs[(long)warp * En + e] = p[e];
        float den = 1.f / (v0 + v1);
        topi[warp * 2 + 0] = e0;
        topi[warp * 2 + 1] = e1;
        gates[warp * 2 + 0] = v0 * den;
        gates[warp * 2 + 1] = v1 * den;
    }
}

__global__ void __launch_bounds__(1024) lb_k(const float* __restrict__ probs,
                                             const int* __restrict__ topi,
                                             float* __restrict__ lbout, int first)
{
    __shared__ float sm[1024];
    int tid = threadIdx.x;
    float ps[En], cs[En];
    #pragma unroll
    for (int e = 0; e < En; e++) { ps[e] = 0.f; cs[e] = 0.f; }
    for (int t = tid; t < NT; t += 1024) {
        #pragma unroll
        for (int e = 0; e < En; e++) ps[e] += probs[(long)t * En + e];
        int a = topi[2 * t], b = topi[2 * t + 1];
        #pragma unroll
        for (int e = 0; e < En; e++) cs[e] += (float)((e == a) + (e == b));
    }
    float lb = 0.f;
    for (int e = 0; e < En; e++) {
        sm[tid] = ps[e]; __syncthreads();
        for (int s = 512; s > 0; s >>= 1) { if (tid < s) sm[tid] += sm[tid + s]; __syncthreads(); }
        float P = sm[0]; __syncthreads();
        sm[tid] = cs[e]; __syncthreads();
        for (int s = 512; s > 0; s >>= 1) { if (tid < s) sm[tid] += sm[tid + s]; __syncthreads(); }
        float C = sm[0]; __syncthreads();
        lb += (C * (1.f / NT)) * (P * (1.f / NT));
    }
    if (tid == 0) {
        lb *= (float)En;
        if (first) *lbout = lb; else *lbout += lb;
    }
}

__global__ void __launch_bounds__(256) group_k(const int* __restrict__ topi,
                                               int* __restrict__ perm,
                                               int* __restrict__ offsets)
{
    __shared__ int cnts[En];
    __shared__ int offs_s[En + 1];
    int w = threadIdx.x >> 5, lane = threadIdx.x & 31;
    int c = 0;
    for (int i = lane; i < NEn; i += 32) c += (topi[i] == w);
    #pragma unroll
    for (int off = 16; off > 0; off >>= 1) c += __shfl_xor_sync(0xffffffffu, c, off);
    if (lane == 0) cnts[w] = c;
    __syncthreads();
    if (threadIdx.x == 0) {
        offs_s[0] = 0;
        for (int e = 0; e < En; e++) offs_s[e + 1] = offs_s[e] + cnts[e];
        for (int e = 0; e <= En; e++) offsets[e] = offs_s[e];
    }
    __syncthreads();
    int pos = offs_s[w];
    for (int i0 = 0; i0 < NEn; i0 += 32) {
        int i = i0 + lane;
        int e = topi[i];
        unsigned mk = __ballot_sync(0xffffffffu, e == w);
        if (e == w) {
            int r = __popc(mk & ((1u << lane) - 1u));
            perm[pos + r] = i;
        }
        pos += __popc(mk);
    }
}

// ---------------- host ----------------
extern "C" void kernel_launch(void* const* d_in, const int* in_sizes, int n_in,
                              void* d_out, int out_size)
{
    (void)in_sizes; (void)n_in;
    const int*   ids  = (const int*)d_in[0];
    const float* enc  = (const float*)d_in[1];
    const int*   am   = (const int*)d_in[2];
    const float* emb  = (const float*)d_in[3];
    const float* pos  = (const float*)d_in[4];
    const float* sa_w = (const float*)d_in[5];
    const float* sa_b = (const float*)d_in[6];
    const float* ca_w = (const float*)d_in[7];
    const float* ca_b = (const float*)d_in[8];
    const float* ln_g = (const float*)d_in[9];
    const float* ln_b = (const float*)d_in[10];
    const float* rw   = (const float*)d_in[11];
    const float* rb   = (const float*)d_in[12];
    const float* w1   = (const float*)d_in[13];
    const float* b1   = (const float*)d_in[14];
    const float* w2   = (const float*)d_in[15];
    const float* b2   = (const float*)d_in[16];
    float* out = (float*)d_out;

    float *y, *proj, *probs, *gates, *eout;
    int *topi, *perm, *offs;
    h16 *qkvh, *qkvl, *yh, *yl, *ench, *encl, *ath, *atl, *Hh, *Hl;
    h16 *sawh, *sawl, *cawh, *cawl, *w1h, *w1l, *w2h, *w2l;
    cudaGetSymbolAddress((void**)&y, g_y);
    cudaGetSymbolAddress((void**)&proj, g_proj);
    cudaGetSymbolAddress((void**)&probs, g_probs);
    cudaGetSymbolAddress((void**)&gates, g_gates);
    cudaGetSymbolAddress((void**)&eout, g_eout);
    cudaGetSymbolAddress((void**)&topi, g_topi);
    cudaGetSymbolAddress((void**)&perm, g_perm);
    cudaGetSymbolAddress((void**)&offs, g_offs);
    cudaGetSymbolAddress((void**)&qkvh, g_qkvh);
    cudaGetSymbolAddress((void**)&qkvl, g_qkvl);
    cudaGetSymbolAddress((void**)&yh, g_yh);
    cudaGetSymbolAddress((void**)&yl, g_yl);
    cudaGetSymbolAddress((void**)&ench, g_ench);
    cudaGetSymbolAddress((void**)&encl, g_encl);
    cudaGetSymbolAddress((void**)&ath, g_ath);
    cudaGetSymbolAddress((void**)&atl, g_atl);
    cudaGetSymbolAddress((void**)&Hh, g_Hh);
    cudaGetSymbolAddress((void**)&Hl, g_Hl);
    cudaGetSymbolAddress((void**)&sawh, g_sawh);
    cudaGetSymbolAddress((void**)&sawl, g_sawl);
    cudaGetSymbolAddress((void**)&cawh, g_cawh);
    cudaGetSymbolAddress((void**)&cawl, g_cawl);
    cudaGetSymbolAddress((void**)&w1h, g_w1h);
    cudaGetSymbolAddress((void**)&w1l, g_w1l);
    cudaGetSymbolAddress((void**)&w2h, g_w2h);
    cudaGetSymbolAddress((void**)&w2l, g_w2l);

    cudaFuncSetAttribute(gemm_k<RowAh, EpiBiasH>,    cudaFuncAttributeMaxDynamicSharedMemorySize, GSMEM);
    cudaFuncSetAttribute(gemm_k<RowAh, EpiBias>,     cudaFuncAttributeMaxDynamicSharedMemorySize, GSMEM);
    cudaFuncSetAttribute(gemm_k<CrossAh, EpiBiasH>,  cudaFuncAttributeMaxDynamicSharedMemorySize, GSMEM);
    cudaFuncSetAttribute(gemm_k<GatherAh, EpiMoE1>,  cudaFuncAttributeMaxDynamicSharedMemorySize, GSMEM);
    cudaFuncSetAttribute(gemm_k<HRowAh, EpiMoE2>,    cudaFuncAttributeMaxDynamicSharedMemorySize, GSMEM);
    cudaFuncSetAttribute(flash_k, cudaFuncAttributeMaxDynamicSharedMemorySize, FSMEM);

    const long DD = (long)Dm * Dm;
    const long SLOT = (long)NT * Dm;

    wsplit_t_k<<<dim3(16, 16, Ln * 4), 256>>>(sa_w, sawh, sawl, Dm, Dm);
    wsplit_t_k<<<dim3(16, 16, Ln * 4), 256>>>(ca_w, cawh, cawl, Dm, Dm);
    wsplit_t_k<<<dim3(16, 64, Ln * En), 256>>>(w1, w1h, w1l, Dm, FFn);
    wsplit_t_k<<<dim3(64, 16, Ln * En), 256>>>(w2, w2h, w2l, FFn, Dm);
    split_k<<<(NT * Dm + 255) / 256, 256>>>(enc, ench, encl, NT * Dm);

    embed_k<<<NT, 256>>>(ids, emb, pos, y, yh, yl);

    for (int l = 0; l < Ln; l++) {
        gemm_k<<<dim3(16, 8, 3), 256, GSMEM>>>(
            RowAh{yh, yl, Dm, 0, NT}, sawh + l * 4 * DD, sawl + l * 4 * DD, DD,
            EpiBiasH{sa_b + (long)l * 4 * Dm, Dm, qkvh, qkvl, SLOT, Dm}, Dm);
        flash_k<<<dim3(Tn / 64, 16), 256, FSMEM>>>(qkvh, qkvl, qkvh + SLOT, qkvl + SLOT,
                                                   qkvh + 2 * SLOT, qkvl + 2 * SLOT, ath, atl, am, Tn, 1);
        gemm_k<<<dim3(16, 8, 1), 256, GSMEM>>>(
            RowAh{ath, atl, Dm, 0, NT}, sawh + (l * 4 + 3) * DD, sawl + (l * 4 + 3) * DD, 0,
            EpiBias{sa_b + (long)(l * 4 + 3) * Dm, 0, proj, 0, Dm}, Dm);
        add_ln_k<<<NT, 256>>>(y, proj, 1, ln_g + (l * 3 + 0) * Dm, ln_b + (l * 3 + 0) * Dm, y, yh, yl);

        // fused cross-attn q+k+v projection (z=0 from y, z=1/2 from enc)
        gemm_k<<<dim3(16, 8, 3), 256, GSMEM>>>(
            CrossAh{yh, yl, ench, encl, nullptr, nullptr},
            cawh + l * 4 * DD, cawl + l * 4 * DD, DD,
            EpiBiasH{ca_b + (long)l * 4 * Dm, Dm, qkvh, qkvl, SLOT, Dm}, Dm);
        flash_k<<<dim3(Tn / 64, 16), 256, FSMEM>>>(qkvh, qkvl, qkvh + SLOT, qkvl + SLOT,
                                                   qkvh + 2 * SLOT, qkvl + 2 * SLOT, ath, atl, nullptr, Tn, 0);
        gemm_k<<<dim3(16, 8, 1), 256, GSMEM>>>(
            RowAh{ath, atl, Dm, 0, NT}, cawh + (l * 4 + 3) * DD, cawl + (l * 4 + 3) * DD, 0,
            EpiBias{ca_b + (long)(l * 4 + 3) * Dm, 0, proj, 0, Dm}, Dm);
        add_ln_k<<<NT, 256>>>(y, proj, 1, ln_g + (l * 3 + 1) * Dm, ln_b + (l * 3 + 1) * Dm, y, yh, yl);

        router_k<<<NT / 8, 256>>>(y, rw + (long)l * Dm * En, rb + l * En, probs, topi, gates);
        lb_k<<<1, 1024>>>(probs, topi, out + (out_size - 1), l == 0 ? 1 : 0);
        group_k<<<1, 256>>>(topi, perm, offs);
        gemm_k<<<dim3(32, 32, En), 256, GSMEM>>>(
            GatherAh{yh, yl, perm, offs, 0},
            w1h + (long)l * En * FFn * Dm, w1l + (long)l * En * FFn * Dm, (long)FFn * Dm,
            EpiMoE1{b1 + (long)l * En * FFn, offs, Hh, Hl, nullptr, nullptr, nullptr}, Dm);
        gemm_k<<<dim3(32, 8, En), 256, GSMEM>>>(
            HRowAh{Hh, Hl, offs, nullptr, nullptr},
            w2h + (long)l * En * Dm * FFn, w2l + (long)l * En * Dm * FFn, (long)Dm * FFn,
            EpiMoE2{b2 + (long)l * En * Dm, offs, perm, gates, eout, nullptr, 0}, FFn);
        float* lnout = (l == Ln - 1) ? out : y;
        add_ln_k<<<NT, 256>>>(y, eout, 2, ln_g + (l * 3 + 2) * Dm, ln_b + (l * 3 + 2) * Dm, lnout, yh, yl);
    }
}

// round 14
// speedup vs baseline: 1.0552x; 1.0225x over previous
#include <cuda_runtime.h>
#include <cuda_fp16.h>
#include <math.h>
#include <stdint.h>

#define Dm   512
#define Tn   1024
#define NT   2048
#define Ln   4
#define En   8
#define FFn  2048
#define NEn  4096
#define DHn  64

typedef __half h16;

// ---------------- scratch ----------------
__device__ __align__(128) float g_y[NT * Dm];
__device__ __align__(128) float g_proj[NT * Dm];
__device__ __align__(128) float g_probs[NT * En];
__device__ __align__(128) float g_gates[NEn];
__device__ __align__(128) float g_eout[(size_t)NEn * Dm];
__device__ int g_topi[NEn];
__device__ int g_perm[NEn];
__device__ int g_offs[En + 1];
__device__ __align__(128) h16 g_qkvh[3 * NT * Dm], g_qkvl[3 * NT * Dm];
__device__ __align__(128) h16 g_yh[NT * Dm],  g_yl[NT * Dm];
__device__ __align__(128) h16 g_ench[NT * Dm], g_encl[NT * Dm];
__device__ __align__(128) h16 g_ath[NT * Dm], g_atl[NT * Dm];
__device__ __align__(128) h16 g_Hh[(size_t)NEn * FFn], g_Hl[(size_t)NEn * FFn];
__device__ __align__(128) h16 g_sawh[(size_t)Ln * 4 * Dm * Dm], g_sawl[(size_t)Ln * 4 * Dm * Dm];
__device__ __align__(128) h16 g_cawh[(size_t)Ln * 4 * Dm * Dm], g_cawl[(size_t)Ln * 4 * Dm * Dm];
__device__ __align__(128) h16 g_w1h[(size_t)Ln * En * FFn * Dm], g_w1l[(size_t)Ln * En * FFn * Dm];
__device__ __align__(128) h16 g_w2h[(size_t)Ln * En * Dm * FFn], g_w2l[(size_t)Ln * En * Dm * FFn];

__device__ __forceinline__ uint32_t smem_u32(const void* p) {
    uint32_t a;
    asm("{ .reg .u64 t; cvta.to.shared.u64 t, %1; cvt.u32.u64 %0, t; }" : "=r"(a) : "l"(p));
    return a;
}
__device__ __forceinline__ void hsplit(float v, h16& h, h16& l) {
    h = __float2half_rn(v);
    l = __float2half_rn(v - __half2float(h));
}
#define CPA(d, s, sz) asm volatile("cp.async.ca.shared.global [%0], [%1], 16, %2;" :: "r"(d), "l"(s), "r"(sz) : "memory")
#define CP_COMMIT()   asm volatile("cp.async.commit_group;" ::: "memory")
#define CP_WAIT1()    asm volatile("cp.async.wait_group 1;" ::: "memory")
#define CP_WAIT0()    asm volatile("cp.async.wait_group 0;" ::: "memory")

__device__ __forceinline__ void mma_f16(float c[4], const uint32_t a[4], const uint32_t b[2])
{
    asm volatile(
        "mma.sync.aligned.m16n8k16.row.col.f32.f16.f16.f32 "
        "{%0,%1,%2,%3},{%4,%5,%6,%7},{%8,%9},{%0,%1,%2,%3};"
        : "+f"(c[0]), "+f"(c[1]), "+f"(c[2]), "+f"(c[3])
        : "r"(a[0]), "r"(a[1]), "r"(a[2]), "r"(a[3]), "r"(b[0]), "r"(b[1]));
}
__device__ __forceinline__ void ldsm_x4(uint32_t r[4], uint32_t addr)
{
    asm volatile("ldmatrix.sync.aligned.m8n8.x4.shared.b16 {%0,%1,%2,%3}, [%4];"
        : "=r"(r[0]), "=r"(r[1]), "=r"(r[2]), "=r"(r[3]) : "r"(addr));
}

// ---------------- A providers ----------------
struct RowAh {
    const h16 *Ah, *Al; int lda; long zs; int M;
    __device__ int setz(int z) { Ah += (long)z * zs; Al += (long)z * zs; return M; }
    __device__ const h16* rowh(int m) const { return Ah + (long)m * lda; }
    __device__ const h16* rowl(int m) const { return Al + (long)m * lda; }
};
struct CrossAh {   // z==0 -> y (q-proj), z>=1 -> enc (k/v-proj)
    const h16 *Yh, *Yl, *Eh, *El;
    const h16 *Ah, *Al;
    __device__ int setz(int z) {
        Ah = (z == 0) ? Yh : Eh;
        Al = (z == 0) ? Yl : El;
        return NT;
    }
    __device__ const h16* rowh(int m) const { return Ah + (long)m * Dm; }
    __device__ const h16* rowl(int m) const { return Al + (long)m * Dm; }
};
struct GatherAh {
    const h16 *Yh, *Yl; const int* perm; const int* offs; int base;
    __device__ int setz(int e) { base = offs[e]; return offs[e + 1] - base; }
    __device__ const h16* rowh(int m) const { return Yh + (long)(perm[base + m] >> 1) * Dm; }
    __device__ const h16* rowl(int m) const { return Yl + (long)(perm[base + m] >> 1) * Dm; }
};
struct HRowAh {
    const h16 *Hh, *Hl; const int* offs; const h16 *Ah, *Al;
    __device__ int setz(int e) {
        int b0 = offs[e];
        Ah = Hh + (long)b0 * FFn; Al = Hl + (long)b0 * FFn;
        return offs[e + 1] - b0;
    }
    __device__ const h16* rowh(int m) const { return Ah + (long)m * FFn; }
    __device__ const h16* rowl(int m) const { return Al + (long)m * FFn; }
};
// ---------------- epilogues ----------------
struct EpiBias {
    const float* bias; long biasZ; float* C; long cZ; int ldc;
    __device__ void setz(int z) { bias += (long)z * biasZ; C += (long)z * cZ; }
    __device__ void op(int m, int n, float v) { C[(long)m * ldc + n] = v + bias[n]; }
};
struct EpiBiasH {
    const float* bias; long biasZ; h16* Ch; h16* Cl; long cZ; int ldc;
    __device__ void setz(int z) { bias += (long)z * biasZ; Ch += (long)z * cZ; Cl += (long)z * cZ; }
    __device__ void op(int m, int n, float v) {
        v += bias[n];
        h16 h, l; hsplit(v, h, l);
        Ch[(long)m * ldc + n] = h; Cl[(long)m * ldc + n] = l;
    }
};
struct EpiMoE1 {
    const float* b1l; const int* offs; h16* Hh; h16* Hl;
    const float* bias; h16 *Ch, *Cl;
    __device__ void setz(int e) {
        bias = b1l + (long)e * FFn;
        Ch = Hh + (long)offs[e] * FFn; Cl = Hl + (long)offs[e] * FFn;
    }
    __device__ void op(int m, int n, float v) {
        v = fmaxf(v + bias[n], 0.f);
        h16 h, l; hsplit(v, h, l);
        Ch[(long)m * FFn + n] = h; Cl[(long)m * FFn + n] = l;
    }
};
struct EpiMoE2 {
    const float* b2l; const int* offs; const int* perm; const float* gates; float* eout;
    const float* bias; int base;
    __device__ void setz(int e) { bias = b2l + (long)e * Dm; base = offs[e]; }
    __device__ void op(int m, int n, float v) {
        int entry = perm[base + m];
        eout[(long)entry * Dm + n] = gates[entry] * (v + bias[n]);
    }
};

// ------- fp16x3 GEMM: 128x64 tile, BK=32, 2-stage cp.async, ldmatrix --------
constexpr int STGH = 15360;               // halves per stage
constexpr int GSMEM = 2 * STGH * 2;       // bytes = 61440

template <class AP, class EP>
__global__ void __launch_bounds__(256, 2) gemm_k(AP ap, const h16* __restrict__ BTh,
                                                 const h16* __restrict__ BTl, long bz,
                                                 EP ep, int K)
{
    extern __shared__ h16 smh[];
    int z = blockIdx.z;
    int M = ap.setz(z);
    int m0 = blockIdx.x * 128;
    if (m0 >= M) return;
    ep.setz(z);
    int n0 = blockIdx.y * 64;

    int tid = threadIdx.x, lane = tid & 31, wid = tid >> 5;
    int wm = wid & 3, wn = wid >> 2;
    int g = lane >> 2, tg = lane & 3;
    int lo16 = lane & 15, hi16 = lane >> 4;
    uint32_t smb = smem_u32(smh);

    int r4 = tid >> 2;
    int c4 = (tid & 3) * 8;
    bool v0 = (m0 + r4) < M, v1 = (m0 + 64 + r4) < M;
    uint32_t szA0 = v0 ? 16u : 0u, szA1 = v1 ? 16u : 0u;
    const h16* sAh0 = ap.rowh(v0 ? m0 + r4 : m0) + c4;
    const h16* sAl0 = ap.rowl(v0 ? m0 + r4 : m0) + c4;
    const h16* sAh1 = ap.rowh(v1 ? m0 + 64 + r4 : m0) + c4;
    const h16* sAl1 = ap.rowl(v1 ? m0 + 64 + r4 : m0) + c4;
    const h16* sBh = BTh + (long)z * bz + (long)(n0 + r4) * K + c4;
    const h16* sBl = BTl + (long)z * bz + (long)(n0 + r4) * K + c4;

    uint32_t dA0 = (uint32_t)r4 * 80 + (uint32_t)(tid & 3) * 16;
    uint32_t dA1 = dA0 + 5120;

    auto issue = [&](int s) {
        uint32_t b = smb + (uint32_t)(s & 1) * (STGH * 2);
        int ko = s * 32;
        CPA(b + dA0, sAh0 + ko, szA0);
        CPA(b + dA1, sAh1 + ko, szA1);
        CPA(b + 10240 + dA0, sAl0 + ko, szA0);
        CPA(b + 10240 + dA1, sAl1 + ko, szA1);
        CPA(b + 20480 + dA0, sBh + ko, 16u);
        CPA(b + 25600 + dA0, sBl + ko, 16u);
        CP_COMMIT();
    };

    float acc[2][4][4];
    #pragma unroll
    for (int mt = 0; mt < 2; mt++)
        #pragma unroll
        for (int nt = 0; nt < 4; nt++)
            #pragma unroll
            for (int j = 0; j < 4; j++) acc[mt][nt][j] = 0.f;

    int ns = K / 32;
    issue(0);
    for (int s = 0; s < ns; s++) {
        bool more = (s + 1 < ns);
        if (more) issue(s + 1);
        if (more) CP_WAIT1(); else CP_WAIT0();
        __syncthreads();

        uint32_t Wb = smb + (uint32_t)(s & 1) * (STGH * 2);
        #pragma unroll
        for (int kc = 0; kc < 2; kc++) {
            int ko = kc * 8;                    // word offset within row
            uint32_t ah[2][4], al[2][4], bh[4][2], bl[4][2];
            #pragma unroll
            for (int mt = 0; mt < 2; mt++) {
                uint32_t ab = Wb + (uint32_t)(((wm * 32 + mt * 16 + lo16) * 20) + hi16 * 4 + ko) * 4;
                ldsm_x4(ah[mt], ab);
                ldsm_x4(al[mt], ab + 10240);
            }
            #pragma unroll
            for (int pr = 0; pr < 2; pr++) {
                uint32_t bb = Wb + 20480 + (uint32_t)(((wn * 32 + pr * 16 + lo16) * 20) + hi16 * 4 + ko) * 4;
                uint32_t t[4];
                ldsm_x4(t, bb);
                bh[pr * 2][0] = t[0]; bh[pr * 2 + 1][0] = t[1];
                bh[pr * 2][1] = t[2]; bh[pr * 2 + 1][1] = t[3];
                ldsm_x4(t, bb + 5120);
                bl[pr * 2][0] = t[0]; bl[pr * 2 + 1][0] = t[1];
                bl[pr * 2][1] = t[2]; bl[pr * 2 + 1][1] = t[3];
            }
            #pragma unroll
            for (int mt = 0; mt < 2; mt++)
                #pragma unroll
                for (int nt = 0; nt < 4; nt++) {
                    mma_f16(acc[mt][nt], al[mt], bh[nt]);
                    mma_f16(acc[mt][nt], ah[mt], bl[nt]);
                    mma_f16(acc[mt][nt], ah[mt], bh[nt]);
                }
        }
        __syncthreads();
    }

    int r0 = wm * 32 + g;
    int c0 = wn * 32 + tg * 2;
    #pragma unroll
    for (int mt = 0; mt < 2; mt++) {
        int gm0 = m0 + r0 + mt * 16;
        int gm1 = gm0 + 8;
        #pragma unroll
        for (int nt = 0; nt < 4; nt++) {
            int gn = n0 + c0 + nt * 8;
            if (gm0 < M) { ep.op(gm0, gn, acc[mt][nt][0]); ep.op(gm0, gn + 1, acc[mt][nt][1]); }
            if (gm1 < M) { ep.op(gm1, gn, acc[mt][nt][2]); ep.op(gm1, gn + 1, acc[mt][nt][3]); }
        }
    }
}

// -------- weight transpose+split --------
__global__ void __launch_bounds__(256) wsplit_t_k(const float* __restrict__ W,
                                                  h16* __restrict__ Oh, h16* __restrict__ Ol,
                                                  int K, int N)
{
    __shared__ float t[32][33];
    size_t zo = (size_t)blockIdx.z * K * N;
    int k0 = blockIdx.x * 32, n0 = blockIdx.y * 32;
    int tx = threadIdx.x & 31, ty = threadIdx.x >> 5;
    #pragma unroll
    for (int j = 0; j < 32; j += 8)
        t[ty + j][tx] = W[zo + (size_t)(k0 + ty + j) * N + n0 + tx];
    __syncthreads();
    #pragma unroll
    for (int j = 0; j < 32; j += 8) {
        float v = t[tx][ty + j];
        h16 h, l; hsplit(v, h, l);
        size_t o = zo + (size_t)(n0 + ty + j) * K + k0 + tx;
        Oh[o] = h; Ol[o] = l;
    }
}

__global__ void __launch_bounds__(256) split_k(const float* __restrict__ x,
                                               h16* __restrict__ oh, h16* __restrict__ ol, int n)
{
    int i = blockIdx.x * 256 + threadIdx.x;
    if (i < n) { h16 h, l; hsplit(x[i], h, l); oh[i] = h; ol[i] = l; }
}

__global__ void embed_k(const int* __restrict__ ids, const float* __restrict__ emb,
                        const float* __restrict__ pos, float* __restrict__ y,
                        h16* __restrict__ yh, h16* __restrict__ yl)
{
    int t = blockIdx.x;
    int id = ids[t];
    int tq = t & (Tn - 1);
    const float* er = emb + (long)id * Dm;
    const float* pr = pos + (long)tq * Dm;
    long o = (long)t * Dm;
    for (int d = threadIdx.x; d < Dm; d += blockDim.x) {
        float v = er[d] + pr[d];
        y[o + d] = v;
        h16 h, l; hsplit(v, h, l);
        yh[o + d] = h; yl[o + d] = l;
    }
}

// ---------------- tensor-core flash attention (ldmatrix fragments) -----------
constexpr int FSMEM = 57344;

__global__ void __launch_bounds__(256) flash_k(const h16* __restrict__ Qh, const h16* __restrict__ Ql,
                                               const h16* __restrict__ Kh, const h16* __restrict__ Kl,
                                               const h16* __restrict__ Vh, const h16* __restrict__ Vl,
                                               h16* __restrict__ Oh, h16* __restrict__ Ol,
                                               const int* __restrict__ am, int Tk, int causal)
{
    extern __shared__ h16 fs[];
    h16 *Qhs = fs, *Qls = fs + 4608, *Khs = fs + 9216, *Kls = fs + 11520;
    h16 *Vths = fs + 13824, *Vtls = fs + 16384, *Phs = fs + 18944, *Pls = fs + 21504;
    float* Ps = (float*)(fs + 24064);
    float* rowm = Ps + 64 * 33;
    float* rowl = rowm + 64;
    float* alph = rowl + 64;
    uint32_t fsb = smem_u32(fs);
    // byte offsets: Ql 9216, Kh 18432, Kl 23040, Vth 27648, Vtl 32768, Ph 37888, Pl 43008

    int q0 = blockIdx.x * 64;
    int bh_ = blockIdx.y;
    int b = bh_ >> 3, h = bh_ & 7;
    const h16* Qbh = Qh + ((long)b * Tn + q0) * Dm + h * DHn;
    const h16* Qbl = Ql + ((long)b * Tn + q0) * Dm + h * DHn;
    const h16* Kbh = Kh + (long)b * Tk * Dm + h * DHn;
    const h16* Kbl = Kl + (long)b * Tk * Dm + h * DHn;
    const h16* Vbh = Vh + (long)b * Tk * Dm + h * DHn;
    const h16* Vbl = Vl + (long)b * Tk * Dm + h * DHn;

    int tid = threadIdx.x, lane = tid & 31, wid = tid >> 5;
    int wm = wid & 3, wn = wid >> 2;
    int g = lane >> 2, tg = lane & 3;
    int lo16 = lane & 15, hi16 = lane >> 4;

    #pragma unroll
    for (int it = 0; it < 2; it++) {
        int idx = tid + it * 256;
        int r = idx >> 3, c8 = (idx & 7) * 8;
        *(uint4*)(Qhs + r * 72 + c8) = *(const uint4*)(Qbh + (long)r * Dm + c8);
        *(uint4*)(Qls + r * 72 + c8) = *(const uint4*)(Qbl + (long)r * Dm + c8);
    }
    if (tid < 64) { rowm[tid] = -1e30f; rowl[tid] = 0.f; }

    float o[4][4];
    #pragma unroll
    for (int i = 0; i < 4; i++)
        #pragma unroll
        for (int j = 0; j < 4; j++) o[i][j] = 0.f;

    int kvmax = causal ? (q0 + 64) : Tk;
    for (int kv0 = 0; kv0 < kvmax; kv0 += 32) {
        __syncthreads();
        {
            int r = tid >> 3, c8 = (tid & 7) * 8;
            *(uint4*)(Khs + r * 72 + c8) = *(const uint4*)(Kbh + (long)(kv0 + r) * Dm + c8);
            *(uint4*)(Kls + r * 72 + c8) = *(const uint4*)(Kbl + (long)(kv0 + r) * Dm + c8);
            h16 vh8[8], vl8[8];
            *(uint4*)vh8 = *(const uint4*)(Vbh + (long)(kv0 + r) * Dm + c8);
            *(uint4*)vl8 = *(const uint4*)(Vbl + (long)(kv0 + r) * Dm + c8);
            #pragma unroll
            for (int j = 0; j < 8; j++) {
                Vths[(c8 + j) * 40 + r] = vh8[j];
                Vtls[(c8 + j) * 40 + r] = vl8[j];
            }
        }
        __syncthreads();

        float s[2][4] = {{0.f, 0.f, 0.f, 0.f}, {0.f, 0.f, 0.f, 0.f}};
        #pragma unroll
        for (int kc = 0; kc < 4; kc++) {
            int ko = kc * 8;
            uint32_t ah[4], al[4];
            uint32_t ab = fsb + (uint32_t)(((wm * 16 + lo16) * 36) + hi16 * 4 + ko) * 4;
            ldsm_x4(ah, ab);
            ldsm_x4(al, ab + 9216);
            uint32_t bh2[2][2], bl2[2][2];
            {
                uint32_t bb = fsb + 18432 + (uint32_t)(((wn * 16 + lo16) * 36) + hi16 * 4 + ko) * 4;
                uint32_t t[4];
                ldsm_x4(t, bb);
                bh2[0][0] = t[0]; bh2[1][0] = t[1]; bh2[0][1] = t[2]; bh2[1][1] = t[3];
                ldsm_x4(t, bb + 4608);
                bl2[0][0] = t[0]; bl2[1][0] = t[1]; bl2[0][1] = t[2]; bl2[1][1] = t[3];
            }
            #pragma unroll
            for (int nt = 0; nt < 2; nt++) {
                mma_f16(s[nt], al, bh2[nt]);
                mma_f16(s[nt], ah, bl2[nt]);
                mma_f16(s[nt], ah, bh2[nt]);
            }
        }
        #pragma unroll
        for (int nt = 0; nt < 2; nt++) {
            #pragma unroll
            for (int j = 0; j < 4; j++) {
                int row = wm * 16 + g + (j >> 1) * 8;
                int col = wn * 16 + nt * 8 + tg * 2 + (j & 1);
                float sv = s[nt][j] * 0.125f;
                if (causal) {
                    int kg = kv0 + col, qg = q0 + row;
                    if (kg > qg || am[b * Tn + kg] == 0) sv = -1e9f;
                }
                Ps[row * 33 + col] = sv;
            }
        }
        __syncthreads();
        {
            int row = tid >> 2, sub = tid & 3;
            float mo = rowm[row], mx = mo;
            #pragma unroll
            for (int j = 0; j < 8; j++) mx = fmaxf(mx, Ps[row * 33 + sub * 8 + j]);
            mx = fmaxf(mx, __shfl_xor_sync(0xffffffffu, mx, 1));
            mx = fmaxf(mx, __shfl_xor_sync(0xffffffffu, mx, 2));
            float sum = 0.f;
            #pragma unroll
            for (int j = 0; j < 8; j++) {
                float p = __expf(Ps[row * 33 + sub * 8 + j] - mx);
                h16 ph, pl; hsplit(p, ph, pl);
                Phs[row * 40 + sub * 8 + j] = ph;
                Pls[row * 40 + sub * 8 + j] = pl;
                sum += p;
            }
            sum += __shfl_xor_sync(0xffffffffu, sum, 1);
            sum += __shfl_xor_sync(0xffffffffu, sum, 2);
            if (sub == 0) {
                float al2 = __expf(mo - mx);
                rowm[row] = mx;
                rowl[row] = rowl[row] * al2 + sum;
                alph[row] = al2;
            }
        }
        __syncthreads();
        {
            float a0 = alph[wm * 16 + g], a1 = alph[wm * 16 + g + 8];
            #pragma unroll
            for (int nt = 0; nt < 4; nt++) {
                o[nt][0] *= a0; o[nt][1] *= a0;
                o[nt][2] *= a1; o[nt][3] *= a1;
            }
        }
        #pragma unroll
        for (int kc = 0; kc < 2; kc++) {
            int ko = kc * 8;
            uint32_t ah[4], al[4];
            uint32_t ab = fsb + 37888 + (uint32_t)(((wm * 16 + lo16) * 20) + hi16 * 4 + ko) * 4;
            ldsm_x4(ah, ab);
            ldsm_x4(al, ab + 5120);
            uint32_t bh4[4][2], bl4[4][2];
            #pragma unroll
            for (int pr = 0; pr < 2; pr++) {
                uint32_t bb = fsb + 27648 + (uint32_t)(((wn * 32 + pr * 16 + lo16) * 20) + hi16 * 4 + ko) * 4;
                uint32_t t[4];
                ldsm_x4(t, bb);
                bh4[pr * 2][0] = t[0]; bh4[pr * 2 + 1][0] = t[1];
                bh4[pr * 2][1] = t[2]; bh4[pr * 2 + 1][1] = t[3];
                ldsm_x4(t, bb + 5120);
                bl4[pr * 2][0] = t[0]; bl4[pr * 2 + 1][0] = t[1];
                bl4[pr * 2][1] = t[2]; bl4[pr * 2 + 1][1] = t[3];
            }
            #pragma unroll
            for (int nt = 0; nt < 4; nt++) {
                mma_f16(o[nt], al, bh4[nt]);
                mma_f16(o[nt], ah, bl4[nt]);
                mma_f16(o[nt], ah, bh4[nt]);
            }
        }
    }
    __syncthreads();
    {
        float inv0 = 1.f / rowl[wm * 16 + g];
        float inv1 = 1.f / rowl[wm * 16 + g + 8];
        int row0 = q0 + wm * 16 + g;
        #pragma unroll
        for (int nt = 0; nt < 4; nt++) {
            int col = h * DHn + wn * 32 + nt * 8 + tg * 2;
            long o0 = ((long)b * Tn + row0) * Dm + col;
            long o1 = ((long)b * Tn + row0 + 8) * Dm + col;
            h16 hh, ll;
            hsplit(o[nt][0] * inv0, hh, ll); Oh[o0] = hh;     Ol[o0] = ll;
            hsplit(o[nt][1] * inv0, hh, ll); Oh[o0 + 1] = hh; Ol[o0 + 1] = ll;
            hsplit(o[nt][2] * inv1, hh, ll); Oh[o1] = hh;     Ol[o1] = ll;
            hsplit(o[nt][3] * inv1, hh, ll); Oh[o1 + 1] = hh; Ol[o1 + 1] = ll;
        }
    }
}

// ---------------- add + layernorm ----------------
__global__ void __launch_bounds__(256) add_ln_k(const float* __restrict__ base,
                                                const float* __restrict__ delta, int nslots,
                                                const float* __restrict__ g,
                                                const float* __restrict__ bet,
                                                float* __restrict__ out,
                                                h16* __restrict__ oh, h16* __restrict__ ol)
{
    int t = blockIdx.x, tid = threadIdx.x;
    __shared__ float red[256];
    float x0 = base[(long)t * Dm + tid];
    float x1 = base[(long)t * Dm + 256 + tid];
    if (nslots == 1) {
        x0 += delta[(long)t * Dm + tid];
        x1 += delta[(long)t * Dm + 256 + tid];
    } else {
        x0 += delta[(long)(t * 2) * Dm + tid] + delta[(long)(t * 2 + 1) * Dm + tid];
        x1 += delta[(long)(t * 2) * Dm + 256 + tid] + delta[(long)(t * 2 + 1) * Dm + 256 + tid];
    }
    red[tid] = x0 + x1;
    __syncthreads();
    #pragma unroll
    for (int s = 128; s > 0; s >>= 1) {
        if (tid < s) red[tid] += red[tid + s];
        __syncthreads();
    }
    float mu = red[0] * (1.f / Dm);
    __syncthreads();
    float d0 = x0 - mu, d1 = x1 - mu;
    red[tid] = d0 * d0 + d1 * d1;
    __syncthreads();
    #pragma unroll
    for (int s = 128; s > 0; s >>= 1) {
        if (tid < s) red[tid] += red[tid + s];
        __syncthreads();
    }
    float rs = rsqrtf(red[0] * (1.f / Dm) + 1e-5f);
    float v0 = d0 * rs * g[tid] + bet[tid];
    float v1 = d1 * rs * g[tid + 256] + bet[tid + 256];
    out[(long)t * Dm + tid] = v0;
    out[(long)t * Dm + 256 + tid] = v1;
    h16 h, l;
    hsplit(v0, h, l); oh[(long)t * Dm + tid] = h; ol[(long)t * Dm + tid] = l;
    hsplit(v1, h, l); oh[(long)t * Dm + 256 + tid] = h; ol[(long)t * Dm + 256 + tid] = l;
}

// ---------------- router / aux loss / grouping ----------------
__global__ void __launch_bounds__(256) router_k(const float* __restrict__ y,
                                                const float* __restrict__ rw,
                                                const float* __restrict__ rb,
                                                float* __restrict__ probs,
                                                int* __restrict__ topi,
                                                float* __restrict__ gates)
{
    int warp = (blockIdx.x * blockDim.x + threadIdx.x) >> 5;
    int lane = threadIdx.x & 31;
    if (warp >= NT) return;
    const float* x = y + (long)warp * Dm;
    float acc[En];
    #pragma unroll
    for (int e = 0; e < En; e++) acc[e] = 0.f;
    for (int d = lane; d < Dm; d += 32) {
        float xv = x[d];
        const float* w = rw + (long)d * En;
        #pragma unroll
        for (int e = 0; e < En; e++) acc[e] += xv * w[e];
    }
    #pragma unroll
    for (int e = 0; e < En; e++) {
        #pragma unroll
        for (int off = 16; off > 0; off >>= 1)
            acc[e] += __shfl_xor_sync(0xffffffffu, acc[e], off);
    }
    float lg[En], p[En];
    float m = -1e30f;
    #pragma unroll
    for (int e = 0; e < En; e++) { lg[e] = acc[e] + rb[e]; m = fmaxf(m, lg[e]); }
    float sum = 0.f;
    #pragma unroll
    for (int e = 0; e < En; e++) { p[e] = __expf(lg[e] - m); sum += p[e]; }
    float inv = 1.f / sum;
    #pragma unroll
    for (int e = 0; e < En; e++) p[e] *= inv;
    int e0 = 0; float v0 = p[0];
    #pragma unroll
    for (int e = 1; e < En; e++) if (p[e] > v0) { v0 = p[e]; e0 = e; }
    int e1 = -1; float v1 = -1.f;
    #pragma unroll
    for (int e = 0; e < En; e++) if (e != e0 && p[e] > v1) { v1 = p[e]; e1 = e; }
    if (lane == 0) {
        #pragma unroll
        for (int e = 0; e < En; e++) probs[(long)warp * En + e] = p[e];
        float den = 1.f / (v0 + v1);
        topi[warp * 2 + 0] = e0;
        topi[warp * 2 + 1] = e1;
        gates[warp * 2 + 0] = v0 * den;
        gates[warp * 2 + 1] = v1 * den;
    }
}

__global__ void __launch_bounds__(1024) lb_k(const float* __restrict__ probs,
                                             const int* __restrict__ topi,
                                             float* __restrict__ lbout, int first)
{
    __shared__ float sm[1024];
    int tid = threadIdx.x;
    float ps[En], cs[En];
    #pragma unroll
    for (int e = 0; e < En; e++) { ps[e] = 0.f; cs[e] = 0.f; }
    for (int t = tid; t < NT; t += 1024) {
        #pragma unroll
        for (int e = 0; e < En; e++) ps[e] += probs[(long)t * En + e];
        int a = topi[2 * t], b = topi[2 * t + 1];
        #pragma unroll
        for (int e = 0; e < En; e++) cs[e] += (float)((e == a) + (e == b));
    }
    float lb = 0.f;
    for (int e = 0; e < En; e++) {
        sm[tid] = ps[e]; __syncthreads();
        for (int s = 512; s > 0; s >>= 1) { if (tid < s) sm[tid] += sm[tid + s]; __syncthreads(); }
        float P = sm[0]; __syncthreads();
        sm[tid] = cs[e]; __syncthreads();
        for (int s = 512; s > 0; s >>= 1) { if (tid < s) sm[tid] += sm[tid + s]; __syncthreads(); }
        float C = sm[0]; __syncthreads();
        lb += (C * (1.f / NT)) * (P * (1.f / NT));
    }
    if (tid == 0) {
        lb *= (float)En;
        if (first) *lbout = lb; else *lbout += lb;
    }
}

__global__ void __launch_bounds__(256) group_k(const int* __restrict__ topi,
                                               int* __restrict__ perm,
                                               int* __restrict__ offsets)
{
    __shared__ int cnts[En];
    __shared__ int offs_s[En + 1];
    int w = threadIdx.x >> 5, lane = threadIdx.x & 31;
    int c = 0;
    for (int i = lane; i < NEn; i += 32) c += (topi[i] == w);
    #pragma unroll
    for (int off = 16; off > 0; off >>= 1) c += __shfl_xor_sync(0xffffffffu, c, off);
    if (lane == 0) cnts[w] = c;
    __syncthreads();
    if (threadIdx.x == 0) {
        offs_s[0] = 0;
        for (int e = 0; e < En; e++) offs_s[e + 1] = offs_s[e] + cnts[e];
        for (int e = 0; e <= En; e++) offsets[e] = offs_s[e];
    }
    __syncthreads();
    int pos = offs_s[w];
    for (int i0 = 0; i0 < NEn; i0 += 32) {
        int i = i0 + lane;
        int e = topi[i];
        unsigned mk = __ballot_sync(0xffffffffu, e == w);
        if (e == w) {
            int r = __popc(mk & ((1u << lane) - 1u));
            perm[pos + r] = i;
        }
        pos += __popc(mk);
    }
}

// ---------------- host ----------------
extern "C" void kernel_launch(void* const* d_in, const int* in_sizes, int n_in,
                              void* d_out, int out_size)
{
    (void)in_sizes; (void)n_in;
    const int*   ids  = (const int*)d_in[0];
    const float* enc  = (const float*)d_in[1];
    const int*   am   = (const int*)d_in[2];
    const float* emb  = (const float*)d_in[3];
    const float* pos  = (const float*)d_in[4];
    const float* sa_w = (const float*)d_in[5];
    const float* sa_b = (const float*)d_in[6];
    const float* ca_w = (const float*)d_in[7];
    const float* ca_b = (const float*)d_in[8];
    const float* ln_g = (const float*)d_in[9];
    const float* ln_b = (const float*)d_in[10];
    const float* rw   = (const float*)d_in[11];
    const float* rb   = (const float*)d_in[12];
    const float* w1   = (const float*)d_in[13];
    const float* b1   = (const float*)d_in[14];
    const float* w2   = (const float*)d_in[15];
    const float* b2   = (const float*)d_in[16];
    float* out = (float*)d_out;

    float *y, *proj, *probs, *gates, *eout;
    int *topi, *perm, *offs;
    h16 *qkvh, *qkvl, *yh, *yl, *ench, *encl, *ath, *atl, *Hh, *Hl;
    h16 *sawh, *sawl, *cawh, *cawl, *w1h, *w1l, *w2h, *w2l;
    cudaGetSymbolAddress((void**)&y, g_y);
    cudaGetSymbolAddress((void**)&proj, g_proj);
    cudaGetSymbolAddress((void**)&probs, g_probs);
    cudaGetSymbolAddress((void**)&gates, g_gates);
    cudaGetSymbolAddress((void**)&eout, g_eout);
    cudaGetSymbolAddress((void**)&topi, g_topi);
    cudaGetSymbolAddress((void**)&perm, g_perm);
    cudaGetSymbolAddress((void**)&offs, g_offs);
    cudaGetSymbolAddress((void**)&qkvh, g_qkvh);
    cudaGetSymbolAddress((void**)&qkvl, g_qkvl);
    cudaGetSymbolAddress((void**)&yh, g_yh);
    cudaGetSymbolAddress((void**)&yl, g_yl);
    cudaGetSymbolAddress((void**)&ench, g_ench);
    cudaGetSymbolAddress((void**)&encl, g_encl);
    cudaGetSymbolAddress((void**)&ath, g_ath);
    cudaGetSymbolAddress((void**)&atl, g_atl);
    cudaGetSymbolAddress((void**)&Hh, g_Hh);
    cudaGetSymbolAddress((void**)&Hl, g_Hl);
    cudaGetSymbolAddress((void**)&sawh, g_sawh);
    cudaGetSymbolAddress((void**)&sawl, g_sawl);
    cudaGetSymbolAddress((void**)&cawh, g_cawh);
    cudaGetSymbolAddress((void**)&cawl, g_cawl);
    cudaGetSymbolAddress((void**)&w1h, g_w1h);
    cudaGetSymbolAddress((void**)&w1l, g_w1l);
    cudaGetSymbolAddress((void**)&w2h, g_w2h);
    cudaGetSymbolAddress((void**)&w2l, g_w2l);

    cudaFuncSetAttribute(gemm_k<RowAh, EpiBiasH>,    cudaFuncAttributeMaxDynamicSharedMemorySize, GSMEM);
    cudaFuncSetAttribute(gemm_k<RowAh, EpiBias>,     cudaFuncAttributeMaxDynamicSharedMemorySize, GSMEM);
    cudaFuncSetAttribute(gemm_k<CrossAh, EpiBiasH>,  cudaFuncAttributeMaxDynamicSharedMemorySize, GSMEM);
    cudaFuncSetAttribute(gemm_k<GatherAh, EpiMoE1>,  cudaFuncAttributeMaxDynamicSharedMemorySize, GSMEM);
    cudaFuncSetAttribute(gemm_k<HRowAh, EpiMoE2>,    cudaFuncAttributeMaxDynamicSharedMemorySize, GSMEM);
    cudaFuncSetAttribute(flash_k, cudaFuncAttributeMaxDynamicSharedMemorySize, FSMEM);

    const long DD = (long)Dm * Dm;
    const long SLOT = (long)NT * Dm;

    wsplit_t_k<<<dim3(16, 16, Ln * 4), 256>>>(sa_w, sawh, sawl, Dm, Dm);
    wsplit_t_k<<<dim3(16, 16, Ln * 4), 256>>>(ca_w, cawh, cawl, Dm, Dm);
    wsplit_t_k<<<dim3(16, 64, Ln * En), 256>>>(w1, w1h, w1l, Dm, FFn);
    wsplit_t_k<<<dim3(64, 16, Ln * En), 256>>>(w2, w2h, w2l, FFn, Dm);
    split_k<<<(NT * Dm + 255) / 256, 256>>>(enc, ench, encl, NT * Dm);

    embed_k<<<NT, 256>>>(ids, emb, pos, y, yh, yl);

    for (int l = 0; l < Ln; l++) {
        gemm_k<<<dim3(16, 8, 3), 256, GSMEM>>>(
            RowAh{yh, yl, Dm, 0, NT}, sawh + l * 4 * DD, sawl + l * 4 * DD, DD,
            EpiBiasH{sa_b + (long)l * 4 * Dm, Dm, qkvh, qkvl, SLOT, Dm}, Dm);
        flash_k<<<dim3(Tn / 64, 16), 256, FSMEM>>>(qkvh, qkvl, qkvh + SLOT, qkvl + SLOT,
                                                   qkvh + 2 * SLOT, qkvl + 2 * SLOT, ath, atl, am, Tn, 1);
        gemm_k<<<dim3(16, 8, 1), 256, GSMEM>>>(
            RowAh{ath, atl, Dm, 0, NT}, sawh + (l * 4 + 3) * DD, sawl + (l * 4 + 3) * DD, 0,
            EpiBias{sa_b + (long)(l * 4 + 3) * Dm, 0, proj, 0, Dm}, Dm);
        add_ln_k<<<NT, 256>>>(y, proj, 1, ln_g + (l * 3 + 0) * Dm, ln_b + (l * 3 + 0) * Dm, y, yh, yl);

        gemm_k<<<dim3(16, 8, 3), 256, GSMEM>>>(
            CrossAh{yh, yl, ench, encl, nullptr, nullptr},
            cawh + l * 4 * DD, cawl + l * 4 * DD, DD,
            EpiBiasH{ca_b + (long)l * 4 * Dm, Dm, qkvh, qkvl, SLOT, Dm}, Dm);
        flash_k<<<dim3(Tn / 64, 16), 256, FSMEM>>>(qkvh, qkvl, qkvh + SLOT, qkvl + SLOT,
                                                   qkvh + 2 * SLOT, qkvl + 2 * SLOT, ath, atl, nullptr, Tn, 0);
        gemm_k<<<dim3(16, 8, 1), 256, GSMEM>>>(
            RowAh{ath, atl, Dm, 0, NT}, cawh + (l * 4 + 3) * DD, cawl + (l * 4 + 3) * DD, 0,
            EpiBias{ca_b + (long)(l * 4 + 3) * Dm, 0, proj, 0, Dm}, Dm);
        add_ln_k<<<NT, 256>>>(y, proj, 1, ln_g + (l * 3 + 1) * Dm, ln_b + (l * 3 + 1) * Dm, y, yh, yl);

        router_k<<<NT / 8, 256>>>(y, rw + (long)l * Dm * En, rb + l * En, probs, topi, gates);
        lb_k<<<1, 1024>>>(probs, topi, out + (out_size - 1), l == 0 ? 1 : 0);
        group_k<<<1, 256>>>(topi, perm, offs);
        gemm_k<<<dim3(32, 32, En), 256, GSMEM>>>(
            GatherAh{yh, yl, perm, offs, 0},
            w1h + (long)l * En * FFn * Dm, w1l + (long)l * En * FFn * Dm, (long)FFn * Dm,
            EpiMoE1{b1 + (long)l * En * FFn, offs, Hh, Hl, nullptr, nullptr, nullptr}, Dm);
        gemm_k<<<dim3(32, 8, En), 256, GSMEM>>>(
            HRowAh{Hh, Hl, offs, nullptr, nullptr},
            w2h + (long)l * En * Dm * FFn, w2l + (long)l * En * Dm * FFn, (long)Dm * FFn,
            EpiMoE2{b2 + (long)l * En * Dm, offs, perm, gates, eout, nullptr, 0}, FFn);
        float* lnout = (l == Ln - 1) ? out : y;
        add_ln_k<<<NT, 256>>>(y, eout, 2, ln_g + (l * 3 + 2) * Dm, ln_b + (l * 3 + 2) * Dm, lnout, yh, yl);
    }
}

// round 15
// speedup vs baseline: 1.0749x; 1.0187x over previous
#include <cuda_runtime.h>
#include <cuda_fp16.h>
#include <math.h>
#include <stdint.h>

#define Dm   512
#define Tn   1024
#define NT   2048
#define Ln   4
#define En   8
#define FFn  2048
#define NEn  4096
#define DHn  64
#define MAXT 40

typedef __half h16;

// ---------------- scratch ----------------
__device__ __align__(128) float g_y[NT * Dm];
__device__ __align__(128) float g_proj[NT * Dm];
__device__ __align__(128) float g_probs[NT * En];
__device__ __align__(128) float g_gates[NEn];
__device__ __align__(128) float g_eout[(size_t)NEn * Dm];
__device__ int g_topi[NEn];
__device__ int g_perm[NEn];
__device__ int g_offs[En + 1];
__device__ int2 g_tiles[MAXT];
__device__ __align__(128) h16 g_qkvh[3 * NT * Dm], g_qkvl[3 * NT * Dm];
__device__ __align__(128) h16 g_yh[NT * Dm],  g_yl[NT * Dm];
__device__ __align__(128) h16 g_ench[NT * Dm], g_encl[NT * Dm];
__device__ __align__(128) h16 g_ath[NT * Dm], g_atl[NT * Dm];
__device__ __align__(128) h16 g_Hh[(size_t)NEn * FFn], g_Hl[(size_t)NEn * FFn];
__device__ __align__(128) h16 g_sawh[(size_t)Ln * 4 * Dm * Dm], g_sawl[(size_t)Ln * 4 * Dm * Dm];
__device__ __align__(128) h16 g_cawh[(size_t)Ln * 4 * Dm * Dm], g_cawl[(size_t)Ln * 4 * Dm * Dm];
__device__ __align__(128) h16 g_w1h[(size_t)Ln * En * FFn * Dm], g_w1l[(size_t)Ln * En * FFn * Dm];
__device__ __align__(128) h16 g_w2h[(size_t)Ln * En * Dm * FFn], g_w2l[(size_t)Ln * En * Dm * FFn];

__device__ __forceinline__ uint32_t smem_u32(const void* p) {
    uint32_t a;
    asm("{ .reg .u64 t; cvta.to.shared.u64 t, %1; cvt.u32.u64 %0, t; }" : "=r"(a) : "l"(p));
    return a;
}
__device__ __forceinline__ void hsplit(float v, h16& h, h16& l) {
    h = __float2half_rn(v);
    l = __float2half_rn(v - __half2float(h));
}
#define CPA(d, s, sz) asm volatile("cp.async.ca.shared.global [%0], [%1], 16, %2;" :: "r"(d), "l"(s), "r"(sz) : "memory")
#define CP_COMMIT()   asm volatile("cp.async.commit_group;" ::: "memory")
#define CP_WAIT1()    asm volatile("cp.async.wait_group 1;" ::: "memory")
#define CP_WAIT0()    asm volatile("cp.async.wait_group 0;" ::: "memory")

__device__ __forceinline__ void mma_f16(float c[4], const uint32_t a[4], const uint32_t b[2])
{
    asm volatile(
        "mma.sync.aligned.m16n8k16.row.col.f32.f16.f16.f32 "
        "{%0,%1,%2,%3},{%4,%5,%6,%7},{%8,%9},{%0,%1,%2,%3};"
        : "+f"(c[0]), "+f"(c[1]), "+f"(c[2]), "+f"(c[3])
        : "r"(a[0]), "r"(a[1]), "r"(a[2]), "r"(a[3]), "r"(b[0]), "r"(b[1]));
}
__device__ __forceinline__ void ldsm_x4(uint32_t r[4], uint32_t addr)
{
    asm volatile("ldmatrix.sync.aligned.m8n8.x4.shared.b16 {%0,%1,%2,%3}, [%4];"
        : "=r"(r[0]), "=r"(r[1]), "=r"(r[2]), "=r"(r[3]) : "r"(addr));
}

// ---------------- A providers ----------------
struct RowAh {
    const h16 *Ah, *Al; int lda; long zs; int M;
    __device__ int setz(int z) { Ah += (long)z * zs; Al += (long)z * zs; return M; }
    __device__ const h16* rowh(int m) const { return Ah + (long)m * lda; }
    __device__ const h16* rowl(int m) const { return Al + (long)m * lda; }
};
struct CrossAh {
    const h16 *Yh, *Yl, *Eh, *El;
    const h16 *Ah, *Al;
    __device__ int setz(int z) {
        Ah = (z == 0) ? Yh : Eh;
        Al = (z == 0) ? Yl : El;
        return NT;
    }
    __device__ const h16* rowh(int m) const { return Ah + (long)m * Dm; }
    __device__ const h16* rowl(int m) const { return Al + (long)m * Dm; }
};
struct GatherAh {
    const h16 *Yh, *Yl; const int* perm; const int* offs; int base;
    __device__ int setz(int e) { base = offs[e]; return offs[e + 1] - base; }
    __device__ const h16* rowh(int m) const { return Yh + (long)(perm[base + m] >> 1) * Dm; }
    __device__ const h16* rowl(int m) const { return Yl + (long)(perm[base + m] >> 1) * Dm; }
};
struct HRowAh {
    const h16 *Hh, *Hl; const int* offs; const h16 *Ah, *Al;
    __device__ int setz(int e) {
        int b0 = offs[e];
        Ah = Hh + (long)b0 * FFn; Al = Hl + (long)b0 * FFn;
        return offs[e + 1] - b0;
    }
    __device__ const h16* rowh(int m) const { return Ah + (long)m * FFn; }
    __device__ const h16* rowl(int m) const { return Al + (long)m * FFn; }
};
// ---------------- epilogues ----------------
struct EpiBias {
    const float* bias; long biasZ; float* C; long cZ; int ldc;
    __device__ void setz(int z) { bias += (long)z * biasZ; C += (long)z * cZ; }
    __device__ void op(int m, int n, float v) { C[(long)m * ldc + n] = v + bias[n]; }
};
struct EpiBiasH {
    const float* bias; long biasZ; h16* Ch; h16* Cl; long cZ; int ldc;
    __device__ void setz(int z) { bias += (long)z * biasZ; Ch += (long)z * cZ; Cl += (long)z * cZ; }
    __device__ void op(int m, int n, float v) {
        v += bias[n];
        h16 h, l; hsplit(v, h, l);
        Ch[(long)m * ldc + n] = h; Cl[(long)m * ldc + n] = l;
    }
};
struct EpiMoE1 {
    const float* b1l; const int* offs; h16* Hh; h16* Hl;
    const float* bias; h16 *Ch, *Cl;
    __device__ void setz(int e) {
        bias = b1l + (long)e * FFn;
        Ch = Hh + (long)offs[e] * FFn; Cl = Hl + (long)offs[e] * FFn;
    }
    __device__ void op(int m, int n, float v) {
        v = fmaxf(v + bias[n], 0.f);
        h16 h, l; hsplit(v, h, l);
        Ch[(long)m * FFn + n] = h; Cl[(long)m * FFn + n] = l;
    }
};
struct EpiMoE2 {
    const float* b2l; const int* offs; const int* perm; const float* gates; float* eout;
    const float* bias; int base;
    __device__ void setz(int e) { bias = b2l + (long)e * Dm; base = offs[e]; }
    __device__ void op(int m, int n, float v) {
        int entry = perm[base + m];
        eout[(long)entry * Dm + n] = gates[entry] * (v + bias[n]);
    }
};

// ------- fp16x3 GEMM: 128x64 tile, BK=32, 2-stage cp.async, ldmatrix --------
constexpr int STGH = 15360;
constexpr int GSMEM = 2 * STGH * 2;

template <class AP, class EP>
__global__ void __launch_bounds__(256, 2) gemm_k(AP ap, const h16* __restrict__ BTh,
                                                 const h16* __restrict__ BTl, long bz,
                                                 EP ep, int K, const int2* __restrict__ tt)
{
    extern __shared__ h16 smh[];
    int z, m0;
    if (tt) {
        int2 t = tt[blockIdx.x];
        if (t.x < 0) return;
        z = t.x; m0 = t.y;
    } else {
        z = blockIdx.z; m0 = blockIdx.x * 128;
    }
    int M = ap.setz(z);
    if (m0 >= M) return;
    ep.setz(z);
    int n0 = blockIdx.y * 64;

    int tid = threadIdx.x, lane = tid & 31, wid = tid >> 5;
    int wm = wid & 3, wn = wid >> 2;
    int g = lane >> 2, tg = lane & 3;
    int lo16 = lane & 15, hi16 = lane >> 4;
    uint32_t smb = smem_u32(smh);

    int r4 = tid >> 2;
    int c4 = (tid & 3) * 8;
    bool v0 = (m0 + r4) < M, v1 = (m0 + 64 + r4) < M;
    uint32_t szA0 = v0 ? 16u : 0u, szA1 = v1 ? 16u : 0u;
    const h16* sAh0 = ap.rowh(v0 ? m0 + r4 : m0) + c4;
    const h16* sAl0 = ap.rowl(v0 ? m0 + r4 : m0) + c4;
    const h16* sAh1 = ap.rowh(v1 ? m0 + 64 + r4 : m0) + c4;
    const h16* sAl1 = ap.rowl(v1 ? m0 + 64 + r4 : m0) + c4;
    const h16* sBh = BTh + (long)z * bz + (long)(n0 + r4) * K + c4;
    const h16* sBl = BTl + (long)z * bz + (long)(n0 + r4) * K + c4;

    uint32_t dA0 = (uint32_t)r4 * 80 + (uint32_t)(tid & 3) * 16;
    uint32_t dA1 = dA0 + 5120;

    auto issue = [&](int s) {
        uint32_t b = smb + (uint32_t)(s & 1) * (STGH * 2);
        int ko = s * 32;
        CPA(b + dA0, sAh0 + ko, szA0);
        CPA(b + dA1, sAh1 + ko, szA1);
        CPA(b + 10240 + dA0, sAl0 + ko, szA0);
        CPA(b + 10240 + dA1, sAl1 + ko, szA1);
        CPA(b + 20480 + dA0, sBh + ko, 16u);
        CPA(b + 25600 + dA0, sBl + ko, 16u);
        CP_COMMIT();
    };

    float acc[2][4][4];
    #pragma unroll
    for (int mt = 0; mt < 2; mt++)
        #pragma unroll
        for (int nt = 0; nt < 4; nt++)
            #pragma unroll
            for (int j = 0; j < 4; j++) acc[mt][nt][j] = 0.f;

    int ns = K / 32;
    issue(0);
    for (int s = 0; s < ns; s++) {
        bool more = (s + 1 < ns);
        if (more) issue(s + 1);
        if (more) CP_WAIT1(); else CP_WAIT0();
        __syncthreads();

        uint32_t Wb = smb + (uint32_t)(s & 1) * (STGH * 2);
        #pragma unroll
        for (int kc = 0; kc < 2; kc++) {
            int ko = kc * 8;
            uint32_t ah[2][4], al[2][4], bh[4][2], bl[4][2];
            #pragma unroll
            for (int mt = 0; mt < 2; mt++) {
                uint32_t ab = Wb + (uint32_t)(((wm * 32 + mt * 16 + lo16) * 20) + hi16 * 4 + ko) * 4;
                ldsm_x4(ah[mt], ab);
                ldsm_x4(al[mt], ab + 10240);
            }
            #pragma unroll
            for (int pr = 0; pr < 2; pr++) {
                uint32_t bb = Wb + 20480 + (uint32_t)(((wn * 32 + pr * 16 + lo16) * 20) + hi16 * 4 + ko) * 4;
                uint32_t t[4];
                ldsm_x4(t, bb);
                bh[pr * 2][0] = t[0]; bh[pr * 2 + 1][0] = t[1];
                bh[pr * 2][1] = t[2]; bh[pr * 2 + 1][1] = t[3];
                ldsm_x4(t, bb + 5120);
                bl[pr * 2][0] = t[0]; bl[pr * 2 + 1][0] = t[1];
                bl[pr * 2][1] = t[2]; bl[pr * 2 + 1][1] = t[3];
            }
            #pragma unroll
            for (int mt = 0; mt < 2; mt++)
                #pragma unroll
                for (int nt = 0; nt < 4; nt++) {
                    mma_f16(acc[mt][nt], al[mt], bh[nt]);
                    mma_f16(acc[mt][nt], ah[mt], bl[nt]);
                    mma_f16(acc[mt][nt], ah[mt], bh[nt]);
                }
        }
        __syncthreads();
    }

    int r0 = wm * 32 + g;
    int c0 = wn * 32 + tg * 2;
    #pragma unroll
    for (int mt = 0; mt < 2; mt++) {
        int gm0 = m0 + r0 + mt * 16;
        int gm1 = gm0 + 8;
        #pragma unroll
        for (int nt = 0; nt < 4; nt++) {
            int gn = n0 + c0 + nt * 8;
            if (gm0 < M) { ep.op(gm0, gn, acc[mt][nt][0]); ep.op(gm0, gn + 1, acc[mt][nt][1]); }
            if (gm1 < M) { ep.op(gm1, gn, acc[mt][nt][2]); ep.op(gm1, gn + 1, acc[mt][nt][3]); }
        }
    }
}

// -------- weight transpose+split: 64(k) x 32(n) tiles, half2 stores ---------
__global__ void __launch_bounds__(256) wsplit_t_k(const float* __restrict__ W,
                                                  h16* __restrict__ Oh, h16* __restrict__ Ol,
                                                  int K, int N)
{
    __shared__ float t[64][33];
    size_t zo = (size_t)blockIdx.z * K * N;
    int k0 = blockIdx.x * 64, n0 = blockIdx.y * 32;
    int tx = threadIdx.x & 31, ty = threadIdx.x >> 5;
    #pragma unroll
    for (int j = 0; j < 64; j += 8)
        t[ty + j][tx] = W[zo + (size_t)(k0 + ty + j) * N + n0 + tx];
    __syncthreads();
    int n = threadIdx.x >> 3;          // 0..31
    int kp0 = threadIdx.x & 7;         // 0..7
    #pragma unroll
    for (int j = 0; j < 4; j++) {
        int kp = kp0 + j * 8;          // 0..31 (pair index)
        float va = t[2 * kp][n], vb = t[2 * kp + 1][n];
        h16 ha, la, hb, lb;
        hsplit(va, ha, la); hsplit(vb, hb, lb);
        size_t o = zo + (size_t)(n0 + n) * K + k0 + 2 * kp;
        __half2 ph, pl;
        ph.x = ha; ph.y = hb; pl.x = la; pl.y = lb;
        *(__half2*)(Oh + o) = ph;
        *(__half2*)(Ol + o) = pl;
    }
}

__global__ void __launch_bounds__(256) split_k(const float* __restrict__ x,
                                               h16* __restrict__ oh, h16* __restrict__ ol, int n)
{
    int i = blockIdx.x * 256 + threadIdx.x;
    if (i < n) { h16 h, l; hsplit(x[i], h, l); oh[i] = h; ol[i] = l; }
}

__global__ void embed_k(const int* __restrict__ ids, const float* __restrict__ emb,
                        const float* __restrict__ pos, float* __restrict__ y,
                        h16* __restrict__ yh, h16* __restrict__ yl)
{
    int t = blockIdx.x;
    int id = ids[t];
    int tq = t & (Tn - 1);
    const float* er = emb + (long)id * Dm;
    const float* pr = pos + (long)tq * Dm;
    long o = (long)t * Dm;
    for (int d = threadIdx.x; d < Dm; d += blockDim.x) {
        float v = er[d] + pr[d];
        y[o + d] = v;
        h16 h, l; hsplit(v, h, l);
        yh[o + d] = h; yl[o + d] = l;
    }
}

// ---------------- tensor-core flash attention (R14 proven) -------------------
constexpr int FSMEM = 57344;

__global__ void __launch_bounds__(256) flash_k(const h16* __restrict__ Qh, const h16* __restrict__ Ql,
                                               const h16* __restrict__ Kh, const h16* __restrict__ Kl,
                                               const h16* __restrict__ Vh, const h16* __restrict__ Vl,
                                               h16* __restrict__ Oh, h16* __restrict__ Ol,
                                               const int* __restrict__ am, int Tk, int causal)
{
    extern __shared__ h16 fs[];
    h16 *Qhs = fs, *Qls = fs + 4608, *Khs = fs + 9216, *Kls = fs + 11520;
    h16 *Vths = fs + 13824, *Vtls = fs + 16384, *Phs = fs + 18944, *Pls = fs + 21504;
    float* Ps = (float*)(fs + 24064);
    float* rowm = Ps + 64 * 33;
    float* rowl = rowm + 64;
    float* alph = rowl + 64;
    uint32_t fsb = smem_u32(fs);

    int q0 = blockIdx.x * 64;
    int bh_ = blockIdx.y;
    int b = bh_ >> 3, h = bh_ & 7;
    const h16* Qbh = Qh + ((long)b * Tn + q0) * Dm + h * DHn;
    const h16* Qbl = Ql + ((long)b * Tn + q0) * Dm + h * DHn;
    const h16* Kbh = Kh + (long)b * Tk * Dm + h * DHn;
    const h16* Kbl = Kl + (long)b * Tk * Dm + h * DHn;
    const h16* Vbh = Vh + (long)b * Tk * Dm + h * DHn;
    const h16* Vbl = Vl + (long)b * Tk * Dm + h * DHn;

    int tid = threadIdx.x, lane = tid & 31, wid = tid >> 5;
    int wm = wid & 3, wn = wid >> 2;
    int g = lane >> 2, tg = lane & 3;
    int lo16 = lane & 15, hi16 = lane >> 4;

    #pragma unroll
    for (int it = 0; it < 2; it++) {
        int idx = tid + it * 256;
        int r = idx >> 3, c8 = (idx & 7) * 8;
        *(uint4*)(Qhs + r * 72 + c8) = *(const uint4*)(Qbh + (long)r * Dm + c8);
        *(uint4*)(Qls + r * 72 + c8) = *(const uint4*)(Qbl + (long)r * Dm + c8);
    }
    if (tid < 64) { rowm[tid] = -1e30f; rowl[tid] = 0.f; }

    float o[4][4];
    #pragma unroll
    for (int i = 0; i < 4; i++)
        #pragma unroll
        for (int j = 0; j < 4; j++) o[i][j] = 0.f;

    int kvmax = causal ? (q0 + 64) : Tk;
    for (int kv0 = 0; kv0 < kvmax; kv0 += 32) {
        __syncthreads();
        {
            int r = tid >> 3, c8 = (tid & 7) * 8;
            *(uint4*)(Khs + r * 72 + c8) = *(const uint4*)(Kbh + (long)(kv0 + r) * Dm + c8);
            *(uint4*)(Kls + r * 72 + c8) = *(const uint4*)(Kbl + (long)(kv0 + r) * Dm + c8);
            h16 vh8[8], vl8[8];
            *(uint4*)vh8 = *(const uint4*)(Vbh + (long)(kv0 + r) * Dm + c8);
            *(uint4*)vl8 = *(const uint4*)(Vbl + (long)(kv0 + r) * Dm + c8);
            #pragma unroll
            for (int j = 0; j < 8; j++) {
                Vths[(c8 + j) * 40 + r] = vh8[j];
                Vtls[(c8 + j) * 40 + r] = vl8[j];
            }
        }
        __syncthreads();

        float s[2][4] = {{0.f, 0.f, 0.f, 0.f}, {0.f, 0.f, 0.f, 0.f}};
        #pragma unroll
        for (int kc = 0; kc < 4; kc++) {
            int ko = kc * 8;
            uint32_t ah[4], al[4];
            uint32_t ab = fsb + (uint32_t)(((wm * 16 + lo16) * 36) + hi16 * 4 + ko) * 4;
            ldsm_x4(ah, ab);
            ldsm_x4(al, ab + 9216);
            uint32_t bh2[2][2], bl2[2][2];
            {
                uint32_t bb = fsb + 18432 + (uint32_t)(((wn * 16 + lo16) * 36) + hi16 * 4 + ko) * 4;
                uint32_t t[4];
                ldsm_x4(t, bb);
                bh2[0][0] = t[0]; bh2[1][0] = t[1]; bh2[0][1] = t[2]; bh2[1][1] = t[3];
                ldsm_x4(t, bb + 4608);
                bl2[0][0] = t[0]; bl2[1][0] = t[1]; bl2[0][1] = t[2]; bl2[1][1] = t[3];
            }
            #pragma unroll
            for (int nt = 0; nt < 2; nt++) {
                mma_f16(s[nt], al, bh2[nt]);
                mma_f16(s[nt], ah, bl2[nt]);
                mma_f16(s[nt], ah, bh2[nt]);
            }
        }
        #pragma unroll
        for (int nt = 0; nt < 2; nt++) {
            #pragma unroll
            for (int j = 0; j < 4; j++) {
                int row = wm * 16 + g + (j >> 1) * 8;
                int col = wn * 16 + nt * 8 + tg * 2 + (j & 1);
                float sv = s[nt][j] * 0.125f;
                if (causal) {
                    int kg = kv0 + col, qg = q0 + row;
                    if (kg > qg || am[b * Tn + kg] == 0) sv = -1e9f;
                }
                Ps[row * 33 + col] = sv;
            }
        }
        __syncthreads();
        {
            int row = tid >> 2, sub = tid & 3;
            float mo = rowm[row], mx = mo;
            #pragma unroll
            for (int j = 0; j < 8; j++) mx = fmaxf(mx, Ps[row * 33 + sub * 8 + j]);
            mx = fmaxf(mx, __shfl_xor_sync(0xffffffffu, mx, 1));
            mx = fmaxf(mx, __shfl_xor_sync(0xffffffffu, mx, 2));
            float sum = 0.f;
            #pragma unroll
            for (int j = 0; j < 8; j++) {
                float p = __expf(Ps[row * 33 + sub * 8 + j] - mx);
                h16 ph, pl; hsplit(p, ph, pl);
                Phs[row * 40 + sub * 8 + j] = ph;
                Pls[row * 40 + sub * 8 + j] = pl;
                sum += p;
            }
            sum += __shfl_xor_sync(0xffffffffu, sum, 1);
            sum += __shfl_xor_sync(0xffffffffu, sum, 2);
            if (sub == 0) {
                float al2 = __expf(mo - mx);
                rowm[row] = mx;
                rowl[row] = rowl[row] * al2 + sum;
                alph[row] = al2;
            }
        }
        __syncthreads();
        {
            float a0 = alph[wm * 16 + g], a1 = alph[wm * 16 + g + 8];
            #pragma unroll
            for (int nt = 0; nt < 4; nt++) {
                o[nt][0] *= a0; o[nt][1] *= a0;
                o[nt][2] *= a1; o[nt][3] *= a1;
            }
        }
        #pragma unroll
        for (int kc = 0; kc < 2; kc++) {
            int ko = kc * 8;
            uint32_t ah[4], al[4];
            uint32_t ab = fsb + 37888 + (uint32_t)(((wm * 16 + lo16) * 20) + hi16 * 4 + ko) * 4;
            ldsm_x4(ah, ab);
            ldsm_x4(al, ab + 5120);
            uint32_t bh4[4][2], bl4[4][2];
            #pragma unroll
            for (int pr = 0; pr < 2; pr++) {
                uint32_t bb = fsb + 27648 + (uint32_t)(((wn * 32 + pr * 16 + lo16) * 20) + hi16 * 4 + ko) * 4;
                uint32_t t[4];
                ldsm_x4(t, bb);
                bh4[pr * 2][0] = t[0]; bh4[pr * 2 + 1][0] = t[1];
                bh4[pr * 2][1] = t[2]; bh4[pr * 2 + 1][1] = t[3];
                ldsm_x4(t, bb + 5120);
                bl4[pr * 2][0] = t[0]; bl4[pr * 2 + 1][0] = t[1];
                bl4[pr * 2][1] = t[2]; bl4[pr * 2 + 1][1] = t[3];
            }
            #pragma unroll
            for (int nt = 0; nt < 4; nt++) {
                mma_f16(o[nt], al, bh4[nt]);
                mma_f16(o[nt], ah, bl4[nt]);
                mma_f16(o[nt], ah, bh4[nt]);
            }
        }
    }
    __syncthreads();
    {
        float inv0 = 1.f / rowl[wm * 16 + g];
        float inv1 = 1.f / rowl[wm * 16 + g + 8];
        int row0 = q0 + wm * 16 + g;
        #pragma unroll
        for (int nt = 0; nt < 4; nt++) {
            int col = h * DHn + wn * 32 + nt * 8 + tg * 2;
            long o0 = ((long)b * Tn + row0) * Dm + col;
            long o1 = ((long)b * Tn + row0 + 8) * Dm + col;
            h16 hh, ll;
            hsplit(o[nt][0] * inv0, hh, ll); Oh[o0] = hh;     Ol[o0] = ll;
            hsplit(o[nt][1] * inv0, hh, ll); Oh[o0 + 1] = hh; Ol[o0 + 1] = ll;
            hsplit(o[nt][2] * inv1, hh, ll); Oh[o1] = hh;     Ol[o1] = ll;
            hsplit(o[nt][3] * inv1, hh, ll); Oh[o1 + 1] = hh; Ol[o1 + 1] = ll;
        }
    }
}

// ---------------- add + layernorm ----------------
__global__ void __launch_bounds__(256) add_ln_k(const float* __restrict__ base,
                                                const float* __restrict__ delta, int nslots,
                                                const float* __restrict__ g,
                                                const float* __restrict__ bet,
                                                float* __restrict__ out,
                                                h16* __restrict__ oh, h16* __restrict__ ol)
{
    int t = blockIdx.x, tid = threadIdx.x;
    __shared__ float red[256];
    float x0 = base[(long)t * Dm + tid];
    float x1 = base[(long)t * Dm + 256 + tid];
    if (nslots == 1) {
        x0 += delta[(long)t * Dm + tid];
        x1 += delta[(long)t * Dm + 256 + tid];
    } else {
        x0 += delta[(long)(t * 2) * Dm + tid] + delta[(long)(t * 2 + 1) * Dm + tid];
        x1 += delta[(long)(t * 2) * Dm + 256 + tid] + delta[(long)(t * 2 + 1) * Dm + 256 + tid];
    }
    red[tid] = x0 + x1;
    __syncthreads();
    #pragma unroll
    for (int s = 128; s > 0; s >>= 1) {
        if (tid < s) red[tid] += red[tid + s];
        __syncthreads();
    }
    float mu = red[0] * (1.f / Dm);
    __syncthreads();
    float d0 = x0 - mu, d1 = x1 - mu;
    red[tid] = d0 * d0 + d1 * d1;
    __syncthreads();
    #pragma unroll
    for (int s = 128; s > 0; s >>= 1) {
        if (tid < s) red[tid] += red[tid + s];
        __syncthreads();
    }
    float rs = rsqrtf(red[0] * (1.f / Dm) + 1e-5f);
    float v0 = d0 * rs * g[tid] + bet[tid];
    float v1 = d1 * rs * g[tid + 256] + bet[tid + 256];
    out[(long)t * Dm + tid] = v0;
    out[(long)t * Dm + 256 + tid] = v1;
    h16 h, l;
    hsplit(v0, h, l); oh[(long)t * Dm + tid] = h; ol[(long)t * Dm + tid] = l;
    hsplit(v1, h, l); oh[(long)t * Dm + 256 + tid] = h; ol[(long)t * Dm + 256 + tid] = l;
}

// ---------------- router / aux loss / grouping ----------------
__global__ void __launch_bounds__(256) router_k(const float* __restrict__ y,
                                                const float* __restrict__ rw,
                                                const float* __restrict__ rb,
                                                float* __restrict__ probs,
                                                int* __restrict__ topi,
                                                float* __restrict__ gates)
{
    int warp = (blockIdx.x * blockDim.x + threadIdx.x) >> 5;
    int lane = threadIdx.x & 31;
    if (warp >= NT) return;
    const float* x = y + (long)warp * Dm;
    float acc[En];
    #pragma unroll
    for (int e = 0; e < En; e++) acc[e] = 0.f;
    for (int d = lane; d < Dm; d += 32) {
        float xv = x[d];
        const float* w = rw + (long)d * En;
        #pragma unroll
        for (int e = 0; e < En; e++) acc[e] += xv * w[e];
    }
    #pragma unroll
    for (int e = 0; e < En; e++) {
        #pragma unroll
        for (int off = 16; off > 0; off >>= 1)
            acc[e] += __shfl_xor_sync(0xffffffffu, acc[e], off);
    }
    float lg[En], p[En];
    float m = -1e30f;
    #pragma unroll
    for (int e = 0; e < En; e++) { lg[e] = acc[e] + rb[e]; m = fmaxf(m, lg[e]); }
    float sum = 0.f;
    #pragma unroll
    for (int e = 0; e < En; e++) { p[e] = __expf(lg[e] - m); sum += p[e]; }
    float inv = 1.f / sum;
    #pragma unroll
    for (int e = 0; e < En; e++) p[e] *= inv;
    int e0 = 0; float v0 = p[0];
    #pragma unroll
    for (int e = 1; e < En; e++) if (p[e] > v0) { v0 = p[e]; e0 = e; }
    int e1 = -1; float v1 = -1.f;
    #pragma unroll
    for (int e = 0; e < En; e++) if (e != e0 && p[e] > v1) { v1 = p[e]; e1 = e; }
    if (lane == 0) {
        #pragma unroll
        for (int e = 0; e < En; e++) probs[(long)warp * En + e] = p[e];
        float den = 1.f / (v0 + v1);
        topi[warp * 2 + 0] = e0;
        topi[warp * 2 + 1] = e1;
        gates[warp * 2 + 0] = v0 * den;
        gates[warp * 2 + 1] = v1 * den;
    }
}

__global__ void __launch_bounds__(1024) lb_k(const float* __restrict__ probs,
                                             const int* __restrict__ topi,
                                             float* __restrict__ lbout, int first)
{
    __shared__ float sm[1024];
    int tid = threadIdx.x;
    float ps[En], cs[En];
    #pragma unroll
    for (int e = 0; e < En; e++) { ps[e] = 0.f; cs[e] = 0.f; }
    for (int t = tid; t < NT; t += 1024) {
        #pragma unroll
        for (int e = 0; e < En; e++) ps[e] += probs[(long)t * En + e];
        int a = topi[2 * t], b = topi[2 * t + 1];
        #pragma unroll
        for (int e = 0; e < En; e++) cs[e] += (float)((e == a) + (e == b));
    }
    float lb = 0.f;
    for (int e = 0; e < En; e++) {
        sm[tid] = ps[e]; __syncthreads();
        for (int s = 512; s > 0; s >>= 1) { if (tid < s) sm[tid] += sm[tid + s]; __syncthreads(); }
        float P = sm[0]; __syncthreads();
        sm[tid] = cs[e]; __syncthreads();
        for (int s = 512; s > 0; s >>= 1) { if (tid < s) sm[tid] += sm[tid + s]; __syncthreads(); }
        float C = sm[0]; __syncthreads();
        lb += (C * (1.f / NT)) * (P * (1.f / NT));
    }
    if (tid == 0) {
        lb *= (float)En;
        if (first) *lbout = lb; else *lbout += lb;
    }
}

__global__ void __launch_bounds__(256) group_k(const int* __restrict__ topi,
                                               int* __restrict__ perm,
                                               int* __restrict__ offsets,
                                               int2* __restrict__ tiles)
{
    __shared__ int cnts[En];
    __shared__ int offs_s[En + 1];
    int w = threadIdx.x >> 5, lane = threadIdx.x & 31;
    int c = 0;
    for (int i = lane; i < NEn; i += 32) c += (topi[i] == w);
    #pragma unroll
    for (int off = 16; off > 0; off >>= 1) c += __shfl_xor_sync(0xffffffffu, c, off);
    if (lane == 0) cnts[w] = c;
    __syncthreads();
    if (threadIdx.x == 0) {
        offs_s[0] = 0;
        for (int e = 0; e < En; e++) offs_s[e + 1] = offs_s[e] + cnts[e];
        for (int e = 0; e <= En; e++) offsets[e] = offs_s[e];
        int t = 0;
        for (int e = 0; e < En; e++) {
            int cnt = offs_s[e + 1] - offs_s[e];
            for (int m0 = 0; m0 < cnt; m0 += 128)
                tiles[t++] = make_int2(e, m0);
        }
        for (; t < MAXT; t++) tiles[t] = make_int2(-1, 0);
    }
    __syncthreads();
    int pos = offs_s[w];
    for (int i0 = 0; i0 < NEn; i0 += 32) {
        int i = i0 + lane;
        int e = topi[i];
        unsigned mk = __ballot_sync(0xffffffffu, e == w);
        if (e == w) {
            int r = __popc(mk & ((1u << lane) - 1u));
            perm[pos + r] = i;
        }
        pos += __popc(mk);
    }
}

// ---------------- host ----------------
extern "C" void kernel_launch(void* const* d_in, const int* in_sizes, int n_in,
                              void* d_out, int out_size)
{
    (void)in_sizes; (void)n_in;
    const int*   ids  = (const int*)d_in[0];
    const float* enc  = (const float*)d_in[1];
    const int*   am   = (const int*)d_in[2];
    const float* emb  = (const float*)d_in[3];
    const float* pos  = (const float*)d_in[4];
    const float* sa_w = (const float*)d_in[5];
    const float* sa_b = (const float*)d_in[6];
    const float* ca_w = (const float*)d_in[7];
    const float* ca_b = (const float*)d_in[8];
    const float* ln_g = (const float*)d_in[9];
    const float* ln_b = (const float*)d_in[10];
    const float* rw   = (const float*)d_in[11];
    const float* rb   = (const float*)d_in[12];
    const float* w1   = (const float*)d_in[13];
    const float* b1   = (const float*)d_in[14];
    const float* w2   = (const float*)d_in[15];
    const float* b2   = (const float*)d_in[16];
    float* out = (float*)d_out;

    float *y, *proj, *probs, *gates, *eout;
    int *topi, *perm, *offs;
    int2* tiles;
    h16 *qkvh, *qkvl, *yh, *yl, *ench, *encl, *ath, *atl, *Hh, *Hl;
    h16 *sawh, *sawl, *cawh, *cawl, *w1h, *w1l, *w2h, *w2l;
    cudaGetSymbolAddress((void**)&y, g_y);
    cudaGetSymbolAddress((void**)&proj, g_proj);
    cudaGetSymbolAddress((void**)&probs, g_probs);
    cudaGetSymbolAddress((void**)&gates, g_gates);
    cudaGetSymbolAddress((void**)&eout, g_eout);
    cudaGetSymbolAddress((void**)&topi, g_topi);
    cudaGetSymbolAddress((void**)&perm, g_perm);
    cudaGetSymbolAddress((void**)&offs, g_offs);
    cudaGetSymbolAddress((void**)&tiles, g_tiles);
    cudaGetSymbolAddress((void**)&qkvh, g_qkvh);
    cudaGetSymbolAddress((void**)&qkvl, g_qkvl);
    cudaGetSymbolAddress((void**)&yh, g_yh);
    cudaGetSymbolAddress((void**)&yl, g_yl);
    cudaGetSymbolAddress((void**)&ench, g_ench);
    cudaGetSymbolAddress((void**)&encl, g_encl);
    cudaGetSymbolAddress((void**)&ath, g_ath);
    cudaGetSymbolAddress((void**)&atl, g_atl);
    cudaGetSymbolAddress((void**)&Hh, g_Hh);
    cudaGetSymbolAddress((void**)&Hl, g_Hl);
    cudaGetSymbolAddress((void**)&sawh, g_sawh);
    cudaGetSymbolAddress((void**)&sawl, g_sawl);
    cudaGetSymbolAddress((void**)&cawh, g_cawh);
    cudaGetSymbolAddress((void**)&cawl, g_cawl);
    cudaGetSymbolAddress((void**)&w1h, g_w1h);
    cudaGetSymbolAddress((void**)&w1l, g_w1l);
    cudaGetSymbolAddress((void**)&w2h, g_w2h);
    cudaGetSymbolAddress((void**)&w2l, g_w2l);

    cudaFuncSetAttribute(gemm_k<RowAh, EpiBiasH>,    cudaFuncAttributeMaxDynamicSharedMemorySize, GSMEM);
    cudaFuncSetAttribute(gemm_k<RowAh, EpiBias>,     cudaFuncAttributeMaxDynamicSharedMemorySize, GSMEM);
    cudaFuncSetAttribute(gemm_k<CrossAh, EpiBiasH>,  cudaFuncAttributeMaxDynamicSharedMemorySize, GSMEM);
    cudaFuncSetAttribute(gemm_k<GatherAh, EpiMoE1>,  cudaFuncAttributeMaxDynamicSharedMemorySize, GSMEM);
    cudaFuncSetAttribute(gemm_k<HRowAh, EpiMoE2>,    cudaFuncAttributeMaxDynamicSharedMemorySize, GSMEM);
    cudaFuncSetAttribute(flash_k, cudaFuncAttributeMaxDynamicSharedMemorySize, FSMEM);

    const long DD = (long)Dm * Dm;
    const long SLOT = (long)NT * Dm;

    wsplit_t_k<<<dim3(8, 16, Ln * 4), 256>>>(sa_w, sawh, sawl, Dm, Dm);
    wsplit_t_k<<<dim3(8, 16, Ln * 4), 256>>>(ca_w, cawh, cawl, Dm, Dm);
    wsplit_t_k<<<dim3(8, 64, Ln * En), 256>>>(w1, w1h, w1l, Dm, FFn);
    wsplit_t_k<<<dim3(32, 16, Ln * En), 256>>>(w2, w2h, w2l, FFn, Dm);
    split_k<<<(NT * Dm + 255) / 256, 256>>>(enc, ench, encl, NT * Dm);

    embed_k<<<NT, 256>>>(ids, emb, pos, y, yh, yl);

    for (int l = 0; l < Ln; l++) {
        gemm_k<<<dim3(16, 8, 3), 256, GSMEM>>>(
            RowAh{yh, yl, Dm, 0, NT}, sawh + l * 4 * DD, sawl + l * 4 * DD, DD,
            EpiBiasH{sa_b + (long)l * 4 * Dm, Dm, qkvh, qkvl, SLOT, Dm}, Dm, nullptr);
        flash_k<<<dim3(Tn / 64, 16), 256, FSMEM>>>(qkvh, qkvl, qkvh + SLOT, qkvl + SLOT,
                                                   qkvh + 2 * SLOT, qkvl + 2 * SLOT, ath, atl, am, Tn, 1);
        gemm_k<<<dim3(16, 8, 1), 256, GSMEM>>>(
            RowAh{ath, atl, Dm, 0, NT}, sawh + (l * 4 + 3) * DD, sawl + (l * 4 + 3) * DD, 0,
            EpiBias{sa_b + (long)(l * 4 + 3) * Dm, 0, proj, 0, Dm}, Dm, nullptr);
        add_ln_k<<<NT, 256>>>(y, proj, 1, ln_g + (l * 3 + 0) * Dm, ln_b + (l * 3 + 0) * Dm, y, yh, yl);

        gemm_k<<<dim3(16, 8, 3), 256, GSMEM>>>(
            CrossAh{yh, yl, ench, encl, nullptr, nullptr},
            cawh + l * 4 * DD, cawl + l * 4 * DD, DD,
            EpiBiasH{ca_b + (long)l * 4 * Dm, Dm, qkvh, qkvl, SLOT, Dm}, Dm, nullptr);
        flash_k<<<dim3(Tn / 64, 16), 256, FSMEM>>>(qkvh, qkvl, qkvh + SLOT, qkvl + SLOT,
                                                   qkvh + 2 * SLOT, qkvl + 2 * SLOT, ath, atl, nullptr, Tn, 0);
        gemm_k<<<dim3(16, 8, 1), 256, GSMEM>>>(
            RowAh{ath, atl, Dm, 0, NT}, cawh + (l * 4 + 3) * DD, cawl + (l * 4 + 3) * DD, 0,
            EpiBias{ca_b + (long)(l * 4 + 3) * Dm, 0, proj, 0, Dm}, Dm, nullptr);
        add_ln_k<<<NT, 256>>>(y, proj, 1, ln_g + (l * 3 + 1) * Dm, ln_b + (l * 3 + 1) * Dm, y, yh, yl);

        router_k<<<NT / 8, 256>>>(y, rw + (long)l * Dm * En, rb + l * En, probs, topi, gates);
        lb_k<<<1, 1024>>>(probs, topi, out + (out_size - 1), l == 0 ? 1 : 0);
        group_k<<<1, 256>>>(topi, perm, offs, tiles);
        gemm_k<<<dim3(MAXT, 32, 1), 256, GSMEM>>>(
            GatherAh{yh, yl, perm, offs, 0},
            w1h + (long)l * En * FFn * Dm, w1l + (long)l * En * FFn * Dm, (long)FFn * Dm,
            EpiMoE1{b1 + (long)l * En * FFn, offs, Hh, Hl, nullptr, nullptr, nullptr}, Dm, tiles);
        gemm_k<<<dim3(MAXT, 8, 1), 256, GSMEM>>>(
            HRowAh{Hh, Hl, offs, nullptr, nullptr},
            w2h + (long)l * En * Dm * FFn, w2l + (long)l * En * Dm * FFn, (long)Dm * FFn,
            EpiMoE2{b2 + (long)l * En * Dm, offs, perm, gates, eout, nullptr, 0}, FFn, tiles);
        float* lnout = (l == Ln - 1) ? out : y;
        add_ln_k<<<NT, 256>>>(y, eout, 2, ln_g + (l * 3 + 2) * Dm, ln_b + (l * 3 + 2) * Dm, lnout, yh, yl);
    }
}

// round 16
// speedup vs baseline: 1.0872x; 1.0114x over previous
#include <cuda_runtime.h>
#include <cuda_fp16.h>
#include <math.h>
#include <stdint.h>

#define Dm   512
#define Tn   1024
#define NT   2048
#define Ln   4
#define En   8
#define FFn  2048
#define NEn  4096
#define DHn  64
#define MAXT 40

typedef __half h16;

// ---------------- scratch ----------------
__device__ __align__(128) float g_y[NT * Dm];
__device__ __align__(128) float g_proj[NT * Dm];
__device__ __align__(128) float g_probs[NT * En];
__device__ __align__(128) float g_gates[NEn];
__device__ __align__(128) float g_eout[(size_t)NEn * Dm];
__device__ int g_topi[NEn];
__device__ int g_perm[NEn];
__device__ int g_offs[En + 1];
__device__ int2 g_tiles[MAXT];
__device__ __align__(128) h16 g_qkvh[3 * NT * Dm], g_qkvl[3 * NT * Dm];
__device__ __align__(128) h16 g_yh[NT * Dm],  g_yl[NT * Dm];
__device__ __align__(128) h16 g_ench[NT * Dm], g_encl[NT * Dm];
__device__ __align__(128) h16 g_ath[NT * Dm], g_atl[NT * Dm];
__device__ __align__(128) h16 g_Hh[(size_t)NEn * FFn], g_Hl[(size_t)NEn * FFn];
__device__ __align__(128) h16 g_sawh[(size_t)Ln * 4 * Dm * Dm], g_sawl[(size_t)Ln * 4 * Dm * Dm];
__device__ __align__(128) h16 g_cawh[(size_t)Ln * 4 * Dm * Dm], g_cawl[(size_t)Ln * 4 * Dm * Dm];
__device__ __align__(128) h16 g_w1h[(size_t)Ln * En * FFn * Dm], g_w1l[(size_t)Ln * En * FFn * Dm];
__device__ __align__(128) h16 g_w2h[(size_t)Ln * En * Dm * FFn], g_w2l[(size_t)Ln * En * Dm * FFn];

__device__ __forceinline__ uint32_t smem_u32(const void* p) {
    uint32_t a;
    asm("{ .reg .u64 t; cvta.to.shared.u64 t, %1; cvt.u32.u64 %0, t; }" : "=r"(a) : "l"(p));
    return a;
}
__device__ __forceinline__ void hsplit(float v, h16& h, h16& l) {
    h = __float2half_rn(v);
    l = __float2half_rn(v - __half2float(h));
}
#define CPA(d, s, sz) asm volatile("cp.async.ca.shared.global [%0], [%1], 16, %2;" :: "r"(d), "l"(s), "r"(sz) : "memory")
#define CP_COMMIT()   asm volatile("cp.async.commit_group;" ::: "memory")
#define CP_WAIT1()    asm volatile("cp.async.wait_group 1;" ::: "memory")
#define CP_WAIT0()    asm volatile("cp.async.wait_group 0;" ::: "memory")

__device__ __forceinline__ void mma_f16(float c[4], const uint32_t a[4], const uint32_t b[2])
{
    asm volatile(
        "mma.sync.aligned.m16n8k16.row.col.f32.f16.f16.f32 "
        "{%0,%1,%2,%3},{%4,%5,%6,%7},{%8,%9},{%0,%1,%2,%3};"
        : "+f"(c[0]), "+f"(c[1]), "+f"(c[2]), "+f"(c[3])
        : "r"(a[0]), "r"(a[1]), "r"(a[2]), "r"(a[3]), "r"(b[0]), "r"(b[1]));
}
__device__ __forceinline__ void ldsm_x4(uint32_t r[4], uint32_t addr)
{
    asm volatile("ldmatrix.sync.aligned.m8n8.x4.shared.b16 {%0,%1,%2,%3}, [%4];"
        : "=r"(r[0]), "=r"(r[1]), "=r"(r[2]), "=r"(r[3]) : "r"(addr));
}

// ---------------- A providers ----------------
struct RowAh {
    const h16 *Ah, *Al; int lda; long zs; int M;
    __device__ int setz(int z) { Ah += (long)z * zs; Al += (long)z * zs; return M; }
    __device__ const h16* rowh(int m) const { return Ah + (long)m * lda; }
    __device__ const h16* rowl(int m) const { return Al + (long)m * lda; }
};
struct CrossAh {
    const h16 *Yh, *Yl, *Eh, *El;
    const h16 *Ah, *Al;
    __device__ int setz(int z) {
        Ah = (z == 0) ? Yh : Eh;
        Al = (z == 0) ? Yl : El;
        return NT;
    }
    __device__ const h16* rowh(int m) const { return Ah + (long)m * Dm; }
    __device__ const h16* rowl(int m) const { return Al + (long)m * Dm; }
};
struct GatherAh {
    const h16 *Yh, *Yl; const int* perm; const int* offs; int base;
    __device__ int setz(int e) { base = offs[e]; return offs[e + 1] - base; }
    __device__ const h16* rowh(int m) const { return Yh + (long)(perm[base + m] >> 1) * Dm; }
    __device__ const h16* rowl(int m) const { return Yl + (long)(perm[base + m] >> 1) * Dm; }
};
struct HRowAh {
    const h16 *Hh, *Hl; const int* offs; const h16 *Ah, *Al;
    __device__ int setz(int e) {
        int b0 = offs[e];
        Ah = Hh + (long)b0 * FFn; Al = Hl + (long)b0 * FFn;
        return offs[e + 1] - b0;
    }
    __device__ const h16* rowh(int m) const { return Ah + (long)m * FFn; }
    __device__ const h16* rowl(int m) const { return Al + (long)m * FFn; }
};
// ---------------- epilogues ----------------
struct EpiBias {
    const float* bias; long biasZ; float* C; long cZ; int ldc;
    __device__ void setz(int z) { bias += (long)z * biasZ; C += (long)z * cZ; }
    __device__ void op(int m, int n, float v) { C[(long)m * ldc + n] = v + bias[n]; }
};
struct EpiBiasH {
    const float* bias; long biasZ; h16* Ch; h16* Cl; long cZ; int ldc;
    __device__ void setz(int z) { bias += (long)z * biasZ; Ch += (long)z * cZ; Cl += (long)z * cZ; }
    __device__ void op(int m, int n, float v) {
        v += bias[n];
        h16 h, l; hsplit(v, h, l);
        Ch[(long)m * ldc + n] = h; Cl[(long)m * ldc + n] = l;
    }
};
struct EpiMoE1 {
    const float* b1l; const int* offs; h16* Hh; h16* Hl;
    const float* bias; h16 *Ch, *Cl;
    __device__ void setz(int e) {
        bias = b1l + (long)e * FFn;
        Ch = Hh + (long)offs[e] * FFn; Cl = Hl + (long)offs[e] * FFn;
    }
    __device__ void op(int m, int n, float v) {
        v = fmaxf(v + bias[n], 0.f);
        h16 h, l; hsplit(v, h, l);
        Ch[(long)m * FFn + n] = h; Cl[(long)m * FFn + n] = l;
    }
};
struct EpiMoE2 {
    const float* b2l; const int* offs; const int* perm; const float* gates; float* eout;
    const float* bias; int base;
    __device__ void setz(int e) { bias = b2l + (long)e * Dm; base = offs[e]; }
    __device__ void op(int m, int n, float v) {
        int entry = perm[base + m];
        eout[(long)entry * Dm + n] = gates[entry] * (v + bias[n]);
    }
};

// ------- fp16x3 GEMM: 128x64 tile, BK=32, 2-stage cp.async, ldmatrix --------
constexpr int STGH = 15360;
constexpr int GSMEM = 2 * STGH * 2;

template <class AP, class EP>
__global__ void __launch_bounds__(256, 2) gemm_k(AP ap, const h16* __restrict__ BTh,
                                                 const h16* __restrict__ BTl, long bz,
                                                 EP ep, int K, const int2* __restrict__ tt)
{
    extern __shared__ h16 smh[];
    int z, m0;
    if (tt) {
        int2 t = tt[blockIdx.x];
        if (t.x < 0) return;
        z = t.x; m0 = t.y;
    } else {
        z = blockIdx.z; m0 = blockIdx.x * 128;
    }
    int M = ap.setz(z);
    if (m0 >= M) return;
    ep.setz(z);
    int n0 = blockIdx.y * 64;

    int tid = threadIdx.x, lane = tid & 31, wid = tid >> 5;
    int wm = wid & 3, wn = wid >> 2;
    int g = lane >> 2, tg = lane & 3;
    int lo16 = lane & 15, hi16 = lane >> 4;
    uint32_t smb = smem_u32(smh);

    int r4 = tid >> 2;
    int c4 = (tid & 3) * 8;
    bool v0 = (m0 + r4) < M, v1 = (m0 + 64 + r4) < M;
    uint32_t szA0 = v0 ? 16u : 0u, szA1 = v1 ? 16u : 0u;
    const h16* sAh0 = ap.rowh(v0 ? m0 + r4 : m0) + c4;
    const h16* sAl0 = ap.rowl(v0 ? m0 + r4 : m0) + c4;
    const h16* sAh1 = ap.rowh(v1 ? m0 + 64 + r4 : m0) + c4;
    const h16* sAl1 = ap.rowl(v1 ? m0 + 64 + r4 : m0) + c4;
    const h16* sBh = BTh + (long)z * bz + (long)(n0 + r4) * K + c4;
    const h16* sBl = BTl + (long)z * bz + (long)(n0 + r4) * K + c4;

    uint32_t dA0 = (uint32_t)r4 * 80 + (uint32_t)(tid & 3) * 16;
    uint32_t dA1 = dA0 + 5120;

    auto issue = [&](int s) {
        uint32_t b = smb + (uint32_t)(s & 1) * (STGH * 2);
        int ko = s * 32;
        CPA(b + dA0, sAh0 + ko, szA0);
        CPA(b + dA1, sAh1 + ko, szA1);
        CPA(b + 10240 + dA0, sAl0 + ko, szA0);
        CPA(b + 10240 + dA1, sAl1 + ko, szA1);
        CPA(b + 20480 + dA0, sBh + ko, 16u);
        CPA(b + 25600 + dA0, sBl + ko, 16u);
        CP_COMMIT();
    };

    float acc[2][4][4];
    #pragma unroll
    for (int mt = 0; mt < 2; mt++)
        #pragma unroll
        for (int nt = 0; nt < 4; nt++)
            #pragma unroll
            for (int j = 0; j < 4; j++) acc[mt][nt][j] = 0.f;

    int ns = K / 32;
    issue(0);
    for (int s = 0; s < ns; s++) {
        bool more = (s + 1 < ns);
        if (more) issue(s + 1);
        if (more) CP_WAIT1(); else CP_WAIT0();
        __syncthreads();

        uint32_t Wb = smb + (uint32_t)(s & 1) * (STGH * 2);
        #pragma unroll
        for (int kc = 0; kc < 2; kc++) {
            int ko = kc * 8;
            uint32_t ah[2][4], al[2][4], bh[4][2], bl[4][2];
            #pragma unroll
            for (int mt = 0; mt < 2; mt++) {
                uint32_t ab = Wb + (uint32_t)(((wm * 32 + mt * 16 + lo16) * 20) + hi16 * 4 + ko) * 4;
                ldsm_x4(ah[mt], ab);
                ldsm_x4(al[mt], ab + 10240);
            }
            #pragma unroll
            for (int pr = 0; pr < 2; pr++) {
                uint32_t bb = Wb + 20480 + (uint32_t)(((wn * 32 + pr * 16 + lo16) * 20) + hi16 * 4 + ko) * 4;
                uint32_t t[4];
                ldsm_x4(t, bb);
                bh[pr * 2][0] = t[0]; bh[pr * 2 + 1][0] = t[1];
                bh[pr * 2][1] = t[2]; bh[pr * 2 + 1][1] = t[3];
                ldsm_x4(t, bb + 5120);
                bl[pr * 2][0] = t[0]; bl[pr * 2 + 1][0] = t[1];
                bl[pr * 2][1] = t[2]; bl[pr * 2 + 1][1] = t[3];
            }
            #pragma unroll
            for (int mt = 0; mt < 2; mt++)
                #pragma unroll
                for (int nt = 0; nt < 4; nt++) {
                    mma_f16(acc[mt][nt], al[mt], bh[nt]);
                    mma_f16(acc[mt][nt], ah[mt], bl[nt]);
                    mma_f16(acc[mt][nt], ah[mt], bh[nt]);
                }
        }
        __syncthreads();
    }

    int r0 = wm * 32 + g;
    int c0 = wn * 32 + tg * 2;
    #pragma unroll
    for (int mt = 0; mt < 2; mt++) {
        int gm0 = m0 + r0 + mt * 16;
        int gm1 = gm0 + 8;
        #pragma unroll
        for (int nt = 0; nt < 4; nt++) {
            int gn = n0 + c0 + nt * 8;
            if (gm0 < M) { ep.op(gm0, gn, acc[mt][nt][0]); ep.op(gm0, gn + 1, acc[mt][nt][1]); }
            if (gm1 < M) { ep.op(gm1, gn, acc[mt][nt][2]); ep.op(gm1, gn + 1, acc[mt][nt][3]); }
        }
    }
}

// -------- weight transpose+split: 64(k) x 32(n) tiles, uint4 stores ---------
__global__ void __launch_bounds__(256) wsplit_t_k(const float* __restrict__ W,
                                                  h16* __restrict__ Oh, h16* __restrict__ Ol,
                                                  int K, int N)
{
    __shared__ float t[64][33];
    size_t zo = (size_t)blockIdx.z * K * N;
    int k0 = blockIdx.x * 64, n0 = blockIdx.y * 32;
    int tx = threadIdx.x & 31, ty = threadIdx.x >> 5;
    #pragma unroll
    for (int j = 0; j < 64; j += 8)
        t[ty + j][tx] = W[zo + (size_t)(k0 + ty + j) * N + n0 + tx];
    __syncthreads();
    int n = threadIdx.x >> 3;          // 0..31
    int seg = threadIdx.x & 7;         // 0..7, covers k halves seg*8..+7
    h16 hh[8], ll[8];
    #pragma unroll
    for (int j = 0; j < 8; j++)
        hsplit(t[seg * 8 + j][n], hh[j], ll[j]);
    size_t o = zo + (size_t)(n0 + n) * K + k0 + seg * 8;
    *(uint4*)(Oh + o) = *(uint4*)hh;
    *(uint4*)(Ol + o) = *(uint4*)ll;
}

// -------- enc split: 8 elems/thread, uint4 stores ---------------------------
__global__ void __launch_bounds__(256) split_k(const float* __restrict__ x,
                                               h16* __restrict__ oh, h16* __restrict__ ol, int n)
{
    int i = (blockIdx.x * 256 + threadIdx.x) * 8;
    if (i + 7 < n) {
        float4 a = *(const float4*)(x + i);
        float4 b = *(const float4*)(x + i + 4);
        float v[8] = {a.x, a.y, a.z, a.w, b.x, b.y, b.z, b.w};
        h16 hh[8], ll[8];
        #pragma unroll
        for (int j = 0; j < 8; j++) hsplit(v[j], hh[j], ll[j]);
        *(uint4*)(oh + i) = *(uint4*)hh;
        *(uint4*)(ol + i) = *(uint4*)ll;
    }
}

__global__ void embed_k(const int* __restrict__ ids, const float* __restrict__ emb,
                        const float* __restrict__ pos, float* __restrict__ y,
                        h16* __restrict__ yh, h16* __restrict__ yl)
{
    int t = blockIdx.x;
    int id = ids[t];
    int tq = t & (Tn - 1);
    const float* er = emb + (long)id * Dm;
    const float* pr = pos + (long)tq * Dm;
    long o = (long)t * Dm;
    for (int d = threadIdx.x; d < Dm; d += blockDim.x) {
        float v = er[d] + pr[d];
        y[o + d] = v;
        h16 h, l; hsplit(v, h, l);
        yh[o + d] = h; yl[o + d] = l;
    }
}

// ---------------- tensor-core flash attention (R14 proven) -------------------
constexpr int FSMEM = 57344;

__global__ void __launch_bounds__(256) flash_k(const h16* __restrict__ Qh, const h16* __restrict__ Ql,
                                               const h16* __restrict__ Kh, const h16* __restrict__ Kl,
                                               const h16* __restrict__ Vh, const h16* __restrict__ Vl,
                                               h16* __restrict__ Oh, h16* __restrict__ Ol,
                                               const int* __restrict__ am, int Tk, int causal)
{
    extern __shared__ h16 fs[];
    h16 *Qhs = fs, *Qls = fs + 4608, *Khs = fs + 9216, *Kls = fs + 11520;
    h16 *Vths = fs + 13824, *Vtls = fs + 16384, *Phs = fs + 18944, *Pls = fs + 21504;
    float* Ps = (float*)(fs + 24064);
    float* rowm = Ps + 64 * 33;
    float* rowl = rowm + 64;
    float* alph = rowl + 64;
    uint32_t fsb = smem_u32(fs);

    int q0 = blockIdx.x * 64;
    int bh_ = blockIdx.y;
    int b = bh_ >> 3, h = bh_ & 7;
    const h16* Qbh = Qh + ((long)b * Tn + q0) * Dm + h * DHn;
    const h16* Qbl = Ql + ((long)b * Tn + q0) * Dm + h * DHn;
    const h16* Kbh = Kh + (long)b * Tk * Dm + h * DHn;
    const h16* Kbl = Kl + (long)b * Tk * Dm + h * DHn;
    const h16* Vbh = Vh + (long)b * Tk * Dm + h * DHn;
    const h16* Vbl = Vl + (long)b * Tk * Dm + h * DHn;

    int tid = threadIdx.x, lane = tid & 31, wid = tid >> 5;
    int wm = wid & 3, wn = wid >> 2;
    int g = lane >> 2, tg = lane & 3;
    int lo16 = lane & 15, hi16 = lane >> 4;

    #pragma unroll
    for (int it = 0; it < 2; it++) {
        int idx = tid + it * 256;
        int r = idx >> 3, c8 = (idx & 7) * 8;
        *(uint4*)(Qhs + r * 72 + c8) = *(const uint4*)(Qbh + (long)r * Dm + c8);
        *(uint4*)(Qls + r * 72 + c8) = *(const uint4*)(Qbl + (long)r * Dm + c8);
    }
    if (tid < 64) { rowm[tid] = -1e30f; rowl[tid] = 0.f; }

    float o[4][4];
    #pragma unroll
    for (int i = 0; i < 4; i++)
        #pragma unroll
        for (int j = 0; j < 4; j++) o[i][j] = 0.f;

    int kvmax = causal ? (q0 + 64) : Tk;
    for (int kv0 = 0; kv0 < kvmax; kv0 += 32) {
        __syncthreads();
        {
            int r = tid >> 3, c8 = (tid & 7) * 8;
            *(uint4*)(Khs + r * 72 + c8) = *(const uint4*)(Kbh + (long)(kv0 + r) * Dm + c8);
            *(uint4*)(Kls + r * 72 + c8) = *(const uint4*)(Kbl + (long)(kv0 + r) * Dm + c8);
            h16 vh8[8], vl8[8];
            *(uint4*)vh8 = *(const uint4*)(Vbh + (long)(kv0 + r) * Dm + c8);
            *(uint4*)vl8 = *(const uint4*)(Vbl + (long)(kv0 + r) * Dm + c8);
            #pragma unroll
            for (int j = 0; j < 8; j++) {
                Vths[(c8 + j) * 40 + r] = vh8[j];
                Vtls[(c8 + j) * 40 + r] = vl8[j];
            }
        }
        __syncthreads();

        float s[2][4] = {{0.f, 0.f, 0.f, 0.f}, {0.f, 0.f, 0.f, 0.f}};
        #pragma unroll
        for (int kc = 0; kc < 4; kc++) {
            int ko = kc * 8;
            uint32_t ah[4], al[4];
            uint32_t ab = fsb + (uint32_t)(((wm * 16 + lo16) * 36) + hi16 * 4 + ko) * 4;
            ldsm_x4(ah, ab);
            ldsm_x4(al, ab + 9216);
            uint32_t bh2[2][2], bl2[2][2];
            {
                uint32_t bb = fsb + 18432 + (uint32_t)(((wn * 16 + lo16) * 36) + hi16 * 4 + ko) * 4;
                uint32_t t[4];
                ldsm_x4(t, bb);
                bh2[0][0] = t[0]; bh2[1][0] = t[1]; bh2[0][1] = t[2]; bh2[1][1] = t[3];
                ldsm_x4(t, bb + 4608);
                bl2[0][0] = t[0]; bl2[1][0] = t[1]; bl2[0][1] = t[2]; bl2[1][1] = t[3];
            }
            #pragma unroll
            for (int nt = 0; nt < 2; nt++) {
                mma_f16(s[nt], al, bh2[nt]);
                mma_f16(s[nt], ah, bl2[nt]);
                mma_f16(s[nt], ah, bh2[nt]);
            }
        }
        #pragma unroll
        for (int nt = 0; nt < 2; nt++) {
            #pragma unroll
            for (int j = 0; j < 4; j++) {
                int row = wm * 16 + g + (j >> 1) * 8;
                int col = wn * 16 + nt * 8 + tg * 2 + (j & 1);
                float sv = s[nt][j] * 0.125f;
                if (causal) {
                    int kg = kv0 + col, qg = q0 + row;
                    if (kg > qg || am[b * Tn + kg] == 0) sv = -1e9f;
                }
                Ps[row * 33 + col] = sv;
            }
        }
        __syncthreads();
        {
            int row = tid >> 2, sub = tid & 3;
            float mo = rowm[row], mx = mo;
            #pragma unroll
            for (int j = 0; j < 8; j++) mx = fmaxf(mx, Ps[row * 33 + sub * 8 + j]);
            mx = fmaxf(mx, __shfl_xor_sync(0xffffffffu, mx, 1));
            mx = fmaxf(mx, __shfl_xor_sync(0xffffffffu, mx, 2));
            float sum = 0.f;
            #pragma unroll
            for (int j = 0; j < 8; j++) {
                float p = __expf(Ps[row * 33 + sub * 8 + j] - mx);
                h16 ph, pl; hsplit(p, ph, pl);
                Phs[row * 40 + sub * 8 + j] = ph;
                Pls[row * 40 + sub * 8 + j] = pl;
                sum += p;
            }
            sum += __shfl_xor_sync(0xffffffffu, sum, 1);
            sum += __shfl_xor_sync(0xffffffffu, sum, 2);
            if (sub == 0) {
                float al2 = __expf(mo - mx);
                rowm[row] = mx;
                rowl[row] = rowl[row] * al2 + sum;
                alph[row] = al2;
            }
        }
        __syncthreads();
        {
            float a0 = alph[wm * 16 + g], a1 = alph[wm * 16 + g + 8];
            #pragma unroll
            for (int nt = 0; nt < 4; nt++) {
                o[nt][0] *= a0; o[nt][1] *= a0;
                o[nt][2] *= a1; o[nt][3] *= a1;
            }
        }
        #pragma unroll
        for (int kc = 0; kc < 2; kc++) {
            int ko = kc * 8;
            uint32_t ah[4], al[4];
            uint32_t ab = fsb + 37888 + (uint32_t)(((wm * 16 + lo16) * 20) + hi16 * 4 + ko) * 4;
            ldsm_x4(ah, ab);
            ldsm_x4(al, ab + 5120);
            uint32_t bh4[4][2], bl4[4][2];
            #pragma unroll
            for (int pr = 0; pr < 2; pr++) {
                uint32_t bb = fsb + 27648 + (uint32_t)(((wn * 32 + pr * 16 + lo16) * 20) + hi16 * 4 + ko) * 4;
                uint32_t t[4];
                ldsm_x4(t, bb);
                bh4[pr * 2][0] = t[0]; bh4[pr * 2 + 1][0] = t[1];
                bh4[pr * 2][1] = t[2]; bh4[pr * 2 + 1][1] = t[3];
                ldsm_x4(t, bb + 5120);
                bl4[pr * 2][0] = t[0]; bl4[pr * 2 + 1][0] = t[1];
                bl4[pr * 2][1] = t[2]; bl4[pr * 2 + 1][1] = t[3];
            }
            #pragma unroll
            for (int nt = 0; nt < 4; nt++) {
                mma_f16(o[nt], al, bh4[nt]);
                mma_f16(o[nt], ah, bl4[nt]);
                mma_f16(o[nt], ah, bh4[nt]);
            }
        }
    }
    __syncthreads();
    {
        float inv0 = 1.f / rowl[wm * 16 + g];
        float inv1 = 1.f / rowl[wm * 16 + g + 8];
        int row0 = q0 + wm * 16 + g;
        #pragma unroll
        for (int nt = 0; nt < 4; nt++) {
            int col = h * DHn + wn * 32 + nt * 8 + tg * 2;
            long o0 = ((long)b * Tn + row0) * Dm + col;
            long o1 = ((long)b * Tn + row0 + 8) * Dm + col;
            h16 hh, ll;
            hsplit(o[nt][0] * inv0, hh, ll); Oh[o0] = hh;     Ol[o0] = ll;
            hsplit(o[nt][1] * inv0, hh, ll); Oh[o0 + 1] = hh; Ol[o0 + 1] = ll;
            hsplit(o[nt][2] * inv1, hh, ll); Oh[o1] = hh;     Ol[o1] = ll;
            hsplit(o[nt][3] * inv1, hh, ll); Oh[o1 + 1] = hh; Ol[o1 + 1] = ll;
        }
    }
}

// ---------------- add + layernorm (warp-shuffle reductions) ------------------
__global__ void __launch_bounds__(256) add_ln_k(const float* __restrict__ base,
                                                const float* __restrict__ delta, int nslots,
                                                const float* __restrict__ g,
                                                const float* __restrict__ bet,
                                                float* __restrict__ out,
                                                h16* __restrict__ oh, h16* __restrict__ ol)
{
    int t = blockIdx.x, tid = threadIdx.x;
    int wid = tid >> 5, lane = tid & 31;
    __shared__ float red[8], red2[8];
    float x0 = base[(long)t * Dm + tid];
    float x1 = base[(long)t * Dm + 256 + tid];
    if (nslots == 1) {
        x0 += delta[(long)t * Dm + tid];
        x1 += delta[(long)t * Dm + 256 + tid];
    } else {
        x0 += delta[(long)(t * 2) * Dm + tid] + delta[(long)(t * 2 + 1) * Dm + tid];
        x1 += delta[(long)(t * 2) * Dm + 256 + tid] + delta[(long)(t * 2 + 1) * Dm + 256 + tid];
    }
    float sum = x0 + x1;
    #pragma unroll
    for (int off = 16; off > 0; off >>= 1) sum += __shfl_xor_sync(0xffffffffu, sum, off);
    if (lane == 0) red[wid] = sum;
    __syncthreads();
    float tot = red[0] + red[1] + red[2] + red[3] + red[4] + red[5] + red[6] + red[7];
    float mu = tot * (1.f / Dm);
    float d0 = x0 - mu, d1 = x1 - mu;
    float sq = d0 * d0 + d1 * d1;
    #pragma unroll
    for (int off = 16; off > 0; off >>= 1) sq += __shfl_xor_sync(0xffffffffu, sq, off);
    if (lane == 0) red2[wid] = sq;
    __syncthreads();
    float var = red2[0] + red2[1] + red2[2] + red2[3] + red2[4] + red2[5] + red2[6] + red2[7];
    float rs = rsqrtf(var * (1.f / Dm) + 1e-5f);
    float v0 = d0 * rs * g[tid] + bet[tid];
    float v1 = d1 * rs * g[tid + 256] + bet[tid + 256];
    out[(long)t * Dm + tid] = v0;
    out[(long)t * Dm + 256 + tid] = v1;
    h16 h, l;
    hsplit(v0, h, l); oh[(long)t * Dm + tid] = h; ol[(long)t * Dm + tid] = l;
    hsplit(v1, h, l); oh[(long)t * Dm + 256 + tid] = h; ol[(long)t * Dm + 256 + tid] = l;
}

// ---------------- router / aux loss / grouping ----------------
__global__ void __launch_bounds__(256) router_k(const float* __restrict__ y,
                                                const float* __restrict__ rw,
                                                const float* __restrict__ rb,
                                                float* __restrict__ probs,
                                                int* __restrict__ topi,
                                                float* __restrict__ gates)
{
    int warp = (blockIdx.x * blockDim.x + threadIdx.x) >> 5;
    int lane = threadIdx.x & 31;
    if (warp >= NT) return;
    const float* x = y + (long)warp * Dm;
    float acc[En];
    #pragma unroll
    for (int e = 0; e < En; e++) acc[e] = 0.f;
    for (int d = lane; d < Dm; d += 32) {
        float xv = x[d];
        const float* w = rw + (long)d * En;
        #pragma unroll
        for (int e = 0; e < En; e++) acc[e] += xv * w[e];
    }
    #pragma unroll
    for (int e = 0; e < En; e++) {
        #pragma unroll
        for (int off = 16; off > 0; off >>= 1)
            acc[e] += __shfl_xor_sync(0xffffffffu, acc[e], off);
    }
    float lg[En], p[En];
    float m = -1e30f;
    #pragma unroll
    for (int e = 0; e < En; e++) { lg[e] = acc[e] + rb[e]; m = fmaxf(m, lg[e]); }
    float sum = 0.f;
    #pragma unroll
    for (int e = 0; e < En; e++) { p[e] = __expf(lg[e] - m); sum += p[e]; }
    float inv = 1.f / sum;
    #pragma unroll
    for (int e = 0; e < En; e++) p[e] *= inv;
    int e0 = 0; float v0 = p[0];
    #pragma unroll
    for (int e = 1; e < En; e++) if (p[e] > v0) { v0 = p[e]; e0 = e; }
    int e1 = -1; float v1 = -1.f;
    #pragma unroll
    for (int e = 0; e < En; e++) if (e != e0 && p[e] > v1) { v1 = p[e]; e1 = e; }
    if (lane == 0) {
        #pragma unroll
        for (int e = 0; e < En; e++) probs[(long)warp * En + e] = p[e];
        float den = 1.f / (v0 + v1);
        topi[warp * 2 + 0] = e0;
        topi[warp * 2 + 1] = e1;
        gates[warp * 2 + 0] = v0 * den;
        gates[warp * 2 + 1] = v1 * den;
    }
}

__global__ void __launch_bounds__(1024) lb_k(const float* __restrict__ probs,
                                             const int* __restrict__ topi,
                                             float* __restrict__ lbout, int first)
{
    __shared__ float sm[1024];
    int tid = threadIdx.x;
    float ps[En], cs[En];
    #pragma unroll
    for (int e = 0; e < En; e++) { ps[e] = 0.f; cs[e] = 0.f; }
    for (int t = tid; t < NT; t += 1024) {
        #pragma unroll
        for (int e = 0; e < En; e++) ps[e] += probs[(long)t * En + e];
        int a = topi[2 * t], b = topi[2 * t + 1];
        #pragma unroll
        for (int e = 0; e < En; e++) cs[e] += (float)((e == a) + (e == b));
    }
    float lb = 0.f;
    for (int e = 0; e < En; e++) {
        sm[tid] = ps[e]; __syncthreads();
        for (int s = 512; s > 0; s >>= 1) { if (tid < s) sm[tid] += sm[tid + s]; __syncthreads(); }
        float P = sm[0]; __syncthreads();
        sm[tid] = cs[e]; __syncthreads();
        for (int s = 512; s > 0; s >>= 1) { if (tid < s) sm[tid] += sm[tid + s]; __syncthreads(); }
        float C = sm[0]; __syncthreads();
        lb += (C * (1.f / NT)) * (P * (1.f / NT));
    }
    if (tid == 0) {
        lb *= (float)En;
        if (first) *lbout = lb; else *lbout += lb;
    }
}

__global__ void __launch_bounds__(256) group_k(const int* __restrict__ topi,
                                               int* __restrict__ perm,
                                               int* __restrict__ offsets,
                                               int2* __restrict__ tiles)
{
    __shared__ int cnts[En];
    __shared__ int offs_s[En + 1];
    int w = threadIdx.x >> 5, lane = threadIdx.x & 31;
    int c = 0;
    for (int i = lane; i < NEn; i += 32) c += (topi[i] == w);
    #pragma unroll
    for (int off = 16; off > 0; off >>= 1) c += __shfl_xor_sync(0xffffffffu, c, off);
    if (lane == 0) cnts[w] = c;
    __syncthreads();
    if (threadIdx.x == 0) {
        offs_s[0] = 0;
        for (int e = 0; e < En; e++) offs_s[e + 1] = offs_s[e] + cnts[e];
        for (int e = 0; e <= En; e++) offsets[e] = offs_s[e];
        int t = 0;
        for (int e = 0; e < En; e++) {
            int cnt = offs_s[e + 1] - offs_s[e];
            for (int m0 = 0; m0 < cnt; m0 += 128)
                tiles[t++] = make_int2(e, m0);
        }
        for (; t < MAXT; t++) tiles[t] = make_int2(-1, 0);
    }
    __syncthreads();
    int pos = offs_s[w];
    for (int i0 = 0; i0 < NEn; i0 += 32) {
        int i = i0 + lane;
        int e = topi[i];
        unsigned mk = __ballot_sync(0xffffffffu, e == w);
        if (e == w) {
            int r = __popc(mk & ((1u << lane) - 1u));
            perm[pos + r] = i;
        }
        pos += __popc(mk);
    }
}

// ---------------- host ----------------
extern "C" void kernel_launch(void* const* d_in, const int* in_sizes, int n_in,
                              void* d_out, int out_size)
{
    (void)in_sizes; (void)n_in;
    const int*   ids  = (const int*)d_in[0];
    const float* enc  = (const float*)d_in[1];
    const int*   am   = (const int*)d_in[2];
    const float* emb  = (const float*)d_in[3];
    const float* pos  = (const float*)d_in[4];
    const float* sa_w = (const float*)d_in[5];
    const float* sa_b = (const float*)d_in[6];
    const float* ca_w = (const float*)d_in[7];
    const float* ca_b = (const float*)d_in[8];
    const float* ln_g = (const float*)d_in[9];
    const float* ln_b = (const float*)d_in[10];
    const float* rw   = (const float*)d_in[11];
    const float* rb   = (const float*)d_in[12];
    const float* w1   = (const float*)d_in[13];
    const float* b1   = (const float*)d_in[14];
    const float* w2   = (const float*)d_in[15];
    const float* b2   = (const float*)d_in[16];
    float* out = (float*)d_out;

    float *y, *proj, *probs, *gates, *eout;
    int *topi, *perm, *offs;
    int2* tiles;
    h16 *qkvh, *qkvl, *yh, *yl, *ench, *encl, *ath, *atl, *Hh, *Hl;
    h16 *sawh, *sawl, *cawh, *cawl, *w1h, *w1l, *w2h, *w2l;
    cudaGetSymbolAddress((void**)&y, g_y);
    cudaGetSymbolAddress((void**)&proj, g_proj);
    cudaGetSymbolAddress((void**)&probs, g_probs);
    cudaGetSymbolAddress((void**)&gates, g_gates);
    cudaGetSymbolAddress((void**)&eout, g_eout);
    cudaGetSymbolAddress((void**)&topi, g_topi);
    cudaGetSymbolAddress((void**)&perm, g_perm);
    cudaGetSymbolAddress((void**)&offs, g_offs);
    cudaGetSymbolAddress((void**)&tiles, g_tiles);
    cudaGetSymbolAddress((void**)&qkvh, g_qkvh);
    cudaGetSymbolAddress((void**)&qkvl, g_qkvl);
    cudaGetSymbolAddress((void**)&yh, g_yh);
    cudaGetSymbolAddress((void**)&yl, g_yl);
    cudaGetSymbolAddress((void**)&ench, g_ench);
    cudaGetSymbolAddress((void**)&encl, g_encl);
    cudaGetSymbolAddress((void**)&ath, g_ath);
    cudaGetSymbolAddress((void**)&atl, g_atl);
    cudaGetSymbolAddress((void**)&Hh, g_Hh);
    cudaGetSymbolAddress((void**)&Hl, g_Hl);
    cudaGetSymbolAddress((void**)&sawh, g_sawh);
    cudaGetSymbolAddress((void**)&sawl, g_sawl);
    cudaGetSymbolAddress((void**)&cawh, g_cawh);
    cudaGetSymbolAddress((void**)&cawl, g_cawl);
    cudaGetSymbolAddress((void**)&w1h, g_w1h);
    cudaGetSymbolAddress((void**)&w1l, g_w1l);
    cudaGetSymbolAddress((void**)&w2h, g_w2h);
    cudaGetSymbolAddress((void**)&w2l, g_w2l);

    cudaFuncSetAttribute(gemm_k<RowAh, EpiBiasH>,    cudaFuncAttributeMaxDynamicSharedMemorySize, GSMEM);
    cudaFuncSetAttribute(gemm_k<RowAh, EpiBias>,     cudaFuncAttributeMaxDynamicSharedMemorySize, GSMEM);
    cudaFuncSetAttribute(gemm_k<CrossAh, EpiBiasH>,  cudaFuncAttributeMaxDynamicSharedMemorySize, GSMEM);
    cudaFuncSetAttribute(gemm_k<GatherAh, EpiMoE1>,  cudaFuncAttributeMaxDynamicSharedMemorySize, GSMEM);
    cudaFuncSetAttribute(gemm_k<HRowAh, EpiMoE2>,    cudaFuncAttributeMaxDynamicSharedMemorySize, GSMEM);
    cudaFuncSetAttribute(flash_k, cudaFuncAttributeMaxDynamicSharedMemorySize, FSMEM);

    const long DD = (long)Dm * Dm;
    const long SLOT = (long)NT * Dm;

    wsplit_t_k<<<dim3(8, 16, Ln * 4), 256>>>(sa_w, sawh, sawl, Dm, Dm);
    wsplit_t_k<<<dim3(8, 16, Ln * 4), 256>>>(ca_w, cawh, cawl, Dm, Dm);
    wsplit_t_k<<<dim3(8, 64, Ln * En), 256>>>(w1, w1h, w1l, Dm, FFn);
    wsplit_t_k<<<dim3(32, 16, Ln * En), 256>>>(w2, w2h, w2l, FFn, Dm);
    split_k<<<(NT * Dm / 8 + 255) / 256, 256>>>(enc, ench, encl, NT * Dm);

    embed_k<<<NT, 256>>>(ids, emb, pos, y, yh, yl);

    for (int l = 0; l < Ln; l++) {
        gemm_k<<<dim3(16, 8, 3), 256, GSMEM>>>(
            RowAh{yh, yl, Dm, 0, NT}, sawh + l * 4 * DD, sawl + l * 4 * DD, DD,
            EpiBiasH{sa_b + (long)l * 4 * Dm, Dm, qkvh, qkvl, SLOT, Dm}, Dm, nullptr);
        flash_k<<<dim3(Tn / 64, 16), 256, FSMEM>>>(qkvh, qkvl, qkvh + SLOT, qkvl + SLOT,
                                                   qkvh + 2 * SLOT, qkvl + 2 * SLOT, ath, atl, am, Tn, 1);
        gemm_k<<<dim3(16, 8, 1), 256, GSMEM>>>(
            RowAh{ath, atl, Dm, 0, NT}, sawh + (l * 4 + 3) * DD, sawl + (l * 4 + 3) * DD, 0,
            EpiBias{sa_b + (long)(l * 4 + 3) * Dm, 0, proj, 0, Dm}, Dm, nullptr);
        add_ln_k<<<NT, 256>>>(y, proj, 1, ln_g + (l * 3 + 0) * Dm, ln_b + (l * 3 + 0) * Dm, y, yh, yl);

        gemm_k<<<dim3(16, 8, 3), 256, GSMEM>>>(
            CrossAh{yh, yl, ench, encl, nullptr, nullptr},
            cawh + l * 4 * DD, cawl + l * 4 * DD, DD,
            EpiBiasH{ca_b + (long)l * 4 * Dm, Dm, qkvh, qkvl, SLOT, Dm}, Dm, nullptr);
        flash_k<<<dim3(Tn / 64, 16), 256, FSMEM>>>(qkvh, qkvl, qkvh + SLOT, qkvl + SLOT,
                                                   qkvh + 2 * SLOT, qkvl + 2 * SLOT, ath, atl, nullptr, Tn, 0);
        gemm_k<<<dim3(16, 8, 1), 256, GSMEM>>>(
            RowAh{ath, atl, Dm, 0, NT}, cawh + (l * 4 + 3) * DD, cawl + (l * 4 + 3) * DD, 0,
            EpiBias{ca_b + (long)(l * 4 + 3) * Dm, 0, proj, 0, Dm}, Dm, nullptr);
        add_ln_k<<<NT, 256>>>(y, proj, 1, ln_g + (l * 3 + 1) * Dm, ln_b + (l * 3 + 1) * Dm, y, yh, yl);

        router_k<<<NT / 8, 256>>>(y, rw + (long)l * Dm * En, rb + l * En, probs, topi, gates);
        lb_k<<<1, 1024>>>(probs, topi, out + (out_size - 1), l == 0 ? 1 : 0);
        group_k<<<1, 256>>>(topi, perm, offs, tiles);
        gemm_k<<<dim3(MAXT, 32, 1), 256, GSMEM>>>(
            GatherAh{yh, yl, perm, offs, 0},
            w1h + (long)l * En * FFn * Dm, w1l + (long)l * En * FFn * Dm, (long)FFn * Dm,
            EpiMoE1{b1 + (long)l * En * FFn, offs, Hh, Hl, nullptr, nullptr, nullptr}, Dm, tiles);
        gemm_k<<<dim3(MAXT, 8, 1), 256, GSMEM>>>(
            HRowAh{Hh, Hl, offs, nullptr, nullptr},
            w2h + (long)l * En * Dm * FFn, w2l + (long)l * En * Dm * FFn, (long)Dm * FFn,
            EpiMoE2{b2 + (long)l * En * Dm, offs, perm, gates, eout, nullptr, 0}, FFn, tiles);
        float* lnout = (l == Ln - 1) ? out : y;
        add_ln_k<<<NT, 256>>>(y, eout, 2, ln_g + (l * 3 + 2) * Dm, ln_b + (l * 3 + 2) * Dm, lnout, yh, yl);
    }
}